// round 1
// baseline (speedup 1.0000x reference)
#include <cuda_runtime.h>
#include <math.h>

// Problem constants (all compile-time, all tile-divisible)
#define Bb   4
#define Tt   2048
#define Dm   1024
#define Hh   16
#define HDm  64
#define NFm  128
#define CHK  128
#define NCH  (Tt/CHK)     // 16
#define BH   (Bb*Hh)      // 64
#define MR   (Bb*Tt)      // 8192
#define EPSf 1e-6f
#define INV_SQRT_NF 0.08838834764831845f  // 1/sqrt(128)

// ---------------- scratch (static device allocations; no cudaMalloc) --------
__device__ float g_q [(size_t)MR*Dm];
__device__ float g_k [(size_t)MR*Dm];
__device__ float g_v [(size_t)MR*Dm];
__device__ float g_y [(size_t)MR*Dm];
__device__ float g_qp[(size_t)BH*Tt*NFm];
__device__ float g_kp[(size_t)BH*Tt*NFm];
__device__ float g_S [(size_t)BH*NCH*NFm*HDm];
__device__ float g_z [(size_t)BH*NCH*NFm];

// ---------------- fp32 SGEMM body: C[128x128 tile] = A(M x 1024) @ B(1024 x 1024)
__device__ __forceinline__ void sgemm_body(const float* __restrict__ A,
                                           const float* __restrict__ B,
                                           float* __restrict__ C) {
    __shared__ float As[8][128];
    __shared__ float Bs[8][128];
    const int tid = threadIdx.x;
    const int m0 = blockIdx.y * 128, n0 = blockIdx.x * 128;
    const int ty = tid >> 4, tx = tid & 15;
    const int arow = tid >> 1, acol = (tid & 1) * 4;
    const int brow = tid >> 5, bcol = (tid & 31) * 4;
    const float* Ap = A + (size_t)(m0 + arow) * 1024 + acol;
    const float* Bp = B + (size_t)brow * 1024 + n0 + bcol;

    float acc[8][8];
#pragma unroll
    for (int i = 0; i < 8; i++)
#pragma unroll
        for (int j = 0; j < 8; j++) acc[i][j] = 0.f;

    for (int k0 = 0; k0 < 1024; k0 += 8) {
        float4 av = *(const float4*)(Ap + k0);
        float4 bv = *(const float4*)(Bp + (size_t)k0 * 1024);
        As[acol + 0][arow] = av.x;
        As[acol + 1][arow] = av.y;
        As[acol + 2][arow] = av.z;
        As[acol + 3][arow] = av.w;
        *(float4*)&Bs[brow][bcol] = bv;
        __syncthreads();
#pragma unroll
        for (int kk = 0; kk < 8; kk++) {
            float4 a0 = *(const float4*)&As[kk][ty * 8];
            float4 a1 = *(const float4*)&As[kk][ty * 8 + 4];
            float4 b0 = *(const float4*)&Bs[kk][tx * 8];
            float4 b1 = *(const float4*)&Bs[kk][tx * 8 + 4];
            float ar[8] = {a0.x, a0.y, a0.z, a0.w, a1.x, a1.y, a1.z, a1.w};
            float br[8] = {b0.x, b0.y, b0.z, b0.w, b1.x, b1.y, b1.z, b1.w};
#pragma unroll
            for (int i = 0; i < 8; i++)
#pragma unroll
                for (int j = 0; j < 8; j++)
                    acc[i][j] = fmaf(ar[i], br[j], acc[i][j]);
        }
        __syncthreads();
    }
#pragma unroll
    for (int i = 0; i < 8; i++) {
        float* cp = C + (size_t)(m0 + ty * 8 + i) * 1024 + n0 + tx * 8;
        *(float4*)cp       = make_float4(acc[i][0], acc[i][1], acc[i][2], acc[i][3]);
        *(float4*)(cp + 4) = make_float4(acc[i][4], acc[i][5], acc[i][6], acc[i][7]);
    }
}

// K1: q/k/v projections, blockIdx.z selects which
__global__ void __launch_bounds__(256) proj_kernel(const float* __restrict__ x,
                                                   const float* __restrict__ Wq,
                                                   const float* __restrict__ Wk,
                                                   const float* __restrict__ Wv) {
    const float* W;
    float* out;
    if (blockIdx.z == 0)      { W = Wq; out = g_q; }
    else if (blockIdx.z == 1) { W = Wk; out = g_k; }
    else                      { W = Wv; out = g_v; }
    sgemm_body(x, W, out);
}

// K6: final projection y @ Wo -> d_out
__global__ void __launch_bounds__(256) out_kernel(const float* __restrict__ Wo,
                                                  float* __restrict__ out) {
    sgemm_body(g_y, Wo, out);
}

// K2: FAVOR+ feature map. One block per (b*T+t, h, {q|k}); 128 threads = 128 features.
__global__ void __launch_bounds__(128) feat_kernel(const float* __restrict__ Wf) {
    const int bt  = blockIdx.x;   // 0..MR-1   (= b*T + t)
    const int h   = blockIdx.y;
    const int sel = blockIdx.z;   // 0 = q, 1 = k
    const float* src = (sel ? g_k : g_q) + (size_t)bt * Dm + h * HDm;
    float* dst = sel ? g_kp : g_qp;

    __shared__ float row[HDm];
    const int f = threadIdx.x;
    if (f < HDm) row[f] = src[f];
    __syncthreads();

    float sq = 0.f, dot = 0.f;
#pragma unroll
    for (int d = 0; d < HDm; d++) {
        float r = row[d];
        sq  = fmaf(r, r, sq);
        dot = fmaf(r, Wf[d * NFm + f], dot);
    }
    const int b = bt / Tt, t = bt % Tt;
    const int bh = b * Hh + h;
    dst[((size_t)bh * Tt + t) * NFm + f] = expf(dot - 0.5f * sq) * INV_SQRT_NF;
}

// K3: per-chunk S_local = K^T V (128x64), z_local = sum_s k_s (128)
#define SMEM3 ((128 * 128 + 128 * 64) * 4)
__global__ void __launch_bounds__(256) chunk_sum_kernel() {
    const int c = blockIdx.x, bh = blockIdx.y;
    const int b = bh >> 4, h = bh & 15;
    extern __shared__ float sm3[];
    float* Ks = sm3;               // [s*128 + f]
    float* Vs = sm3 + 128 * 128;   // [s*64 + e]
    const int tid = threadIdx.x;

    const size_t kbase = ((size_t)bh * Tt + c * CHK) * NFm;
#pragma unroll 4
    for (int j = 0; j < 64; j++) {
        int idx = tid + 256 * j;
        Ks[idx] = g_kp[kbase + idx];
    }
    const size_t vbase = ((size_t)(b * Tt + c * CHK) * Hh + h) * HDm;
#pragma unroll 4
    for (int j = 0; j < 32; j++) {
        int idx = tid + 256 * j;
        int s = idx >> 6, e = idx & 63;
        Vs[idx] = g_v[vbase + (size_t)s * (Hh * HDm) + e];
    }
    __syncthreads();

    const int fg = tid >> 3, eg = tid & 7;      // 32 x 8
    const int f0 = fg * 4, e0 = eg * 8;
    float acc[4][8];
#pragma unroll
    for (int i = 0; i < 4; i++)
#pragma unroll
        for (int j = 0; j < 8; j++) acc[i][j] = 0.f;
    float zacc[4] = {0.f, 0.f, 0.f, 0.f};

    for (int s = 0; s < 128; s++) {
        float kv[4], vv[8];
#pragma unroll
        for (int i = 0; i < 4; i++) { kv[i] = Ks[s * 128 + f0 + i]; zacc[i] += kv[i]; }
#pragma unroll
        for (int j = 0; j < 8; j++) vv[j] = Vs[s * 64 + e0 + j];
#pragma unroll
        for (int i = 0; i < 4; i++)
#pragma unroll
            for (int j = 0; j < 8; j++) acc[i][j] = fmaf(kv[i], vv[j], acc[i][j]);
    }

    const size_t Sbase = ((size_t)bh * NCH + c) * (NFm * HDm);
#pragma unroll
    for (int i = 0; i < 4; i++)
#pragma unroll
        for (int j = 0; j < 8; j++)
            g_S[Sbase + (size_t)(f0 + i) * 64 + e0 + j] = acc[i][j];
    if (eg == 0) {
#pragma unroll
        for (int i = 0; i < 4; i++)
            g_z[((size_t)bh * NCH + c) * NFm + f0 + i] = zacc[i];
    }
}

// K4: exclusive prefix over chunks (in place). One CTA per (b,h); 16 sequential steps.
__global__ void __launch_bounds__(256) prefix_kernel() {
    const int bh = blockIdx.x, tid = threadIdx.x;
    float acc[32];
#pragma unroll
    for (int j = 0; j < 32; j++) acc[j] = 0.f;
    float az = 0.f;
    for (int c = 0; c < NCH; c++) {
        const size_t base = ((size_t)bh * NCH + c) * (NFm * HDm);
#pragma unroll
        for (int j = 0; j < 32; j++) {
            size_t id = base + tid + 256 * j;
            float cur = g_S[id];
            g_S[id] = acc[j];
            acc[j] += cur;
        }
        if (tid < NFm) {
            size_t zi = ((size_t)bh * NCH + c) * NFm + tid;
            float cur = g_z[zi];
            g_z[zi] = az;
            az += cur;
        }
    }
}

// K5: chunk output.
//   A = tril(Q K^T)  (128x128, built in smem, pitch 129 for conflict-free column access)
//   Y = A @ V + Q @ S_prev ; den_t = rowsum(A)_t + q_t . z_prev + eps ; y_t = Y_t / den_t
#define PITCH 129
#define SMEM5 ((2 * 128 * PITCH + 2 * 128 * 64 + 256) * 4)
__global__ void __launch_bounds__(256) chunk_out_kernel() {
    const int c = blockIdx.x, bh = blockIdx.y;
    const int b = bh >> 4, h = bh & 15;
    extern __shared__ float sm5[];
    float* Qst  = sm5;                       // [f*PITCH + t]
    float* Kst  = Qst + 128 * PITCH;         // [f*PITCH + s]; later reused as Ast[s*PITCH + t]
    float* Vs   = Kst + 128 * PITCH;         // [s*64 + e]
    float* Ss   = Vs  + 128 * 64;            // [f*64 + e]   (S_prev)
    float* zs   = Ss  + 128 * 64;            // [f]
    float* dinv = zs  + 128;                 // [t]
    const int tid = threadIdx.x;

    const size_t qbase = ((size_t)bh * Tt + c * CHK) * NFm;
#pragma unroll 4
    for (int j = 0; j < 64; j++) {
        int idx = tid + 256 * j;
        int s = idx >> 7, f = idx & 127;
        Qst[f * PITCH + s] = g_qp[qbase + idx];
        Kst[f * PITCH + s] = g_kp[qbase + idx];
    }
    const size_t vbase = ((size_t)(b * Tt + c * CHK) * Hh + h) * HDm;
    const size_t Sbase = ((size_t)bh * NCH + c) * (NFm * HDm);
#pragma unroll 4
    for (int j = 0; j < 32; j++) {
        int idx = tid + 256 * j;
        int s = idx >> 6, e = idx & 63;
        Vs[idx] = g_v[vbase + (size_t)s * (Hh * HDm) + e];
        Ss[idx] = g_S[Sbase + idx];
    }
    if (tid < 128) zs[tid] = g_z[((size_t)bh * NCH + c) * NFm + tid];
    __syncthreads();

    // Phase A: A[t][s] = sum_f Q[t][f] K[s][f]; thread (tg,sg) owns t=tg+16i, s=sg+16j
    const int tg = tid >> 4, sg = tid & 15;
    float a[8][8];
#pragma unroll
    for (int i = 0; i < 8; i++)
#pragma unroll
        for (int j = 0; j < 8; j++) a[i][j] = 0.f;
    for (int f = 0; f < 128; f++) {
        float qv[8], kv[8];
#pragma unroll
        for (int i = 0; i < 8; i++) qv[i] = Qst[f * PITCH + tg + 16 * i];
#pragma unroll
        for (int j = 0; j < 8; j++) kv[j] = Kst[f * PITCH + sg + 16 * j];
#pragma unroll
        for (int i = 0; i < 8; i++)
#pragma unroll
            for (int j = 0; j < 8; j++) a[i][j] = fmaf(qv[i], kv[j], a[i][j]);
    }
    __syncthreads();  // everyone done reading Kst

    // Write masked A into Ast (= Kst storage), layout [s*PITCH + t]
#pragma unroll
    for (int i = 0; i < 8; i++) {
        int t = tg + 16 * i;
#pragma unroll
        for (int j = 0; j < 8; j++) {
            int s = sg + 16 * j;
            Kst[s * PITCH + t] = (s <= t) ? a[i][j] : 0.f;
        }
    }
    __syncthreads();

    // Denominator: den_t = eps + q_t.z_prev + sum_s A[t][s]
    if (tid < 128) {
        const int t = tid;
        float den = EPSf;
        for (int f = 0; f < 128; f++) den = fmaf(Qst[f * PITCH + t], zs[f], den);
        for (int s = 0; s < 128; s++) den += Kst[s * PITCH + t];
        dinv[t] = 1.f / den;
    }
    __syncthreads();

    // Phase Y: Y[t][e] = sum_s A[t][s] V[s][e] + sum_f Q[t][f] S_prev[f][e]
    const int tg2 = tid >> 4, eg = tid & 15;   // t = tg2+16i (8), e = eg*4+j (4)
    float y[8][4];
#pragma unroll
    for (int i = 0; i < 8; i++)
#pragma unroll
        for (int j = 0; j < 4; j++) y[i][j] = 0.f;
    for (int s = 0; s < 128; s++) {
        float av[8], vv[4];
#pragma unroll
        for (int i = 0; i < 8; i++) av[i] = Kst[s * PITCH + tg2 + 16 * i];
#pragma unroll
        for (int j = 0; j < 4; j++) vv[j] = Vs[s * 64 + eg * 4 + j];
#pragma unroll
        for (int i = 0; i < 8; i++)
#pragma unroll
            for (int j = 0; j < 4; j++) y[i][j] = fmaf(av[i], vv[j], y[i][j]);
    }
    for (int f = 0; f < 128; f++) {
        float qv[8], sv[4];
#pragma unroll
        for (int i = 0; i < 8; i++) qv[i] = Qst[f * PITCH + tg2 + 16 * i];
#pragma unroll
        for (int j = 0; j < 4; j++) sv[j] = Ss[f * 64 + eg * 4 + j];
#pragma unroll
        for (int i = 0; i < 8; i++)
#pragma unroll
            for (int j = 0; j < 4; j++) y[i][j] = fmaf(qv[i], sv[j], y[i][j]);
    }
#pragma unroll
    for (int i = 0; i < 8; i++) {
        const int t = tg2 + 16 * i;
        const float di = dinv[t];
        float* yp = g_y + ((size_t)(b * Tt + c * CHK + t)) * Dm + h * HDm + eg * 4;
#pragma unroll
        for (int j = 0; j < 4; j++) yp[j] = y[i][j] * di;
    }
}

// ---------------------------------------------------------------------------
extern "C" void kernel_launch(void* const* d_in, const int* in_sizes, int n_in,
                              void* d_out, int out_size) {
    const float* x  = (const float*)d_in[0];
    const float* Wq = (const float*)d_in[1];
    const float* Wk = (const float*)d_in[2];
    const float* Wv = (const float*)d_in[3];
    const float* Wo = (const float*)d_in[4];
    const float* Wf = (const float*)d_in[5];
    float* out = (float*)d_out;

    cudaFuncSetAttribute(chunk_sum_kernel, cudaFuncAttributeMaxDynamicSharedMemorySize, SMEM3);
    cudaFuncSetAttribute(chunk_out_kernel, cudaFuncAttributeMaxDynamicSharedMemorySize, SMEM5);

    proj_kernel<<<dim3(Dm / 128, MR / 128, 3), 256>>>(x, Wq, Wk, Wv);
    feat_kernel<<<dim3(MR, Hh, 2), 128>>>(Wf);
    chunk_sum_kernel<<<dim3(NCH, BH), 256, SMEM3>>>();
    prefix_kernel<<<BH, 256>>>();
    chunk_out_kernel<<<dim3(NCH, BH), 256, SMEM5>>>();
    out_kernel<<<dim3(Dm / 128, MR / 128), 256>>>(Wo, out);
}

// round 3
// speedup vs baseline: 1.9123x; 1.9123x over previous
#include <cuda_runtime.h>
#include <cuda_bf16.h>
#include <math.h>
#include <stdint.h>

// ---------------- problem constants ----------------
#define Bb   4
#define Tt   2048
#define Dm   1024
#define Hh   16
#define HDm  64
#define NFm  128
#define CHK  128
#define NCH  16
#define BH   64
#define MR   8192
#define EPSf 1e-6f
#define INV_SQRT_NF 0.08838834764831845f

#define QKV_OFF ((size_t)MR * Dm)

// ---------------- scratch ----------------
__device__ float g_qkv[3 * (size_t)MR * Dm];   // q | k | v
__device__ float g_y  [(size_t)MR * Dm];
__device__ float g_qp [(size_t)BH * Tt * NFm];
__device__ float g_kp [(size_t)BH * Tt * NFm];
__device__ float g_S  [(size_t)BH * NCH * NFm * HDm];
__device__ float g_z  [(size_t)BH * NCH * NFm];

__device__ __nv_bfloat16 g_xhi[(size_t)MR * Dm], g_xlo[(size_t)MR * Dm];
__device__ __nv_bfloat16 g_yhi[(size_t)MR * Dm], g_ylo[(size_t)MR * Dm];
__device__ __nv_bfloat16 g_wth[4 * (size_t)Dm * Dm], g_wtl[4 * (size_t)Dm * Dm]; // W^T: [n][k]

// ---------------- helpers ----------------
__device__ __forceinline__ uint32_t smem_u32(const void* p) {
    uint32_t a;
    asm("{ .reg .u64 t; cvta.to.shared.u64 t, %1; cvt.u32.u64 %0, t; }" : "=r"(a) : "l"(p));
    return a;
}

#define LDSM4(r0, r1, r2, r3, addr)                                          \
    asm volatile("ldmatrix.sync.aligned.m8n8.x4.shared.b16 {%0,%1,%2,%3}, [%4];" \
                 : "=r"(r0), "=r"(r1), "=r"(r2), "=r"(r3) : "r"(addr))

#define MMA16816(d, a0, a1, a2, a3, b0, b1)                                  \
    asm volatile("mma.sync.aligned.m16n8k16.row.col.f32.bf16.bf16.f32 "      \
                 "{%0,%1,%2,%3}, {%4,%5,%6,%7}, {%8,%9}, {%0,%1,%2,%3};"     \
                 : "+f"((d)[0]), "+f"((d)[1]), "+f"((d)[2]), "+f"((d)[3])    \
                 : "r"(a0), "r"(a1), "r"(a2), "r"(a3), "r"(b0), "r"(b1))

#define CP_ASYNC16(sa, g) \
    asm volatile("cp.async.cg.shared.global [%0], [%1], 16;" :: "r"(sa), "l"(g))

// ---------------- K0: fp32 -> bf16 hi/lo split (x or y) ----------------
__global__ void __launch_bounds__(256) split_kernel(const float* __restrict__ xsrc, int mode) {
    const size_t i = (size_t)blockIdx.x * 256 + threadIdx.x;   // float4 index
    const float4 v = mode ? ((const float4*)g_y)[i] : ((const float4*)xsrc)[i];
    __nv_bfloat16* hi = mode ? g_yhi : g_xhi;
    __nv_bfloat16* lo = mode ? g_ylo : g_xlo;
    float vv[4] = {v.x, v.y, v.z, v.w};
    unsigned short h[4], l[4];
#pragma unroll
    for (int j = 0; j < 4; j++) {
        __nv_bfloat16 hb = __float2bfloat16(vv[j]);
        __nv_bfloat16 lb = __float2bfloat16(vv[j] - __bfloat162float(hb));
        h[j] = __bfloat16_as_ushort(hb);
        l[j] = __bfloat16_as_ushort(lb);
    }
    uint2 ph, pl;
    ph.x = ((uint32_t)h[1] << 16) | h[0];  ph.y = ((uint32_t)h[3] << 16) | h[2];
    pl.x = ((uint32_t)l[1] << 16) | l[0];  pl.y = ((uint32_t)l[3] << 16) | l[2];
    *(uint2*)(hi + 4 * i) = ph;
    *(uint2*)(lo + 4 * i) = pl;
}

// ---------------- K0b: W transpose + split.  Wt[n][k] = W[k][n] ----------------
__global__ void __launch_bounds__(256) wsplit_kernel(const float* __restrict__ Wq,
                                                     const float* __restrict__ Wk,
                                                     const float* __restrict__ Wv,
                                                     const float* __restrict__ Wo) {
    __shared__ float t[32][33];
    const int z = blockIdx.z;
    const float* W = (z == 0) ? Wq : (z == 1) ? Wk : (z == 2) ? Wv : Wo;
    const int tx = threadIdx.x & 31, ty = threadIdx.x >> 5;   // 32 x 8
    const int bx = blockIdx.x, by = blockIdx.y;
#pragma unroll
    for (int j = 0; j < 4; j++) {
        int k = by * 32 + ty + j * 8;
        int n = bx * 32 + tx;
        t[ty + j * 8][tx] = W[(size_t)k * Dm + n];
    }
    __syncthreads();
#pragma unroll
    for (int j = 0; j < 4; j++) {
        int n = bx * 32 + ty + j * 8;
        int k = by * 32 + tx;
        float v = t[tx][ty + j * 8];
        __nv_bfloat16 hb = __float2bfloat16(v);
        __nv_bfloat16 lb = __float2bfloat16(v - __bfloat162float(hb));
        size_t o = (size_t)z * Dm * Dm + (size_t)n * Dm + k;
        g_wth[o] = hb;
        g_wtl[o] = lb;
    }
}

// ---------------- K1: HMMA split-bf16 GEMM  C(8192x1024) = A @ Wt^T -------------
// CTA tile 128x128, kt=32, 3-stage cp.async pipeline.
// smem per stage: 4 tiles (Ahi,Alo,Bhi,Blo), each 128 rows x 32 bf16, row pitch 80B.
#define TROW   80
#define TILE_B (128 * TROW)          // 10240
#define STG_B  (4 * TILE_B)          // 40960
#define GSMEM  (3 * STG_B)           // 122880

__global__ void __launch_bounds__(256, 1) gemm_kernel(float* __restrict__ Cout, int mode) {
    extern __shared__ char sm[];
    const uint32_t smb = smem_u32(sm);
    const int tid = threadIdx.x;
    const int z = blockIdx.z;
    const int m0 = blockIdx.y * 128, n0 = blockIdx.x * 128;

    const __nv_bfloat16 *Ahi, *Alo, *Bhi, *Blo;
    float* C;
    if (mode == 0) {
        Ahi = g_xhi; Alo = g_xlo;
        Bhi = g_wth + (size_t)z * Dm * Dm;
        Blo = g_wtl + (size_t)z * Dm * Dm;
        C = g_qkv + (size_t)z * QKV_OFF;
    } else {
        Ahi = g_yhi; Alo = g_ylo;
        Bhi = g_wth + (size_t)3 * Dm * Dm;
        Blo = g_wtl + (size_t)3 * Dm * Dm;
        C = Cout;
    }

    // loader mapping: 64 threads per tile
    const int lq = tid >> 6, lu = tid & 63;
    const __nv_bfloat16* gp = (lq == 0) ? Ahi : (lq == 1) ? Alo : (lq == 2) ? Bhi : Blo;
    const int grow0 = (lq < 2) ? m0 : n0;
    const uint32_t sload0 = smb + lq * TILE_B;

#define LOAD_STAGE(buf, k0)                                                   \
    do {                                                                      \
        uint32_t sb_ = sload0 + (buf) * STG_B;                                \
        _Pragma("unroll")                                                     \
        for (int j_ = 0; j_ < 8; ++j_) {                                      \
            int lin_ = lu + 64 * j_;                                          \
            int r_ = lin_ >> 2, c_ = lin_ & 3;                                \
            CP_ASYNC16(sb_ + r_ * TROW + c_ * 16,                             \
                       gp + (size_t)(grow0 + r_) * Dm + (k0) + c_ * 8);       \
        }                                                                     \
    } while (0)

    // compute mapping
    const int lane = tid & 31, w = tid >> 5;
    const int wm = w & 3, wn = w >> 2;           // 4 x 2 warps, warp tile 32x64
    const int lj = lane >> 3, lm = lane & 7;
    const int arow = wm * 32 + (lj & 1) * 8 + lm;       // + i*16
    const int acho = lj >> 1;                            // + ks*2
    const int brow = wn * 64 + ((lj & 2) ? 8 : 0) + lm;  // + g*16
    const int bcho = lj & 1;                             // + ks*2

    float acc[2][8][4];
#pragma unroll
    for (int i = 0; i < 2; i++)
#pragma unroll
        for (int jn = 0; jn < 8; jn++)
#pragma unroll
            for (int r = 0; r < 4; r++) acc[i][jn][r] = 0.f;

    LOAD_STAGE(0, 0);
    asm volatile("cp.async.commit_group;" ::: "memory");
    LOAD_STAGE(1, 32);
    asm volatile("cp.async.commit_group;" ::: "memory");

    for (int it = 0; it < 32; ++it) {
        asm volatile("cp.async.wait_group 1;" ::: "memory");
        __syncthreads();
        const int nxt = it + 2;
        if (nxt < 32) LOAD_STAGE(nxt % 3, nxt * 32);
        asm volatile("cp.async.commit_group;" ::: "memory");

        const uint32_t buf = smb + (it % 3) * STG_B;
#pragma unroll
        for (int ks = 0; ks < 2; ++ks) {
            uint32_t ah[2][4], al[2][4], bh[4][4], bl[4][4];
#pragma unroll
            for (int i = 0; i < 2; ++i) {
                uint32_t ra = buf + (arow + i * 16) * TROW + (ks * 2 + acho) * 16;
                LDSM4(ah[i][0], ah[i][1], ah[i][2], ah[i][3], ra);
                LDSM4(al[i][0], al[i][1], al[i][2], al[i][3], ra + TILE_B);
            }
#pragma unroll
            for (int g = 0; g < 4; ++g) {
                uint32_t rb = buf + 2 * TILE_B + (brow + g * 16) * TROW + (ks * 2 + bcho) * 16;
                LDSM4(bh[g][0], bh[g][1], bh[g][2], bh[g][3], rb);
                LDSM4(bl[g][0], bl[g][1], bl[g][2], bl[g][3], rb + TILE_B);
            }
#pragma unroll
            for (int i = 0; i < 2; ++i)
#pragma unroll
                for (int jn = 0; jn < 8; ++jn) {
                    const int g = jn >> 1, hf = (jn & 1) * 2;
                    MMA16816(acc[i][jn], ah[i][0], ah[i][1], ah[i][2], ah[i][3],
                             bh[g][hf], bh[g][hf + 1]);
                    MMA16816(acc[i][jn], ah[i][0], ah[i][1], ah[i][2], ah[i][3],
                             bl[g][hf], bl[g][hf + 1]);
                    MMA16816(acc[i][jn], al[i][0], al[i][1], al[i][2], al[i][3],
                             bh[g][hf], bh[g][hf + 1]);
                }
        }
    }

    // epilogue: direct stores (each quad writes 32B contiguous = full sectors)
#pragma unroll
    for (int i = 0; i < 2; ++i) {
        const int r0 = m0 + wm * 32 + i * 16 + (lane >> 2);
#pragma unroll
        for (int jn = 0; jn < 8; ++jn) {
            const int cc = n0 + wn * 64 + jn * 8 + 2 * (lane & 3);
            *(float2*)&C[(size_t)r0 * Dm + cc]       = make_float2(acc[i][jn][0], acc[i][jn][1]);
            *(float2*)&C[(size_t)(r0 + 8) * Dm + cc] = make_float2(acc[i][jn][2], acc[i][jn][3]);
        }
    }
#undef LOAD_STAGE
}

// ---------------- K2: FAVOR+ features. One CTA per token (bt). ----------------
__global__ void __launch_bounds__(256) feat_kernel(const float* __restrict__ Wf) {
    __shared__ float wfs[HDm * NFm];      // 32 KB
    __shared__ float qrow[Dm], krow[Dm];  // 8 KB
    const int bt = blockIdx.x, tid = threadIdx.x;
#pragma unroll
    for (int j = 0; j < 32; ++j) wfs[tid + 256 * j] = Wf[tid + 256 * j];
    ((float4*)qrow)[tid] = ((const float4*)(g_qkv + (size_t)bt * Dm))[tid];
    ((float4*)krow)[tid] = ((const float4*)(g_qkv + QKV_OFF + (size_t)bt * Dm))[tid];
    __syncthreads();
    const int sel = tid >> 7, f = tid & 127;
    const float* row0 = sel ? krow : qrow;
    float* dst = sel ? g_kp : g_qp;
    const int b = bt >> 11, t = bt & 2047;
    for (int h = 0; h < 16; ++h) {
        const float* row = row0 + h * 64;
        float sq = 0.f, dot = 0.f;
#pragma unroll
        for (int d = 0; d < 64; ++d) {
            float r = row[d];
            sq  = fmaf(r, r, sq);
            dot = fmaf(r, wfs[d * 128 + f], dot);
        }
        dst[(((size_t)(b * 16 + h)) * Tt + t) * NFm + f] = expf(dot - 0.5f * sq) * INV_SQRT_NF;
    }
}

// ---------------- K3: per-chunk S_local = K^T V, z_local = sum k ----------------
#define SMEM3 ((128 * 128 + 128 * 64) * 4)
__global__ void __launch_bounds__(256) chunk_sum_kernel() {
    const int c = blockIdx.x, bh = blockIdx.y;
    const int b = bh >> 4, h = bh & 15;
    extern __shared__ float sm3[];
    float* Ks = sm3;
    float* Vs = sm3 + 128 * 128;
    const int tid = threadIdx.x;
    const float* GV = g_qkv + 2 * QKV_OFF;

    const size_t kbase = ((size_t)bh * Tt + c * CHK) * NFm;
#pragma unroll 4
    for (int j = 0; j < 64; j++) {
        int idx = tid + 256 * j;
        Ks[idx] = g_kp[kbase + idx];
    }
    const size_t vbase = ((size_t)(b * Tt + c * CHK)) * Dm + h * HDm;
#pragma unroll 4
    for (int j = 0; j < 32; j++) {
        int idx = tid + 256 * j;
        int s = idx >> 6, e = idx & 63;
        Vs[idx] = GV[vbase + (size_t)s * Dm + e];
    }
    __syncthreads();

    const int fg = tid >> 3, eg = tid & 7;
    const int f0 = fg * 4, e0 = eg * 8;
    float acc[4][8];
#pragma unroll
    for (int i = 0; i < 4; i++)
#pragma unroll
        for (int j = 0; j < 8; j++) acc[i][j] = 0.f;
    float zacc[4] = {0.f, 0.f, 0.f, 0.f};

    for (int s = 0; s < 128; s++) {
        float kv[4], vv[8];
#pragma unroll
        for (int i = 0; i < 4; i++) { kv[i] = Ks[s * 128 + f0 + i]; zacc[i] += kv[i]; }
#pragma unroll
        for (int j = 0; j < 8; j++) vv[j] = Vs[s * 64 + e0 + j];
#pragma unroll
        for (int i = 0; i < 4; i++)
#pragma unroll
            for (int j = 0; j < 8; j++) acc[i][j] = fmaf(kv[i], vv[j], acc[i][j]);
    }

    const size_t Sbase = ((size_t)bh * NCH + c) * (NFm * HDm);
#pragma unroll
    for (int i = 0; i < 4; i++)
#pragma unroll
        for (int j = 0; j < 8; j++)
            g_S[Sbase + (size_t)(f0 + i) * 64 + e0 + j] = acc[i][j];
    if (eg == 0) {
#pragma unroll
        for (int i = 0; i < 4; i++)
            g_z[((size_t)bh * NCH + c) * NFm + f0 + i] = zacc[i];
    }
}

// ---------------- K4: exclusive prefix over chunks (parallel over columns) ------
__global__ void __launch_bounds__(256) prefix_kernel() {   // grid (32, BH)
    const int bh = blockIdx.y, seg = blockIdx.x;
    const int idx = seg * 256 + threadIdx.x;
    float v[NCH];
    const size_t base = (size_t)bh * NCH * NFm * HDm + idx;
#pragma unroll
    for (int c = 0; c < NCH; ++c) v[c] = g_S[base + (size_t)c * NFm * HDm];
    float acc = 0.f;
#pragma unroll
    for (int c = 0; c < NCH; ++c) { float cur = v[c]; v[c] = acc; acc += cur; }
#pragma unroll
    for (int c = 0; c < NCH; ++c) g_S[base + (size_t)c * NFm * HDm] = v[c];
    if (seg == 0 && threadIdx.x < NFm) {
        float zv[NCH];
        const size_t zb = (size_t)bh * NCH * NFm + threadIdx.x;
#pragma unroll
        for (int c = 0; c < NCH; ++c) zv[c] = g_z[zb + c * NFm];
        float az = 0.f;
#pragma unroll
        for (int c = 0; c < NCH; ++c) { float cur = zv[c]; zv[c] = az; az += cur; }
#pragma unroll
        for (int c = 0; c < NCH; ++c) g_z[zb + c * NFm] = zv[c];
    }
}

// ---------------- K5: chunk output ----------------
#define PITCH 129
#define SMEM5 ((2 * 128 * PITCH + 2 * 128 * 64 + 256) * 4)
__global__ void __launch_bounds__(256) chunk_out_kernel() {
    const int c = blockIdx.x, bh = blockIdx.y;
    const int b = bh >> 4, h = bh & 15;
    extern __shared__ float sm5[];
    float* Qst  = sm5;
    float* Kst  = Qst + 128 * PITCH;
    float* Vs   = Kst + 128 * PITCH;
    float* Ss   = Vs  + 128 * 64;
    float* zs   = Ss  + 128 * 64;
    float* dinv = zs  + 128;
    const int tid = threadIdx.x;
    const float* GV = g_qkv + 2 * QKV_OFF;

    const size_t qbase = ((size_t)bh * Tt + c * CHK) * NFm;
#pragma unroll 4
    for (int j = 0; j < 64; j++) {
        int idx = tid + 256 * j;
        int s = idx >> 7, f = idx & 127;
        Qst[f * PITCH + s] = g_qp[qbase + idx];
        Kst[f * PITCH + s] = g_kp[qbase + idx];
    }
    const size_t vbase = ((size_t)(b * Tt + c * CHK)) * Dm + h * HDm;
    const size_t Sbase = ((size_t)bh * NCH + c) * (NFm * HDm);
#pragma unroll 4
    for (int j = 0; j < 32; j++) {
        int idx = tid + 256 * j;
        int s = idx >> 6, e = idx & 63;
        Vs[idx] = GV[vbase + (size_t)s * Dm + e];
        Ss[idx] = g_S[Sbase + idx];
    }
    if (tid < 128) zs[tid] = g_z[((size_t)bh * NCH + c) * NFm + tid];
    __syncthreads();

    const int tg = tid >> 4, sg = tid & 15;
    float a[8][8];
#pragma unroll
    for (int i = 0; i < 8; i++)
#pragma unroll
        for (int j = 0; j < 8; j++) a[i][j] = 0.f;
    for (int f = 0; f < 128; f++) {
        float qv[8], kv[8];
#pragma unroll
        for (int i = 0; i < 8; i++) qv[i] = Qst[f * PITCH + tg + 16 * i];
#pragma unroll
        for (int j = 0; j < 8; j++) kv[j] = Kst[f * PITCH + sg + 16 * j];
#pragma unroll
        for (int i = 0; i < 8; i++)
#pragma unroll
            for (int j = 0; j < 8; j++) a[i][j] = fmaf(qv[i], kv[j], a[i][j]);
    }
    __syncthreads();

#pragma unroll
    for (int i = 0; i < 8; i++) {
        int t = tg + 16 * i;
#pragma unroll
        for (int j = 0; j < 8; j++) {
            int s = sg + 16 * j;
            Kst[s * PITCH + t] = (s <= t) ? a[i][j] : 0.f;
        }
    }
    __syncthreads();

    if (tid < 128) {
        const int t = tid;
        float den = EPSf;
        for (int f = 0; f < 128; f++) den = fmaf(Qst[f * PITCH + t], zs[f], den);
        for (int s = 0; s < 128; s++) den += Kst[s * PITCH + t];
        dinv[t] = 1.f / den;
    }
    __syncthreads();

    const int tg2 = tid >> 4, eg = tid & 15;
    float y[8][4];
#pragma unroll
    for (int i = 0; i < 8; i++)
#pragma unroll
        for (int j = 0; j < 4; j++) y[i][j] = 0.f;
    for (int s = 0; s < 128; s++) {
        float av[8], vv[4];
#pragma unroll
        for (int i = 0; i < 8; i++) av[i] = Kst[s * PITCH + tg2 + 16 * i];
#pragma unroll
        for (int j = 0; j < 4; j++) vv[j] = Vs[s * 64 + eg * 4 + j];
#pragma unroll
        for (int i = 0; i < 8; i++)
#pragma unroll
            for (int j = 0; j < 4; j++) y[i][j] = fmaf(av[i], vv[j], y[i][j]);
    }
    for (int f = 0; f < 128; f++) {
        float qv[8], sv[4];
#pragma unroll
        for (int i = 0; i < 8; i++) qv[i] = Qst[f * PITCH + tg2 + 16 * i];
#pragma unroll
        for (int j = 0; j < 4; j++) sv[j] = Ss[f * 64 + eg * 4 + j];
#pragma unroll
        for (int i = 0; i < 8; i++)
#pragma unroll
            for (int j = 0; j < 4; j++) y[i][j] = fmaf(qv[i], sv[j], y[i][j]);
    }
#pragma unroll
    for (int i = 0; i < 8; i++) {
        const int t = tg2 + 16 * i;
        const float di = dinv[t];
        float* yp = g_y + ((size_t)(b * Tt + c * CHK + t)) * Dm + h * HDm + eg * 4;
#pragma unroll
        for (int j = 0; j < 4; j++) yp[j] = y[i][j] * di;
    }
}

// ---------------------------------------------------------------------------
extern "C" void kernel_launch(void* const* d_in, const int* in_sizes, int n_in,
                              void* d_out, int out_size) {
    const float* x  = (const float*)d_in[0];
    const float* Wq = (const float*)d_in[1];
    const float* Wk = (const float*)d_in[2];
    const float* Wv = (const float*)d_in[3];
    const float* Wo = (const float*)d_in[4];
    const float* Wf = (const float*)d_in[5];
    float* out = (float*)d_out;

    cudaFuncSetAttribute(gemm_kernel,      cudaFuncAttributeMaxDynamicSharedMemorySize, GSMEM);
    cudaFuncSetAttribute(chunk_sum_kernel, cudaFuncAttributeMaxDynamicSharedMemorySize, SMEM3);
    cudaFuncSetAttribute(chunk_out_kernel, cudaFuncAttributeMaxDynamicSharedMemorySize, SMEM5);

    split_kernel<<<(MR * Dm / 4) / 256, 256>>>(x, 0);
    wsplit_kernel<<<dim3(32, 32, 4), 256>>>(Wq, Wk, Wv, Wo);
    gemm_kernel<<<dim3(8, 64, 3), 256, GSMEM>>>(nullptr, 0);
    feat_kernel<<<MR, 256>>>(Wf);
    chunk_sum_kernel<<<dim3(NCH, BH), 256, SMEM3>>>();
    prefix_kernel<<<dim3(32, BH), 256>>>();
    chunk_out_kernel<<<dim3(NCH, BH), 256, SMEM5>>>();
    split_kernel<<<(MR * Dm / 4) / 256, 256>>>(x, 1);
    gemm_kernel<<<dim3(8, 64, 1), 256, GSMEM>>>(out, 1);
}

// round 4
// speedup vs baseline: 2.4662x; 1.2896x over previous
#include <cuda_runtime.h>
#include <cuda_bf16.h>
#include <math.h>
#include <stdint.h>

// ---------------- problem constants ----------------
#define Bb   4
#define Tt   2048
#define Dm   1024
#define Hh   16
#define HDm  64
#define NFm  128
#define CHK  128
#define NCH  16
#define BH   64
#define MR   8192
#define EPSf 1e-6f
#define INV_SQRT_NF 0.08838834764831845f

#define QKV_OFF ((size_t)MR * Dm)

// ---------------- scratch ----------------
__device__ float g_qkv[3 * (size_t)MR * Dm];   // q | k | v
__device__ float g_y  [(size_t)MR * Dm];
__device__ float g_qp [(size_t)BH * Tt * NFm];
__device__ float g_kp [(size_t)BH * Tt * NFm];
__device__ float g_S  [(size_t)BH * NCH * NFm * HDm];
__device__ float g_z  [(size_t)BH * NCH * NFm];

__device__ __nv_bfloat16 g_xhi[(size_t)MR * Dm], g_xlo[(size_t)MR * Dm];
__device__ __nv_bfloat16 g_yhi[(size_t)MR * Dm], g_ylo[(size_t)MR * Dm];
__device__ __nv_bfloat16 g_wth[4 * (size_t)Dm * Dm], g_wtl[4 * (size_t)Dm * Dm]; // W^T: [n][k]

// ---------------- helpers ----------------
__device__ __forceinline__ uint32_t smem_u32(const void* p) {
    uint32_t a;
    asm("{ .reg .u64 t; cvta.to.shared.u64 t, %1; cvt.u32.u64 %0, t; }" : "=r"(a) : "l"(p));
    return a;
}

#define LDSM4(r0, r1, r2, r3, addr)                                          \
    asm volatile("ldmatrix.sync.aligned.m8n8.x4.shared.b16 {%0,%1,%2,%3}, [%4];" \
                 : "=r"(r0), "=r"(r1), "=r"(r2), "=r"(r3) : "r"(addr))

#define LDSM4T(r0, r1, r2, r3, addr)                                         \
    asm volatile("ldmatrix.sync.aligned.m8n8.x4.trans.shared.b16 {%0,%1,%2,%3}, [%4];" \
                 : "=r"(r0), "=r"(r1), "=r"(r2), "=r"(r3) : "r"(addr))

#define MMA16816(d, a0, a1, a2, a3, b0, b1)                                  \
    asm volatile("mma.sync.aligned.m16n8k16.row.col.f32.bf16.bf16.f32 "      \
                 "{%0,%1,%2,%3}, {%4,%5,%6,%7}, {%8,%9}, {%0,%1,%2,%3};"     \
                 : "+f"((d)[0]), "+f"((d)[1]), "+f"((d)[2]), "+f"((d)[3])    \
                 : "r"(a0), "r"(a1), "r"(a2), "r"(a3), "r"(b0), "r"(b1))

#define CP_ASYNC16(sa, g) \
    asm volatile("cp.async.cg.shared.global [%0], [%1], 16;" :: "r"(sa), "l"(g))

// hi/lo split of a pair of floats into two packed bf16x2 words
__device__ __forceinline__ void split2(float a, float b, uint32_t& hi, uint32_t& lo) {
    __nv_bfloat16 ha = __float2bfloat16(a), hb = __float2bfloat16(b);
    __nv_bfloat16 la = __float2bfloat16(a - __bfloat162float(ha));
    __nv_bfloat16 lb = __float2bfloat16(b - __bfloat162float(hb));
    hi = ((uint32_t)__bfloat16_as_ushort(hb) << 16) | __bfloat16_as_ushort(ha);
    lo = ((uint32_t)__bfloat16_as_ushort(lb) << 16) | __bfloat16_as_ushort(la);
}

// ---------------- K0: fp32 -> bf16 hi/lo split (x or y) ----------------
__global__ void __launch_bounds__(256) split_kernel(const float* __restrict__ xsrc, int mode) {
    const size_t i = (size_t)blockIdx.x * 256 + threadIdx.x;   // float4 index
    const float4 v = mode ? ((const float4*)g_y)[i] : ((const float4*)xsrc)[i];
    __nv_bfloat16* hi = mode ? g_yhi : g_xhi;
    __nv_bfloat16* lo = mode ? g_ylo : g_xlo;
    uint32_t h01, l01, h23, l23;
    split2(v.x, v.y, h01, l01);
    split2(v.z, v.w, h23, l23);
    *(uint2*)(hi + 4 * i) = make_uint2(h01, h23);
    *(uint2*)(lo + 4 * i) = make_uint2(l01, l23);
}

// ---------------- K0b: W transpose + split.  Wt[n][k] = W[k][n] ----------------
__global__ void __launch_bounds__(256) wsplit_kernel(const float* __restrict__ Wq,
                                                     const float* __restrict__ Wk,
                                                     const float* __restrict__ Wv,
                                                     const float* __restrict__ Wo) {
    __shared__ float t[32][33];
    const int z = blockIdx.z;
    const float* W = (z == 0) ? Wq : (z == 1) ? Wk : (z == 2) ? Wv : Wo;
    const int tx = threadIdx.x & 31, ty = threadIdx.x >> 5;   // 32 x 8
    const int bx = blockIdx.x, by = blockIdx.y;
#pragma unroll
    for (int j = 0; j < 4; j++) {
        int k = by * 32 + ty + j * 8;
        int n = bx * 32 + tx;
        t[ty + j * 8][tx] = W[(size_t)k * Dm + n];
    }
    __syncthreads();
#pragma unroll
    for (int j = 0; j < 4; j++) {
        int n = bx * 32 + ty + j * 8;
        int k = by * 32 + tx;
        float v = t[tx][ty + j * 8];
        __nv_bfloat16 hb = __float2bfloat16(v);
        __nv_bfloat16 lb = __float2bfloat16(v - __bfloat162float(hb));
        size_t o = (size_t)z * Dm * Dm + (size_t)n * Dm + k;
        g_wth[o] = hb;
        g_wtl[o] = lb;
    }
}

// ---------------- K1: HMMA split-bf16 GEMM  C(8192x1024) = A @ Wt^T -------------
#define TROW   80
#define TILE_B (128 * TROW)          // 10240
#define STG_B  (4 * TILE_B)          // 40960
#define GSMEM  (3 * STG_B)           // 122880

__global__ void __launch_bounds__(256, 1) gemm_kernel(float* __restrict__ Cout, int mode) {
    extern __shared__ char sm[];
    const uint32_t smb = smem_u32(sm);
    const int tid = threadIdx.x;
    const int z = blockIdx.z;
    const int m0 = blockIdx.y * 128, n0 = blockIdx.x * 128;

    const __nv_bfloat16 *Ahi, *Alo, *Bhi, *Blo;
    float* C;
    if (mode == 0) {
        Ahi = g_xhi; Alo = g_xlo;
        Bhi = g_wth + (size_t)z * Dm * Dm;
        Blo = g_wtl + (size_t)z * Dm * Dm;
        C = g_qkv + (size_t)z * QKV_OFF;
    } else {
        Ahi = g_yhi; Alo = g_ylo;
        Bhi = g_wth + (size_t)3 * Dm * Dm;
        Blo = g_wtl + (size_t)3 * Dm * Dm;
        C = Cout;
    }

    const int lq = tid >> 6, lu = tid & 63;
    const __nv_bfloat16* gp = (lq == 0) ? Ahi : (lq == 1) ? Alo : (lq == 2) ? Bhi : Blo;
    const int grow0 = (lq < 2) ? m0 : n0;
    const uint32_t sload0 = smb + lq * TILE_B;

#define LOAD_STAGE(buf, k0)                                                   \
    do {                                                                      \
        uint32_t sb_ = sload0 + (buf) * STG_B;                                \
        _Pragma("unroll")                                                     \
        for (int j_ = 0; j_ < 8; ++j_) {                                      \
            int lin_ = lu + 64 * j_;                                          \
            int r_ = lin_ >> 2, c_ = lin_ & 3;                                \
            CP_ASYNC16(sb_ + r_ * TROW + c_ * 16,                             \
                       gp + (size_t)(grow0 + r_) * Dm + (k0) + c_ * 8);       \
        }                                                                     \
    } while (0)

    const int lane = tid & 31, w = tid >> 5;
    const int wm = w & 3, wn = w >> 2;
    const int lj = lane >> 3, lm = lane & 7;
    const int arow = wm * 32 + (lj & 1) * 8 + lm;
    const int acho = lj >> 1;
    const int brow = wn * 64 + ((lj & 2) ? 8 : 0) + lm;
    const int bcho = lj & 1;

    float acc[2][8][4];
#pragma unroll
    for (int i = 0; i < 2; i++)
#pragma unroll
        for (int jn = 0; jn < 8; jn++)
#pragma unroll
            for (int r = 0; r < 4; r++) acc[i][jn][r] = 0.f;

    LOAD_STAGE(0, 0);
    asm volatile("cp.async.commit_group;" ::: "memory");
    LOAD_STAGE(1, 32);
    asm volatile("cp.async.commit_group;" ::: "memory");

    for (int it = 0; it < 32; ++it) {
        asm volatile("cp.async.wait_group 1;" ::: "memory");
        __syncthreads();
        const int nxt = it + 2;
        if (nxt < 32) LOAD_STAGE(nxt % 3, nxt * 32);
        asm volatile("cp.async.commit_group;" ::: "memory");

        const uint32_t buf = smb + (it % 3) * STG_B;
#pragma unroll
        for (int ks = 0; ks < 2; ++ks) {
            uint32_t ah[2][4], al[2][4], bh[4][4], bl[4][4];
#pragma unroll
            for (int i = 0; i < 2; ++i) {
                uint32_t ra = buf + (arow + i * 16) * TROW + (ks * 2 + acho) * 16;
                LDSM4(ah[i][0], ah[i][1], ah[i][2], ah[i][3], ra);
                LDSM4(al[i][0], al[i][1], al[i][2], al[i][3], ra + TILE_B);
            }
#pragma unroll
            for (int g = 0; g < 4; ++g) {
                uint32_t rb = buf + 2 * TILE_B + (brow + g * 16) * TROW + (ks * 2 + bcho) * 16;
                LDSM4(bh[g][0], bh[g][1], bh[g][2], bh[g][3], rb);
                LDSM4(bl[g][0], bl[g][1], bl[g][2], bl[g][3], rb + TILE_B);
            }
#pragma unroll
            for (int i = 0; i < 2; ++i)
#pragma unroll
                for (int jn = 0; jn < 8; ++jn) {
                    const int g = jn >> 1, hf = (jn & 1) * 2;
                    MMA16816(acc[i][jn], ah[i][0], ah[i][1], ah[i][2], ah[i][3],
                             bh[g][hf], bh[g][hf + 1]);
                    MMA16816(acc[i][jn], ah[i][0], ah[i][1], ah[i][2], ah[i][3],
                             bl[g][hf], bl[g][hf + 1]);
                    MMA16816(acc[i][jn], al[i][0], al[i][1], al[i][2], al[i][3],
                             bh[g][hf], bh[g][hf + 1]);
                }
        }
    }

#pragma unroll
    for (int i = 0; i < 2; ++i) {
        const int r0 = m0 + wm * 32 + i * 16 + (lane >> 2);
#pragma unroll
        for (int jn = 0; jn < 8; ++jn) {
            const int cc = n0 + wn * 64 + jn * 8 + 2 * (lane & 3);
            *(float2*)&C[(size_t)r0 * Dm + cc]       = make_float2(acc[i][jn][0], acc[i][jn][1]);
            *(float2*)&C[(size_t)(r0 + 8) * Dm + cc] = make_float2(acc[i][jn][2], acc[i][jn][3]);
        }
    }
#undef LOAD_STAGE
}

// ---------------- K2: FAVOR+ features. One CTA per token. Wf column in regs. ----
__global__ void __launch_bounds__(256) feat_kernel(const float* __restrict__ Wf) {
    __shared__ float rows[2][Dm];   // q row | k row
    __shared__ float sqs[32];
    const int bt = blockIdx.x, tid = threadIdx.x;
    ((float4*)rows[0])[tid] = ((const float4*)(g_qkv + (size_t)bt * Dm))[tid];
    ((float4*)rows[1])[tid] = ((const float4*)(g_qkv + QKV_OFF + (size_t)bt * Dm))[tid];
    const int sel = tid >> 7, f = tid & 127;
    float wcol[64];
#pragma unroll
    for (int d = 0; d < 64; ++d) wcol[d] = Wf[d * NFm + f];
    __syncthreads();
    if (tid < 32) {
        const int s2 = tid >> 4, h2 = tid & 15;
        const float* rp = &rows[s2][h2 * 64];
        float s = 0.f;
#pragma unroll
        for (int d = 0; d < 64; ++d) s = fmaf(rp[d], rp[d], s);
        sqs[tid] = 0.5f * s;
    }
    __syncthreads();
    float* dst = sel ? g_kp : g_qp;
    const int b = bt >> 11, t = bt & 2047;
    for (int h = 0; h < 16; ++h) {
        const float4* rp = (const float4*)&rows[sel][h * 64];
        float dot = 0.f;
#pragma unroll
        for (int q = 0; q < 16; ++q) {
            float4 rv = rp[q];
            dot = fmaf(rv.x, wcol[4 * q + 0], dot);
            dot = fmaf(rv.y, wcol[4 * q + 1], dot);
            dot = fmaf(rv.z, wcol[4 * q + 2], dot);
            dot = fmaf(rv.w, wcol[4 * q + 3], dot);
        }
        dst[(((size_t)(b * 16 + h)) * Tt + t) * NFm + f] =
            expf(dot - sqs[sel * 16 + h]) * INV_SQRT_NF;
    }
}

// ---------------- K3: chunk_sum via HMMA.  S[f][e] = sum_s K[s][f] V[s][e] -------
#define PKb 272                       // pitch for 128-wide bf16 rows
#define PVb 144                       // pitch for 64-wide bf16 rows
#define CS_KH 0
#define CS_KL (CS_KH + 128 * PKb)     // 34816
#define CS_VH (CS_KL + 128 * PKb)     // 69632
#define CS_VL (CS_VH + 128 * PVb)     // 88064
#define SMEM3 (CS_VL + 128 * PVb)     // 106496

__global__ void __launch_bounds__(256, 1) chunk_sum_kernel() {
    extern __shared__ char sm[];
    const uint32_t smb = smem_u32(sm);
    const int c = blockIdx.x, bh = blockIdx.y;
    const int b = bh >> 4, h = bh & 15;
    const int tid = threadIdx.x;
    const float* GV = g_qkv + 2 * QKV_OFF;
    const size_t kbase = ((size_t)bh * Tt + c * CHK) * NFm;
    const size_t vbase = ((size_t)(b * Tt + c * CHK)) * Dm + h * HDm;

    // K tile: 128 x 128 fp32 -> bf16 hi/lo
#pragma unroll
    for (int j = 0; j < 16; ++j) {
        int lin = tid + 256 * j;              // 4096 chunks of 4 floats
        int rr = lin >> 5, cc = lin & 31;
        float4 v = *(const float4*)(g_kp + kbase + (size_t)rr * NFm + cc * 4);
        uint32_t h01, l01, h23, l23;
        split2(v.x, v.y, h01, l01);
        split2(v.z, v.w, h23, l23);
        *(uint2*)(sm + CS_KH + rr * PKb + cc * 8) = make_uint2(h01, h23);
        *(uint2*)(sm + CS_KL + rr * PKb + cc * 8) = make_uint2(l01, l23);
    }
    // V tile: 128 x 64
#pragma unroll
    for (int j = 0; j < 8; ++j) {
        int lin = tid + 256 * j;
        int rr = lin >> 4, cc = lin & 15;
        float4 v = *(const float4*)(GV + vbase + (size_t)rr * Dm + cc * 4);
        uint32_t h01, l01, h23, l23;
        split2(v.x, v.y, h01, l01);
        split2(v.z, v.w, h23, l23);
        *(uint2*)(sm + CS_VH + rr * PVb + cc * 8) = make_uint2(h01, h23);
        *(uint2*)(sm + CS_VL + rr * PVb + cc * 8) = make_uint2(l01, l23);
    }
    __syncthreads();

    const int l = tid & 31, w = tid >> 5;
    const int m = l >> 3, r = l & 7;
    const int f0w = (w & 3) * 32, e0w = (w >> 2) * 32;
    const int sA = (m & 2) ? 8 : 0, fA = (m & 1) ? 8 : 0;   // A trans offsets
    const int sB = (m & 1) ? 8 : 0, eB = (m & 2) ? 8 : 0;   // B trans offsets

    float acc[2][4][4];
#pragma unroll
    for (int i = 0; i < 2; i++)
#pragma unroll
        for (int jn = 0; jn < 4; jn++)
#pragma unroll
            for (int q = 0; q < 4; q++) acc[i][jn][q] = 0.f;

    for (int s0 = 0; s0 < 128; s0 += 16) {
        uint32_t ah[2][4], al[2][4], bhf[2][4], blf[2][4];
#pragma unroll
        for (int i = 0; i < 2; ++i) {
            uint32_t ad = smb + CS_KH + (s0 + sA + r) * PKb + (f0w + i * 16 + fA) * 2;
            LDSM4T(ah[i][0], ah[i][1], ah[i][2], ah[i][3], ad);
            LDSM4T(al[i][0], al[i][1], al[i][2], al[i][3], ad + (CS_KL - CS_KH));
        }
#pragma unroll
        for (int j2 = 0; j2 < 2; ++j2) {
            uint32_t ad = smb + CS_VH + (s0 + sB + r) * PVb + (e0w + j2 * 16 + eB) * 2;
            LDSM4T(bhf[j2][0], bhf[j2][1], bhf[j2][2], bhf[j2][3], ad);
            LDSM4T(blf[j2][0], blf[j2][1], blf[j2][2], blf[j2][3], ad + (CS_VL - CS_VH));
        }
#pragma unroll
        for (int i = 0; i < 2; ++i)
#pragma unroll
            for (int jn = 0; jn < 4; ++jn) {
                const int j2 = jn >> 1, o = (jn & 1) * 2;
                MMA16816(acc[i][jn], ah[i][0], ah[i][1], ah[i][2], ah[i][3],
                         bhf[j2][o], bhf[j2][o + 1]);
                MMA16816(acc[i][jn], ah[i][0], ah[i][1], ah[i][2], ah[i][3],
                         blf[j2][o], blf[j2][o + 1]);
                MMA16816(acc[i][jn], al[i][0], al[i][1], al[i][2], al[i][3],
                         bhf[j2][o], bhf[j2][o + 1]);
            }
    }

    const size_t Sbase = ((size_t)bh * NCH + c) * (NFm * HDm);
#pragma unroll
    for (int i = 0; i < 2; ++i) {
        const int fr = f0w + i * 16 + (l >> 2);
#pragma unroll
        for (int jn = 0; jn < 4; ++jn) {
            const int ec = e0w + jn * 8 + (l & 3) * 2;
            *(float2*)(g_S + Sbase + (size_t)fr * HDm + ec) =
                make_float2(acc[i][jn][0], acc[i][jn][1]);
            *(float2*)(g_S + Sbase + (size_t)(fr + 8) * HDm + ec) =
                make_float2(acc[i][jn][2], acc[i][jn][3]);
        }
    }
    // z in fp32 straight from gmem (coalesced over f)
    if (tid < 128) {
        float zz = 0.f;
        for (int s = 0; s < 128; ++s) zz += g_kp[kbase + (size_t)s * NFm + tid];
        g_z[((size_t)bh * NCH + c) * NFm + tid] = zz;
    }
}

// ---------------- K4: exclusive prefix over chunks ----------------
__global__ void __launch_bounds__(256) prefix_kernel() {   // grid (32, BH)
    const int bh = blockIdx.y, seg = blockIdx.x;
    const int idx = seg * 256 + threadIdx.x;
    float v[NCH];
    const size_t base = (size_t)bh * NCH * NFm * HDm + idx;
#pragma unroll
    for (int c = 0; c < NCH; ++c) v[c] = g_S[base + (size_t)c * NFm * HDm];
    float acc = 0.f;
#pragma unroll
    for (int c = 0; c < NCH; ++c) { float cur = v[c]; v[c] = acc; acc += cur; }
#pragma unroll
    for (int c = 0; c < NCH; ++c) g_S[base + (size_t)c * NFm * HDm] = v[c];
    if (seg == 0 && threadIdx.x < NFm) {
        float zv[NCH];
        const size_t zb = (size_t)bh * NCH * NFm + threadIdx.x;
#pragma unroll
        for (int c = 0; c < NCH; ++c) zv[c] = g_z[zb + c * NFm];
        float az = 0.f;
#pragma unroll
        for (int c = 0; c < NCH; ++c) { float cur = zv[c]; zv[c] = az; az += cur; }
#pragma unroll
        for (int c = 0; c < NCH; ++c) g_z[zb + c * NFm] = zv[c];
    }
}

// ---------------- K5: chunk_out via HMMA ----------------
// Phase A: A_ts = tril(Q K^T).  Phase Y: Y = A V + Q S_prev, / den.
#define CO_QH 0
#define CO_QL (CO_QH + 128 * PKb)   // 34816
#define CO_KH (CO_QL + 128 * PKb)   // 69632  (reused as A hi after phase A)
#define CO_KL (CO_KH + 128 * PKb)   // 104448 (reused as A lo)
#define CO_VH (CO_KL + 128 * PKb)   // 139264
#define CO_VL (CO_VH + 128 * PVb)   // 157696
#define CO_SH (CO_VL + 128 * PVb)   // 176128
#define CO_SL (CO_SH + 128 * PVb)   // 194560
#define CO_Z  (CO_SL + 128 * PVb)   // 212992
#define CO_D  (CO_Z + 512)          // 213504
#define SMEM5 (CO_D + 512)          // 214016

__global__ void __launch_bounds__(256, 1) chunk_out_kernel() {
    extern __shared__ char sm[];
    const uint32_t smb = smem_u32(sm);
    const int c = blockIdx.x, bh = blockIdx.y;
    const int b = bh >> 4, h = bh & 15;
    const int tid = threadIdx.x;
    const float* GV = g_qkv + 2 * QKV_OFF;
    const size_t qbase = ((size_t)bh * Tt + c * CHK) * NFm;
    const size_t vbase = ((size_t)(b * Tt + c * CHK)) * Dm + h * HDm;
    const size_t Sbase = ((size_t)bh * NCH + c) * (NFm * HDm);

    // Q & K tiles: 128 x 128 fp32 -> bf16 hi/lo
#pragma unroll
    for (int j = 0; j < 16; ++j) {
        int lin = tid + 256 * j;
        int rr = lin >> 5, cc = lin & 31;
        float4 q4 = *(const float4*)(g_qp + qbase + (size_t)rr * NFm + cc * 4);
        float4 k4 = *(const float4*)(g_kp + qbase + (size_t)rr * NFm + cc * 4);
        uint32_t h01, l01, h23, l23;
        split2(q4.x, q4.y, h01, l01);
        split2(q4.z, q4.w, h23, l23);
        *(uint2*)(sm + CO_QH + rr * PKb + cc * 8) = make_uint2(h01, h23);
        *(uint2*)(sm + CO_QL + rr * PKb + cc * 8) = make_uint2(l01, l23);
        split2(k4.x, k4.y, h01, l01);
        split2(k4.z, k4.w, h23, l23);
        *(uint2*)(sm + CO_KH + rr * PKb + cc * 8) = make_uint2(h01, h23);
        *(uint2*)(sm + CO_KL + rr * PKb + cc * 8) = make_uint2(l01, l23);
    }
    // V & S_prev tiles: 128 x 64
#pragma unroll
    for (int j = 0; j < 8; ++j) {
        int lin = tid + 256 * j;
        int rr = lin >> 4, cc = lin & 15;
        float4 v4 = *(const float4*)(GV + vbase + (size_t)rr * Dm + cc * 4);
        uint32_t h01, l01, h23, l23;
        split2(v4.x, v4.y, h01, l01);
        split2(v4.z, v4.w, h23, l23);
        *(uint2*)(sm + CO_VH + rr * PVb + cc * 8) = make_uint2(h01, h23);
        *(uint2*)(sm + CO_VL + rr * PVb + cc * 8) = make_uint2(l01, l23);
        float4 s4 = *(const float4*)(g_S + Sbase + (size_t)rr * HDm + cc * 4);
        split2(s4.x, s4.y, h01, l01);
        split2(s4.z, s4.w, h23, l23);
        *(uint2*)(sm + CO_SH + rr * PVb + cc * 8) = make_uint2(h01, h23);
        *(uint2*)(sm + CO_SL + rr * PVb + cc * 8) = make_uint2(l01, l23);
    }
    if (tid < 128)
        ((float*)(sm + CO_Z))[tid] = g_z[((size_t)bh * NCH + c) * NFm + tid];
    __syncthreads();

    const int l = tid & 31, w = tid >> 5;
    const int wm = w & 3, wn = w >> 2;
    const int lj = l >> 3, lm = l & 7;
    const int m = l >> 3, r = l & 7;
    const int arow = wm * 32 + (lj & 1) * 8 + lm;        // natural A frag rows
    const int acho = lj >> 1;
    const int brow = ((lj & 2) ? 8 : 0) + lm;            // natural B frag rows (+ n-block)
    const int bcho = lj & 1;
    const int sB = (m & 1) ? 8 : 0, eB = (m & 2) ? 8 : 0; // trans B offsets

    // ---- Phase A: D[t][s] = sum_f Q[t][f] K[s][f] ----
    float accA[2][8][4];
#pragma unroll
    for (int i = 0; i < 2; i++)
#pragma unroll
        for (int jn = 0; jn < 8; jn++)
#pragma unroll
            for (int q = 0; q < 4; q++) accA[i][jn][q] = 0.f;

    for (int f0 = 0; f0 < 128; f0 += 16) {
        uint32_t qh[2][4], ql[2][4], kh[4][4], kl[4][4];
#pragma unroll
        for (int i = 0; i < 2; ++i) {
            uint32_t ad = smb + CO_QH + (arow + i * 16) * PKb + (f0 / 8 + acho) * 16;
            LDSM4(qh[i][0], qh[i][1], qh[i][2], qh[i][3], ad);
            LDSM4(ql[i][0], ql[i][1], ql[i][2], ql[i][3], ad + (CO_QL - CO_QH));
        }
#pragma unroll
        for (int g = 0; g < 4; ++g) {
            uint32_t ad = smb + CO_KH + (wn * 64 + brow + g * 16) * PKb + (f0 / 8 + bcho) * 16;
            LDSM4(kh[g][0], kh[g][1], kh[g][2], kh[g][3], ad);
            LDSM4(kl[g][0], kl[g][1], kl[g][2], kl[g][3], ad + (CO_KL - CO_KH));
        }
#pragma unroll
        for (int i = 0; i < 2; ++i)
#pragma unroll
            for (int jn = 0; jn < 8; ++jn) {
                const int g = jn >> 1, o = (jn & 1) * 2;
                MMA16816(accA[i][jn], qh[i][0], qh[i][1], qh[i][2], qh[i][3],
                         kh[g][o], kh[g][o + 1]);
                MMA16816(accA[i][jn], qh[i][0], qh[i][1], qh[i][2], qh[i][3],
                         kl[g][o], kl[g][o + 1]);
                MMA16816(accA[i][jn], ql[i][0], ql[i][1], ql[i][2], ql[i][3],
                         kh[g][o], kh[g][o + 1]);
            }
    }
    __syncthreads();   // all warps done reading K smem

    // masked A -> bf16 hi/lo in K's smem, layout [t][s] pitch PKb
#pragma unroll
    for (int i = 0; i < 2; ++i) {
        const int tr = wm * 32 + i * 16 + (l >> 2);
#pragma unroll
        for (int jn = 0; jn < 8; ++jn) {
            const int sc = wn * 64 + jn * 8 + (l & 3) * 2;
            float v0 = (sc     <= tr) ? accA[i][jn][0] : 0.f;
            float v1 = (sc + 1 <= tr) ? accA[i][jn][1] : 0.f;
            uint32_t hi, lo;
            split2(v0, v1, hi, lo);
            *(uint32_t*)(sm + CO_KH + tr * PKb + sc * 2) = hi;
            *(uint32_t*)(sm + CO_KL + tr * PKb + sc * 2) = lo;
            const int tr8 = tr + 8;
            v0 = (sc     <= tr8) ? accA[i][jn][2] : 0.f;
            v1 = (sc + 1 <= tr8) ? accA[i][jn][3] : 0.f;
            split2(v0, v1, hi, lo);
            *(uint32_t*)(sm + CO_KH + tr8 * PKb + sc * 2) = hi;
            *(uint32_t*)(sm + CO_KL + tr8 * PKb + sc * 2) = lo;
        }
    }
    __syncthreads();

    // denominator: den_t = eps + sum_f Q[t][f] z[f] + sum_s A[t][s]
    if (tid < 128) {
        const int t = tid;
        float den = EPSf;
        const float* zp = (const float*)(sm + CO_Z);
#pragma unroll 8
        for (int f2 = 0; f2 < 64; ++f2) {
            __nv_bfloat162 qh2 = *(__nv_bfloat162*)(sm + CO_QH + t * PKb + f2 * 4);
            __nv_bfloat162 ql2 = *(__nv_bfloat162*)(sm + CO_QL + t * PKb + f2 * 4);
            float2 fh = __bfloat1622float2(qh2), fl = __bfloat1622float2(ql2);
            den += (fh.x + fl.x) * zp[2 * f2] + (fh.y + fl.y) * zp[2 * f2 + 1];
        }
#pragma unroll 8
        for (int s2 = 0; s2 < 64; ++s2) {
            __nv_bfloat162 ah2 = *(__nv_bfloat162*)(sm + CO_KH + t * PKb + s2 * 4);
            __nv_bfloat162 al2 = *(__nv_bfloat162*)(sm + CO_KL + t * PKb + s2 * 4);
            float2 fa = __bfloat1622float2(ah2), fb = __bfloat1622float2(al2);
            den += fa.x + fa.y + fb.x + fb.y;
        }
        ((float*)(sm + CO_D))[t] = 1.f / den;
    }
    __syncthreads();

    // ---- Phase Y: D[t][e] = sum_s A[t][s] V[s][e] + sum_f Q[t][f] S[f][e] ----
    const int e0w = wn * 32;
    float accY[2][4][4];
#pragma unroll
    for (int i = 0; i < 2; i++)
#pragma unroll
        for (int jn = 0; jn < 4; jn++)
#pragma unroll
            for (int q = 0; q < 4; q++) accY[i][jn][q] = 0.f;

    // part 1: A(masked) @ V
    for (int s0 = 0; s0 < 128; s0 += 16) {
        uint32_t aah[2][4], aal[2][4], vh[2][4], vl[2][4];
#pragma unroll
        for (int i = 0; i < 2; ++i) {
            uint32_t ad = smb + CO_KH + (arow + i * 16) * PKb + (s0 / 8 + acho) * 16;
            LDSM4(aah[i][0], aah[i][1], aah[i][2], aah[i][3], ad);
            LDSM4(aal[i][0], aal[i][1], aal[i][2], aal[i][3], ad + (CO_KL - CO_KH));
        }
#pragma unroll
        for (int j2 = 0; j2 < 2; ++j2) {
            uint32_t ad = smb + CO_VH + (s0 + sB + r) * PVb + (e0w + j2 * 16 + eB) * 2;
            LDSM4T(vh[j2][0], vh[j2][1], vh[j2][2], vh[j2][3], ad);
            LDSM4T(vl[j2][0], vl[j2][1], vl[j2][2], vl[j2][3], ad + (CO_VL - CO_VH));
        }
#pragma unroll
        for (int i = 0; i < 2; ++i)
#pragma unroll
            for (int jn = 0; jn < 4; ++jn) {
                const int j2 = jn >> 1, o = (jn & 1) * 2;
                MMA16816(accY[i][jn], aah[i][0], aah[i][1], aah[i][2], aah[i][3],
                         vh[j2][o], vh[j2][o + 1]);
                MMA16816(accY[i][jn], aah[i][0], aah[i][1], aah[i][2], aah[i][3],
                         vl[j2][o], vl[j2][o + 1]);
                MMA16816(accY[i][jn], aal[i][0], aal[i][1], aal[i][2], aal[i][3],
                         vh[j2][o], vh[j2][o + 1]);
            }
    }
    // part 2: Q @ S_prev
    for (int f0 = 0; f0 < 128; f0 += 16) {
        uint32_t qh[2][4], ql[2][4], sh[2][4], sl[2][4];
#pragma unroll
        for (int i = 0; i < 2; ++i) {
            uint32_t ad = smb + CO_QH + (arow + i * 16) * PKb + (f0 / 8 + acho) * 16;
            LDSM4(qh[i][0], qh[i][1], qh[i][2], qh[i][3], ad);
            LDSM4(ql[i][0], ql[i][1], ql[i][2], ql[i][3], ad + (CO_QL - CO_QH));
        }
#pragma unroll
        for (int j2 = 0; j2 < 2; ++j2) {
            uint32_t ad = smb + CO_SH + (f0 + sB + r) * PVb + (e0w + j2 * 16 + eB) * 2;
            LDSM4T(sh[j2][0], sh[j2][1], sh[j2][2], sh[j2][3], ad);
            LDSM4T(sl[j2][0], sl[j2][1], sl[j2][2], sl[j2][3], ad + (CO_SL - CO_SH));
        }
#pragma unroll
        for (int i = 0; i < 2; ++i)
#pragma unroll
            for (int jn = 0; jn < 4; ++jn) {
                const int j2 = jn >> 1, o = (jn & 1) * 2;
                MMA16816(accY[i][jn], qh[i][0], qh[i][1], qh[i][2], qh[i][3],
                         sh[j2][o], sh[j2][o + 1]);
                MMA16816(accY[i][jn], qh[i][0], qh[i][1], qh[i][2], qh[i][3],
                         sl[j2][o], sl[j2][o + 1]);
                MMA16816(accY[i][jn], ql[i][0], ql[i][1], ql[i][2], ql[i][3],
                         sh[j2][o], sh[j2][o + 1]);
            }
    }

    // epilogue: divide by den, write y
    const float* dv = (const float*)(sm + CO_D);
#pragma unroll
    for (int i = 0; i < 2; ++i) {
        const int tr = wm * 32 + i * 16 + (l >> 2);
        const float d0 = dv[tr], d1 = dv[tr + 8];
#pragma unroll
        for (int jn = 0; jn < 4; ++jn) {
            const int ec = e0w + jn * 8 + (l & 3) * 2;
            float* yp = g_y + ((size_t)(b * Tt + c * CHK + tr)) * Dm + h * HDm + ec;
            *(float2*)yp = make_float2(accY[i][jn][0] * d0, accY[i][jn][1] * d0);
            float* yp8 = g_y + ((size_t)(b * Tt + c * CHK + tr + 8)) * Dm + h * HDm + ec;
            *(float2*)yp8 = make_float2(accY[i][jn][2] * d1, accY[i][jn][3] * d1);
        }
    }
}

// ---------------------------------------------------------------------------
extern "C" void kernel_launch(void* const* d_in, const int* in_sizes, int n_in,
                              void* d_out, int out_size) {
    const float* x  = (const float*)d_in[0];
    const float* Wq = (const float*)d_in[1];
    const float* Wk = (const float*)d_in[2];
    const float* Wv = (const float*)d_in[3];
    const float* Wo = (const float*)d_in[4];
    const float* Wf = (const float*)d_in[5];
    float* out = (float*)d_out;

    cudaFuncSetAttribute(gemm_kernel,      cudaFuncAttributeMaxDynamicSharedMemorySize, GSMEM);
    cudaFuncSetAttribute(chunk_sum_kernel, cudaFuncAttributeMaxDynamicSharedMemorySize, SMEM3);
    cudaFuncSetAttribute(chunk_out_kernel, cudaFuncAttributeMaxDynamicSharedMemorySize, SMEM5);

    split_kernel<<<(MR * Dm / 4) / 256, 256>>>(x, 0);
    wsplit_kernel<<<dim3(32, 32, 4), 256>>>(Wq, Wk, Wv, Wo);
    gemm_kernel<<<dim3(8, 64, 3), 256, GSMEM>>>(nullptr, 0);
    feat_kernel<<<MR, 256>>>(Wf);
    chunk_sum_kernel<<<dim3(NCH, BH), 256, SMEM3>>>();
    prefix_kernel<<<dim3(32, BH), 256>>>();
    chunk_out_kernel<<<dim3(NCH, BH), 256, SMEM5>>>();
    split_kernel<<<(MR * Dm / 4) / 256, 256>>>(x, 1);
    gemm_kernel<<<dim3(8, 64, 1), 256, GSMEM>>>(out, 1);
}

// round 6
// speedup vs baseline: 2.7609x; 1.1195x over previous
#include <cuda_runtime.h>
#include <cuda_bf16.h>
#include <math.h>
#include <stdint.h>

// ---------------- problem constants ----------------
#define Bb   4
#define Tt   2048
#define Dm   1024
#define Hh   16
#define HDm  64
#define NFm  128
#define CHK  128
#define NCH  16
#define BH   64
#define MR   8192
#define EPSf 1e-6f
#define INV_SQRT_NF 0.08838834764831845f

#define QKV_OFF ((size_t)MR * Dm)

// ---------------- scratch ----------------
__device__ float g_qkv[3 * (size_t)MR * Dm];   // q | k | v
__device__ float g_qp [(size_t)BH * Tt * NFm];
__device__ float g_kp [(size_t)BH * Tt * NFm];
__device__ float g_S  [(size_t)BH * NCH * NFm * HDm];
__device__ float g_z  [(size_t)BH * NCH * NFm];

__device__ __nv_bfloat16 g_xhi[(size_t)MR * Dm], g_xlo[(size_t)MR * Dm];
__device__ __nv_bfloat16 g_yhi[(size_t)MR * Dm], g_ylo[(size_t)MR * Dm];
__device__ __nv_bfloat16 g_wth[4 * (size_t)Dm * Dm], g_wtl[4 * (size_t)Dm * Dm]; // W^T: [n][k]

// ---------------- helpers ----------------
__device__ __forceinline__ uint32_t smem_u32(const void* p) {
    uint32_t a;
    asm("{ .reg .u64 t; cvta.to.shared.u64 t, %1; cvt.u32.u64 %0, t; }" : "=r"(a) : "l"(p));
    return a;
}

#define LDSM4(r0, r1, r2, r3, addr)                                          \
    asm volatile("ldmatrix.sync.aligned.m8n8.x4.shared.b16 {%0,%1,%2,%3}, [%4];" \
                 : "=r"(r0), "=r"(r1), "=r"(r2), "=r"(r3) : "r"(addr))

#define LDSM4T(r0, r1, r2, r3, addr)                                         \
    asm volatile("ldmatrix.sync.aligned.m8n8.x4.trans.shared.b16 {%0,%1,%2,%3}, [%4];" \
                 : "=r"(r0), "=r"(r1), "=r"(r2), "=r"(r3) : "r"(addr))

#define MMA16816(d, a0, a1, a2, a3, b0, b1)                                  \
    asm volatile("mma.sync.aligned.m16n8k16.row.col.f32.bf16.bf16.f32 "      \
                 "{%0,%1,%2,%3}, {%4,%5,%6,%7}, {%8,%9}, {%0,%1,%2,%3};"     \
                 : "+f"((d)[0]), "+f"((d)[1]), "+f"((d)[2]), "+f"((d)[3])    \
                 : "r"(a0), "r"(a1), "r"(a2), "r"(a3), "r"(b0), "r"(b1))

#define CP_ASYNC16(sa, g) \
    asm volatile("cp.async.cg.shared.global [%0], [%1], 16;" :: "r"(sa), "l"(g))

__device__ __forceinline__ void split2(float a, float b, uint32_t& hi, uint32_t& lo) {
    __nv_bfloat16 ha = __float2bfloat16(a), hb = __float2bfloat16(b);
    __nv_bfloat16 la = __float2bfloat16(a - __bfloat162float(ha));
    __nv_bfloat16 lb = __float2bfloat16(b - __bfloat162float(hb));
    hi = ((uint32_t)__bfloat16_as_ushort(hb) << 16) | __bfloat16_as_ushort(ha);
    lo = ((uint32_t)__bfloat16_as_ushort(lb) << 16) | __bfloat16_as_ushort(la);
}

// ---------------- K0: fp32 x -> bf16 hi/lo split ----------------
__global__ void __launch_bounds__(256) split_kernel(const float* __restrict__ xsrc) {
    const size_t i = (size_t)blockIdx.x * 256 + threadIdx.x;   // float4 index
    const float4 v = ((const float4*)xsrc)[i];
    uint32_t h01, l01, h23, l23;
    split2(v.x, v.y, h01, l01);
    split2(v.z, v.w, h23, l23);
    *(uint2*)(g_xhi + 4 * i) = make_uint2(h01, h23);
    *(uint2*)(g_xlo + 4 * i) = make_uint2(l01, l23);
}

// ---------------- K0b: W transpose + split.  Wt[n][k] = W[k][n] ----------------
__global__ void __launch_bounds__(256) wsplit_kernel(const float* __restrict__ Wq,
                                                     const float* __restrict__ Wk,
                                                     const float* __restrict__ Wv,
                                                     const float* __restrict__ Wo) {
    __shared__ float t[32][33];
    const int z = blockIdx.z;
    const float* W = (z == 0) ? Wq : (z == 1) ? Wk : (z == 2) ? Wv : Wo;
    const int tx = threadIdx.x & 31, ty = threadIdx.x >> 5;   // 32 x 8
    const int bx = blockIdx.x, by = blockIdx.y;
#pragma unroll
    for (int j = 0; j < 4; j++) {
        int k = by * 32 + ty + j * 8;
        int n = bx * 32 + tx;
        t[ty + j * 8][tx] = W[(size_t)k * Dm + n];
    }
    __syncthreads();
#pragma unroll
    for (int j = 0; j < 4; j++) {
        int n = bx * 32 + ty + j * 8;
        int k = by * 32 + tx;
        float v = t[tx][ty + j * 8];
        __nv_bfloat16 hb = __float2bfloat16(v);
        __nv_bfloat16 lb = __float2bfloat16(v - __bfloat162float(hb));
        size_t o = (size_t)z * Dm * Dm + (size_t)n * Dm + k;
        g_wth[o] = hb;
        g_wtl[o] = lb;
    }
}

// ---------------- K1: HMMA split-bf16 GEMM ----------------
#define TROW   80
#define TILE_B (128 * TROW)
#define STG_B  (4 * TILE_B)
#define GSMEM  (3 * STG_B)

__global__ void __launch_bounds__(256, 1) gemm_kernel(float* __restrict__ Cout, int mode) {
    extern __shared__ char sm[];
    const uint32_t smb = smem_u32(sm);
    const int tid = threadIdx.x;
    const int z = blockIdx.z;
    const int m0 = blockIdx.y * 128, n0 = blockIdx.x * 128;

    const __nv_bfloat16 *Ahi, *Alo, *Bhi, *Blo;
    float* C;
    if (mode == 0) {
        Ahi = g_xhi; Alo = g_xlo;
        Bhi = g_wth + (size_t)z * Dm * Dm;
        Blo = g_wtl + (size_t)z * Dm * Dm;
        C = g_qkv + (size_t)z * QKV_OFF;
    } else {
        Ahi = g_yhi; Alo = g_ylo;
        Bhi = g_wth + (size_t)3 * Dm * Dm;
        Blo = g_wtl + (size_t)3 * Dm * Dm;
        C = Cout;
    }

    const int lq = tid >> 6, lu = tid & 63;
    const __nv_bfloat16* gp = (lq == 0) ? Ahi : (lq == 1) ? Alo : (lq == 2) ? Bhi : Blo;
    const int grow0 = (lq < 2) ? m0 : n0;
    const uint32_t sload0 = smb + lq * TILE_B;

#define LOAD_STAGE(buf, k0)                                                   \
    do {                                                                      \
        uint32_t sb_ = sload0 + (buf) * STG_B;                                \
        _Pragma("unroll")                                                     \
        for (int j_ = 0; j_ < 8; ++j_) {                                      \
            int lin_ = lu + 64 * j_;                                          \
            int r_ = lin_ >> 2, c_ = lin_ & 3;                                \
            CP_ASYNC16(sb_ + r_ * TROW + c_ * 16,                             \
                       gp + (size_t)(grow0 + r_) * Dm + (k0) + c_ * 8);       \
        }                                                                     \
    } while (0)

    const int lane = tid & 31, w = tid >> 5;
    const int wm = w & 3, wn = w >> 2;
    const int lj = lane >> 3, lm = lane & 7;
    const int arow = wm * 32 + (lj & 1) * 8 + lm;
    const int acho = lj >> 1;
    const int brow = wn * 64 + ((lj & 2) ? 8 : 0) + lm;
    const int bcho = lj & 1;

    float acc[2][8][4];
#pragma unroll
    for (int i = 0; i < 2; i++)
#pragma unroll
        for (int jn = 0; jn < 8; jn++)
#pragma unroll
            for (int r = 0; r < 4; r++) acc[i][jn][r] = 0.f;

    LOAD_STAGE(0, 0);
    asm volatile("cp.async.commit_group;" ::: "memory");
    LOAD_STAGE(1, 32);
    asm volatile("cp.async.commit_group;" ::: "memory");

    for (int it = 0; it < 32; ++it) {
        asm volatile("cp.async.wait_group 1;" ::: "memory");
        __syncthreads();
        const int nxt = it + 2;
        if (nxt < 32) LOAD_STAGE(nxt % 3, nxt * 32);
        asm volatile("cp.async.commit_group;" ::: "memory");

        const uint32_t buf = smb + (it % 3) * STG_B;
#pragma unroll
        for (int ks = 0; ks < 2; ++ks) {
            uint32_t ah[2][4], al[2][4], bh[4][4], bl[4][4];
#pragma unroll
            for (int i = 0; i < 2; ++i) {
                uint32_t ra = buf + (arow + i * 16) * TROW + (ks * 2 + acho) * 16;
                LDSM4(ah[i][0], ah[i][1], ah[i][2], ah[i][3], ra);
                LDSM4(al[i][0], al[i][1], al[i][2], al[i][3], ra + TILE_B);
            }
#pragma unroll
            for (int g = 0; g < 4; ++g) {
                uint32_t rb = buf + 2 * TILE_B + (brow + g * 16) * TROW + (ks * 2 + bcho) * 16;
                LDSM4(bh[g][0], bh[g][1], bh[g][2], bh[g][3], rb);
                LDSM4(bl[g][0], bl[g][1], bl[g][2], bl[g][3], rb + TILE_B);
            }
#pragma unroll
            for (int i = 0; i < 2; ++i)
#pragma unroll
                for (int jn = 0; jn < 8; ++jn) {
                    const int g = jn >> 1, hf = (jn & 1) * 2;
                    MMA16816(acc[i][jn], ah[i][0], ah[i][1], ah[i][2], ah[i][3],
                             bh[g][hf], bh[g][hf + 1]);
                    MMA16816(acc[i][jn], ah[i][0], ah[i][1], ah[i][2], ah[i][3],
                             bl[g][hf], bl[g][hf + 1]);
                    MMA16816(acc[i][jn], al[i][0], al[i][1], al[i][2], al[i][3],
                             bh[g][hf], bh[g][hf + 1]);
                }
        }
    }

#pragma unroll
    for (int i = 0; i < 2; ++i) {
        const int r0 = m0 + wm * 32 + i * 16 + (lane >> 2);
#pragma unroll
        for (int jn = 0; jn < 8; ++jn) {
            const int cc = n0 + wn * 64 + jn * 8 + 2 * (lane & 3);
            *(float2*)&C[(size_t)r0 * Dm + cc]       = make_float2(acc[i][jn][0], acc[i][jn][1]);
            *(float2*)&C[(size_t)(r0 + 8) * Dm + cc] = make_float2(acc[i][jn][2], acc[i][jn][3]);
        }
    }
#undef LOAD_STAGE
}

// ---------------- K2: FAVOR+ features via HMMA + exp epilogue ----------------
// grid (MR/128, Hh, 2). CTA: 128 tokens x one head x {q|k}.
// phi = exp( row.Wf - 0.5||row||^2 ) * inv_sqrt_nf
#define FA_P 144                       // pitch bytes for 64 bf16 cols
#define FW_P 272                       // pitch bytes for 128 bf16 cols
#define FA_H 0
#define FA_L (FA_H + 128 * FA_P)       // 18432
#define FW_H (FA_L + 128 * FA_P)       // 36864
#define FW_L (FW_H + 64 * FW_P)        // 54272
#define FSQ  (FW_L + 64 * FW_P)        // 71680
#define FSM  (FSQ + 512)               // 72192

__global__ void __launch_bounds__(256) feat_kernel(const float* __restrict__ Wf) {
    extern __shared__ char sm[];
    const uint32_t smb = smem_u32(sm);
    const int tid = threadIdx.x;
    const int bt0 = blockIdx.x * 128, h = blockIdx.y, sel = blockIdx.z;
    const float* src = g_qkv + (size_t)sel * QKV_OFF;

    // A tile: 128 tokens x 64 dims fp32 -> bf16 hi/lo
#pragma unroll
    for (int j = 0; j < 8; ++j) {
        int lin = tid + 256 * j;               // 2048 float4s
        int rr = lin >> 4, cc = lin & 15;
        float4 v = *(const float4*)(src + (size_t)(bt0 + rr) * Dm + h * HDm + cc * 4);
        uint32_t h01, l01, h23, l23;
        split2(v.x, v.y, h01, l01);
        split2(v.z, v.w, h23, l23);
        *(uint2*)(sm + FA_H + rr * FA_P + cc * 8) = make_uint2(h01, h23);
        *(uint2*)(sm + FA_L + rr * FA_P + cc * 8) = make_uint2(l01, l23);
    }
    // W tile: 64 x 128 fp32 -> bf16 hi/lo (natural [d][f] layout)
#pragma unroll
    for (int j = 0; j < 8; ++j) {
        int lin = tid + 256 * j;               // 2048 float4s
        int rr = lin >> 5, cc = lin & 31;
        float4 v = *(const float4*)(Wf + (size_t)rr * NFm + cc * 4);
        uint32_t h01, l01, h23, l23;
        split2(v.x, v.y, h01, l01);
        split2(v.z, v.w, h23, l23);
        *(uint2*)(sm + FW_H + rr * FW_P + cc * 8) = make_uint2(h01, h23);
        *(uint2*)(sm + FW_L + rr * FW_P + cc * 8) = make_uint2(l01, l23);
    }
    __syncthreads();

    // sq per token from hi+lo reconstruction
    if (tid < 128) {
        float s = 0.f;
#pragma unroll
        for (int d2 = 0; d2 < 32; ++d2) {
            __nv_bfloat162 vh = *(__nv_bfloat162*)(sm + FA_H + tid * FA_P + d2 * 4);
            __nv_bfloat162 vl = *(__nv_bfloat162*)(sm + FA_L + tid * FA_P + d2 * 4);
            float2 fh = __bfloat1622float2(vh), fl = __bfloat1622float2(vl);
            float a = fh.x + fl.x, b = fh.y + fl.y;
            s = fmaf(a, a, fmaf(b, b, s));
        }
        ((float*)(sm + FSQ))[tid] = 0.5f * s;
    }
    __syncthreads();

    const int l = tid & 31, w = tid >> 5;      // warp w owns tokens w*16..+15
    const int lj = l >> 3, lm = l & 7;
    const int arow = w * 16 + (lj & 1) * 8 + lm;
    const int acho = lj >> 1;
    const int m = l >> 3, r = l & 7;
    const int sB = (m & 1) ? 8 : 0, eB = (m & 2) ? 8 : 0;

    float acc[16][4];
#pragma unroll
    for (int nb = 0; nb < 16; ++nb)
#pragma unroll
        for (int q = 0; q < 4; ++q) acc[nb][q] = 0.f;

#pragma unroll
    for (int ks = 0; ks < 4; ++ks) {           // d-chunks of 16
        uint32_t ah[4], al[4];
        uint32_t ad = smb + FA_H + arow * FA_P + (ks * 2 + acho) * 16;
        LDSM4(ah[0], ah[1], ah[2], ah[3], ad);
        LDSM4(al[0], al[1], al[2], al[3], ad + (FA_L - FA_H));
#pragma unroll
        for (int fg = 0; fg < 8; ++fg) {       // f-groups of 16
            uint32_t bhf[4], blf[4];
            uint32_t bd = smb + FW_H + (ks * 16 + sB + r) * FW_P + (fg * 16 + eB) * 2;
            LDSM4T(bhf[0], bhf[1], bhf[2], bhf[3], bd);
            LDSM4T(blf[0], blf[1], blf[2], blf[3], bd + (FW_L - FW_H));
#pragma unroll
            for (int hf = 0; hf < 2; ++hf) {
                const int nb = fg * 2 + hf;
                MMA16816(acc[nb], ah[0], ah[1], ah[2], ah[3], bhf[hf * 2], bhf[hf * 2 + 1]);
                MMA16816(acc[nb], ah[0], ah[1], ah[2], ah[3], blf[hf * 2], blf[hf * 2 + 1]);
                MMA16816(acc[nb], al[0], al[1], al[2], al[3], bhf[hf * 2], bhf[hf * 2 + 1]);
            }
        }
    }

    // epilogue: exp(dot - sq) * inv_sqrt_nf
    float* dst = sel ? g_kp : g_qp;
    const int b = bt0 >> 11;
    const int bh = b * Hh + h;
    const int trow0 = w * 16 + (l >> 2);
    const float* sqp = (const float*)(sm + FSQ);
    const float sq0 = sqp[trow0], sq1 = sqp[trow0 + 8];
    const int t0 = (bt0 & 2047) + trow0;
    float* d0 = dst + ((size_t)bh * Tt + t0) * NFm;
    float* d1 = dst + ((size_t)bh * Tt + t0 + 8) * NFm;
#pragma unroll
    for (int nb = 0; nb < 16; ++nb) {
        const int f = nb * 8 + (l & 3) * 2;
        *(float2*)(d0 + f) = make_float2(expf(acc[nb][0] - sq0) * INV_SQRT_NF,
                                         expf(acc[nb][1] - sq0) * INV_SQRT_NF);
        *(float2*)(d1 + f) = make_float2(expf(acc[nb][2] - sq1) * INV_SQRT_NF,
                                         expf(acc[nb][3] - sq1) * INV_SQRT_NF);
    }
}

// ---------------- K3: chunk_sum via HMMA ----------------
#define PKb 272
#define PVb 144
#define CS_KH 0
#define CS_KL (CS_KH + 128 * PKb)
#define CS_VH (CS_KL + 128 * PKb)
#define CS_VL (CS_VH + 128 * PVb)
#define SMEM3 (CS_VL + 128 * PVb)

__global__ void __launch_bounds__(256, 1) chunk_sum_kernel() {
    extern __shared__ char sm[];
    const uint32_t smb = smem_u32(sm);
    const int c = blockIdx.x, bh = blockIdx.y;
    const int b = bh >> 4, h = bh & 15;
    const int tid = threadIdx.x;
    const float* GV = g_qkv + 2 * QKV_OFF;
    const size_t kbase = ((size_t)bh * Tt + c * CHK) * NFm;
    const size_t vbase = ((size_t)(b * Tt + c * CHK)) * Dm + h * HDm;

#pragma unroll
    for (int j = 0; j < 16; ++j) {
        int lin = tid + 256 * j;
        int rr = lin >> 5, cc = lin & 31;
        float4 v = *(const float4*)(g_kp + kbase + (size_t)rr * NFm + cc * 4);
        uint32_t h01, l01, h23, l23;
        split2(v.x, v.y, h01, l01);
        split2(v.z, v.w, h23, l23);
        *(uint2*)(sm + CS_KH + rr * PKb + cc * 8) = make_uint2(h01, h23);
        *(uint2*)(sm + CS_KL + rr * PKb + cc * 8) = make_uint2(l01, l23);
    }
#pragma unroll
    for (int j = 0; j < 8; ++j) {
        int lin = tid + 256 * j;
        int rr = lin >> 4, cc = lin & 15;
        float4 v = *(const float4*)(GV + vbase + (size_t)rr * Dm + cc * 4);
        uint32_t h01, l01, h23, l23;
        split2(v.x, v.y, h01, l01);
        split2(v.z, v.w, h23, l23);
        *(uint2*)(sm + CS_VH + rr * PVb + cc * 8) = make_uint2(h01, h23);
        *(uint2*)(sm + CS_VL + rr * PVb + cc * 8) = make_uint2(l01, l23);
    }
    __syncthreads();

    const int l = tid & 31, w = tid >> 5;
    const int m = l >> 3, r = l & 7;
    const int f0w = (w & 3) * 32, e0w = (w >> 2) * 32;
    const int sA = (m & 2) ? 8 : 0, fA = (m & 1) ? 8 : 0;
    const int sB = (m & 1) ? 8 : 0, eB = (m & 2) ? 8 : 0;

    float acc[2][4][4];
#pragma unroll
    for (int i = 0; i < 2; i++)
#pragma unroll
        for (int jn = 0; jn < 4; jn++)
#pragma unroll
            for (int q = 0; q < 4; q++) acc[i][jn][q] = 0.f;

    for (int s0 = 0; s0 < 128; s0 += 16) {
        uint32_t ah[2][4], al[2][4], bhf[2][4], blf[2][4];
#pragma unroll
        for (int i = 0; i < 2; ++i) {
            uint32_t ad = smb + CS_KH + (s0 + sA + r) * PKb + (f0w + i * 16 + fA) * 2;
            LDSM4T(ah[i][0], ah[i][1], ah[i][2], ah[i][3], ad);
            LDSM4T(al[i][0], al[i][1], al[i][2], al[i][3], ad + (CS_KL - CS_KH));
        }
#pragma unroll
        for (int j2 = 0; j2 < 2; ++j2) {
            uint32_t ad = smb + CS_VH + (s0 + sB + r) * PVb + (e0w + j2 * 16 + eB) * 2;
            LDSM4T(bhf[j2][0], bhf[j2][1], bhf[j2][2], bhf[j2][3], ad);
            LDSM4T(blf[j2][0], blf[j2][1], blf[j2][2], blf[j2][3], ad + (CS_VL - CS_VH));
        }
#pragma unroll
        for (int i = 0; i < 2; ++i)
#pragma unroll
            for (int jn = 0; jn < 4; ++jn) {
                const int j2 = jn >> 1, o = (jn & 1) * 2;
                MMA16816(acc[i][jn], ah[i][0], ah[i][1], ah[i][2], ah[i][3],
                         bhf[j2][o], bhf[j2][o + 1]);
                MMA16816(acc[i][jn], ah[i][0], ah[i][1], ah[i][2], ah[i][3],
                         blf[j2][o], blf[j2][o + 1]);
                MMA16816(acc[i][jn], al[i][0], al[i][1], al[i][2], al[i][3],
                         bhf[j2][o], bhf[j2][o + 1]);
            }
    }

    const size_t Sbase = ((size_t)bh * NCH + c) * (NFm * HDm);
#pragma unroll
    for (int i = 0; i < 2; ++i) {
        const int fr = f0w + i * 16 + (l >> 2);
#pragma unroll
        for (int jn = 0; jn < 4; ++jn) {
            const int ec = e0w + jn * 8 + (l & 3) * 2;
            *(float2*)(g_S + Sbase + (size_t)fr * HDm + ec) =
                make_float2(acc[i][jn][0], acc[i][jn][1]);
            *(float2*)(g_S + Sbase + (size_t)(fr + 8) * HDm + ec) =
                make_float2(acc[i][jn][2], acc[i][jn][3]);
        }
    }
    if (tid < 128) {
        float zz = 0.f;
        for (int s = 0; s < 128; ++s) zz += g_kp[kbase + (size_t)s * NFm + tid];
        g_z[((size_t)bh * NCH + c) * NFm + tid] = zz;
    }
}

// ---------------- K4: exclusive prefix over chunks ----------------
__global__ void __launch_bounds__(256) prefix_kernel() {   // grid (32, BH)
    const int bh = blockIdx.y, seg = blockIdx.x;
    const int idx = seg * 256 + threadIdx.x;
    float v[NCH];
    const size_t base = (size_t)bh * NCH * NFm * HDm + idx;
#pragma unroll
    for (int c = 0; c < NCH; ++c) v[c] = g_S[base + (size_t)c * NFm * HDm];
    float acc = 0.f;
#pragma unroll
    for (int c = 0; c < NCH; ++c) { float cur = v[c]; v[c] = acc; acc += cur; }
#pragma unroll
    for (int c = 0; c < NCH; ++c) g_S[base + (size_t)c * NFm * HDm] = v[c];
    if (seg == 0 && threadIdx.x < NFm) {
        float zv[NCH];
        const size_t zb = (size_t)bh * NCH * NFm + threadIdx.x;
#pragma unroll
        for (int c = 0; c < NCH; ++c) zv[c] = g_z[zb + c * NFm];
        float az = 0.f;
#pragma unroll
        for (int c = 0; c < NCH; ++c) { float cur = zv[c]; zv[c] = az; az += cur; }
#pragma unroll
        for (int c = 0; c < NCH; ++c) g_z[zb + c * NFm] = zv[c];
    }
}

// ---------------- K5: chunk_out via HMMA (writes y as bf16 hi/lo) ----------------
#define CO_QH 0
#define CO_QL (CO_QH + 128 * PKb)
#define CO_KH (CO_QL + 128 * PKb)
#define CO_KL (CO_KH + 128 * PKb)
#define CO_VH (CO_KL + 128 * PKb)
#define CO_VL (CO_VH + 128 * PVb)
#define CO_SH (CO_VL + 128 * PVb)
#define CO_SL (CO_SH + 128 * PVb)
#define CO_Z  (CO_SL + 128 * PVb)
#define CO_D  (CO_Z + 512)
#define SMEM5 (CO_D + 512)

__global__ void __launch_bounds__(256, 1) chunk_out_kernel() {
    extern __shared__ char sm[];
    const uint32_t smb = smem_u32(sm);
    const int c = blockIdx.x, bh = blockIdx.y;
    const int b = bh >> 4, h = bh & 15;
    const int tid = threadIdx.x;
    const float* GV = g_qkv + 2 * QKV_OFF;
    const size_t qbase = ((size_t)bh * Tt + c * CHK) * NFm;
    const size_t vbase = ((size_t)(b * Tt + c * CHK)) * Dm + h * HDm;
    const size_t Sbase = ((size_t)bh * NCH + c) * (NFm * HDm);

#pragma unroll
    for (int j = 0; j < 16; ++j) {
        int lin = tid + 256 * j;
        int rr = lin >> 5, cc = lin & 31;
        float4 q4 = *(const float4*)(g_qp + qbase + (size_t)rr * NFm + cc * 4);
        float4 k4 = *(const float4*)(g_kp + qbase + (size_t)rr * NFm + cc * 4);
        uint32_t h01, l01, h23, l23;
        split2(q4.x, q4.y, h01, l01);
        split2(q4.z, q4.w, h23, l23);
        *(uint2*)(sm + CO_QH + rr * PKb + cc * 8) = make_uint2(h01, h23);
        *(uint2*)(sm + CO_QL + rr * PKb + cc * 8) = make_uint2(l01, l23);
        split2(k4.x, k4.y, h01, l01);
        split2(k4.z, k4.w, h23, l23);
        *(uint2*)(sm + CO_KH + rr * PKb + cc * 8) = make_uint2(h01, h23);
        *(uint2*)(sm + CO_KL + rr * PKb + cc * 8) = make_uint2(l01, l23);
    }
#pragma unroll
    for (int j = 0; j < 8; ++j) {
        int lin = tid + 256 * j;
        int rr = lin >> 4, cc = lin & 15;
        float4 v4 = *(const float4*)(GV + vbase + (size_t)rr * Dm + cc * 4);
        uint32_t h01, l01, h23, l23;
        split2(v4.x, v4.y, h01, l01);
        split2(v4.z, v4.w, h23, l23);
        *(uint2*)(sm + CO_VH + rr * PVb + cc * 8) = make_uint2(h01, h23);
        *(uint2*)(sm + CO_VL + rr * PVb + cc * 8) = make_uint2(l01, l23);
        float4 s4 = *(const float4*)(g_S + Sbase + (size_t)rr * HDm + cc * 4);
        split2(s4.x, s4.y, h01, l01);
        split2(s4.z, s4.w, h23, l23);
        *(uint2*)(sm + CO_SH + rr * PVb + cc * 8) = make_uint2(h01, h23);
        *(uint2*)(sm + CO_SL + rr * PVb + cc * 8) = make_uint2(l01, l23);
    }
    if (tid < 128)
        ((float*)(sm + CO_Z))[tid] = g_z[((size_t)bh * NCH + c) * NFm + tid];
    __syncthreads();

    const int l = tid & 31, w = tid >> 5;
    const int wm = w & 3, wn = w >> 2;
    const int lj = l >> 3, lm = l & 7;
    const int m = l >> 3, r = l & 7;
    const int arow = wm * 32 + (lj & 1) * 8 + lm;
    const int acho = lj >> 1;
    const int brow = ((lj & 2) ? 8 : 0) + lm;
    const int bcho = lj & 1;
    const int sB = (m & 1) ? 8 : 0, eB = (m & 2) ? 8 : 0;

    // ---- Phase A ----
    float accA[2][8][4];
#pragma unroll
    for (int i = 0; i < 2; i++)
#pragma unroll
        for (int jn = 0; jn < 8; jn++)
#pragma unroll
            for (int q = 0; q < 4; q++) accA[i][jn][q] = 0.f;

    for (int f0 = 0; f0 < 128; f0 += 16) {
        uint32_t qh[2][4], ql[2][4], kh[4][4], kl[4][4];
#pragma unroll
        for (int i = 0; i < 2; ++i) {
            uint32_t ad = smb + CO_QH + (arow + i * 16) * PKb + (f0 / 8 + acho) * 16;
            LDSM4(qh[i][0], qh[i][1], qh[i][2], qh[i][3], ad);
            LDSM4(ql[i][0], ql[i][1], ql[i][2], ql[i][3], ad + (CO_QL - CO_QH));
        }
#pragma unroll
        for (int g = 0; g < 4; ++g) {
            uint32_t ad = smb + CO_KH + (wn * 64 + brow + g * 16) * PKb + (f0 / 8 + bcho) * 16;
            LDSM4(kh[g][0], kh[g][1], kh[g][2], kh[g][3], ad);
            LDSM4(kl[g][0], kl[g][1], kl[g][2], kl[g][3], ad + (CO_KL - CO_KH));
        }
#pragma unroll
        for (int i = 0; i < 2; ++i)
#pragma unroll
            for (int jn = 0; jn < 8; ++jn) {
                const int g = jn >> 1, o = (jn & 1) * 2;
                MMA16816(accA[i][jn], qh[i][0], qh[i][1], qh[i][2], qh[i][3],
                         kh[g][o], kh[g][o + 1]);
                MMA16816(accA[i][jn], qh[i][0], qh[i][1], qh[i][2], qh[i][3],
                         kl[g][o], kl[g][o + 1]);
                MMA16816(accA[i][jn], ql[i][0], ql[i][1], ql[i][2], ql[i][3],
                         kh[g][o], kh[g][o + 1]);
            }
    }
    __syncthreads();

#pragma unroll
    for (int i = 0; i < 2; ++i) {
        const int tr = wm * 32 + i * 16 + (l >> 2);
#pragma unroll
        for (int jn = 0; jn < 8; ++jn) {
            const int sc = wn * 64 + jn * 8 + (l & 3) * 2;
            float v0 = (sc     <= tr) ? accA[i][jn][0] : 0.f;
            float v1 = (sc + 1 <= tr) ? accA[i][jn][1] : 0.f;
            uint32_t hi, lo;
            split2(v0, v1, hi, lo);
            *(uint32_t*)(sm + CO_KH + tr * PKb + sc * 2) = hi;
            *(uint32_t*)(sm + CO_KL + tr * PKb + sc * 2) = lo;
            const int tr8 = tr + 8;
            v0 = (sc     <= tr8) ? accA[i][jn][2] : 0.f;
            v1 = (sc + 1 <= tr8) ? accA[i][jn][3] : 0.f;
            split2(v0, v1, hi, lo);
            *(uint32_t*)(sm + CO_KH + tr8 * PKb + sc * 2) = hi;
            *(uint32_t*)(sm + CO_KL + tr8 * PKb + sc * 2) = lo;
        }
    }
    __syncthreads();

    if (tid < 128) {
        const int t = tid;
        float den = EPSf;
        const float* zp = (const float*)(sm + CO_Z);
#pragma unroll 8
        for (int f2 = 0; f2 < 64; ++f2) {
            __nv_bfloat162 qh2 = *(__nv_bfloat162*)(sm + CO_QH + t * PKb + f2 * 4);
            __nv_bfloat162 ql2 = *(__nv_bfloat162*)(sm + CO_QL + t * PKb + f2 * 4);
            float2 fh = __bfloat1622float2(qh2), fl = __bfloat1622float2(ql2);
            den += (fh.x + fl.x) * zp[2 * f2] + (fh.y + fl.y) * zp[2 * f2 + 1];
        }
#pragma unroll 8
        for (int s2 = 0; s2 < 64; ++s2) {
            __nv_bfloat162 ah2 = *(__nv_bfloat162*)(sm + CO_KH + t * PKb + s2 * 4);
            __nv_bfloat162 al2 = *(__nv_bfloat162*)(sm + CO_KL + t * PKb + s2 * 4);
            float2 fa = __bfloat1622float2(ah2), fb = __bfloat1622float2(al2);
            den += fa.x + fa.y + fb.x + fb.y;
        }
        ((float*)(sm + CO_D))[t] = 1.f / den;
    }
    __syncthreads();

    // ---- Phase Y ----
    const int e0w = wn * 32;
    float accY[2][4][4];
#pragma unroll
    for (int i = 0; i < 2; i++)
#pragma unroll
        for (int jn = 0; jn < 4; jn++)
#pragma unroll
            for (int q = 0; q < 4; q++) accY[i][jn][q] = 0.f;

    for (int s0 = 0; s0 < 128; s0 += 16) {
        uint32_t aah[2][4], aal[2][4], vh[2][4], vl[2][4];
#pragma unroll
        for (int i = 0; i < 2; ++i) {
            uint32_t ad = smb + CO_KH + (arow + i * 16) * PKb + (s0 / 8 + acho) * 16;
            LDSM4(aah[i][0], aah[i][1], aah[i][2], aah[i][3], ad);
            LDSM4(aal[i][0], aal[i][1], aal[i][2], aal[i][3], ad + (CO_KL - CO_KH));
        }
#pragma unroll
        for (int j2 = 0; j2 < 2; ++j2) {
            uint32_t ad = smb + CO_VH + (s0 + sB + r) * PVb + (e0w + j2 * 16 + eB) * 2;
            LDSM4T(vh[j2][0], vh[j2][1], vh[j2][2], vh[j2][3], ad);
            LDSM4T(vl[j2][0], vl[j2][1], vl[j2][2], vl[j2][3], ad + (CO_VL - CO_VH));
        }
#pragma unroll
        for (int i = 0; i < 2; ++i)
#pragma unroll
            for (int jn = 0; jn < 4; ++jn) {
                const int j2 = jn >> 1, o = (jn & 1) * 2;
                MMA16816(accY[i][jn], aah[i][0], aah[i][1], aah[i][2], aah[i][3],
                         vh[j2][o], vh[j2][o + 1]);
                MMA16816(accY[i][jn], aah[i][0], aah[i][1], aah[i][2], aah[i][3],
                         vl[j2][o], vl[j2][o + 1]);
                MMA16816(accY[i][jn], aal[i][0], aal[i][1], aal[i][2], aal[i][3],
                         vh[j2][o], vh[j2][o + 1]);
            }
    }
    for (int f0 = 0; f0 < 128; f0 += 16) {
        uint32_t qh[2][4], ql[2][4], sh[2][4], sl[2][4];
#pragma unroll
        for (int i = 0; i < 2; ++i) {
            uint32_t ad = smb + CO_QH + (arow + i * 16) * PKb + (f0 / 8 + acho) * 16;
            LDSM4(qh[i][0], qh[i][1], qh[i][2], qh[i][3], ad);
            LDSM4(ql[i][0], ql[i][1], ql[i][2], ql[i][3], ad + (CO_QL - CO_QH));
        }
#pragma unroll
        for (int j2 = 0; j2 < 2; ++j2) {
            uint32_t ad = smb + CO_SH + (f0 + sB + r) * PVb + (e0w + j2 * 16 + eB) * 2;
            LDSM4T(sh[j2][0], sh[j2][1], sh[j2][2], sh[j2][3], ad);
            LDSM4T(sl[j2][0], sl[j2][1], sl[j2][2], sl[j2][3], ad + (CO_SL - CO_SH));
        }
#pragma unroll
        for (int i = 0; i < 2; ++i)
#pragma unroll
            for (int jn = 0; jn < 4; ++jn) {
                const int j2 = jn >> 1, o = (jn & 1) * 2;
                MMA16816(accY[i][jn], qh[i][0], qh[i][1], qh[i][2], qh[i][3],
                         sh[j2][o], sh[j2][o + 1]);
                MMA16816(accY[i][jn], qh[i][0], qh[i][1], qh[i][2], qh[i][3],
                         sl[j2][o], sl[j2][o + 1]);
                MMA16816(accY[i][jn], ql[i][0], ql[i][1], ql[i][2], ql[i][3],
                         sh[j2][o], sh[j2][o + 1]);
            }
    }

    // epilogue: divide by den, write y as bf16 hi/lo directly
    const float* dv = (const float*)(sm + CO_D);
#pragma unroll
    for (int i = 0; i < 2; ++i) {
        const int tr = wm * 32 + i * 16 + (l >> 2);
        const float d0 = dv[tr], d1 = dv[tr + 8];
#pragma unroll
        for (int jn = 0; jn < 4; ++jn) {
            const int ec = e0w + jn * 8 + (l & 3) * 2;
            size_t o0 = ((size_t)(b * Tt + c * CHK + tr)) * Dm + h * HDm + ec;
            size_t o1 = ((size_t)(b * Tt + c * CHK + tr + 8)) * Dm + h * HDm + ec;
            uint32_t hi, lo;
            split2(accY[i][jn][0] * d0, accY[i][jn][1] * d0, hi, lo);
            *(uint32_t*)(g_yhi + o0) = hi;
            *(uint32_t*)(g_ylo + o0) = lo;
            split2(accY[i][jn][2] * d1, accY[i][jn][3] * d1, hi, lo);
            *(uint32_t*)(g_yhi + o1) = hi;
            *(uint32_t*)(g_ylo + o1) = lo;
        }
    }
}

// ---------------------------------------------------------------------------
extern "C" void kernel_launch(void* const* d_in, const int* in_sizes, int n_in,
                              void* d_out, int out_size) {
    const float* x  = (const float*)d_in[0];
    const float* Wq = (const float*)d_in[1];
    const float* Wk = (const float*)d_in[2];
    const float* Wv = (const float*)d_in[3];
    const float* Wo = (const float*)d_in[4];
    const float* Wf = (const float*)d_in[5];
    float* out = (float*)d_out;

    cudaFuncSetAttribute(gemm_kernel,      cudaFuncAttributeMaxDynamicSharedMemorySize, GSMEM);
    cudaFuncSetAttribute(feat_kernel,      cudaFuncAttributeMaxDynamicSharedMemorySize, FSM);
    cudaFuncSetAttribute(chunk_sum_kernel, cudaFuncAttributeMaxDynamicSharedMemorySize, SMEM3);
    cudaFuncSetAttribute(chunk_out_kernel, cudaFuncAttributeMaxDynamicSharedMemorySize, SMEM5);

    split_kernel<<<(MR * Dm / 4) / 256, 256>>>(x);
    wsplit_kernel<<<dim3(32, 32, 4), 256>>>(Wq, Wk, Wv, Wo);
    gemm_kernel<<<dim3(8, 64, 3), 256, GSMEM>>>(nullptr, 0);
    feat_kernel<<<dim3(MR / 128, Hh, 2), 256, FSM>>>(Wf);
    chunk_sum_kernel<<<dim3(NCH, BH), 256, SMEM3>>>();
    prefix_kernel<<<dim3(32, BH), 256>>>();
    chunk_out_kernel<<<dim3(NCH, BH), 256, SMEM5>>>();
    gemm_kernel<<<dim3(8, 64, 1), 256, GSMEM>>>(out, 1);
}

// round 7
// speedup vs baseline: 3.0773x; 1.1146x over previous
#include <cuda_runtime.h>
#include <cuda_bf16.h>
#include <cuda_fp16.h>
#include <math.h>
#include <stdint.h>

// ---------------- problem constants ----------------
#define Bb   4
#define Tt   2048
#define Dm   1024
#define Hh   16
#define HDm  64
#define NFm  128
#define CHK  128
#define NCH  16
#define BH   64
#define MR   8192
#define EPSf 1e-6f
#define INV_SQRT_NF 0.08838834764831845f

#define QKV_OFF ((size_t)MR * Dm)

// ---------------- scratch ----------------
__device__ float g_qkv[3 * (size_t)MR * Dm];   // q | k | v
__device__ float g_qp [(size_t)BH * Tt * NFm];
__device__ float g_kp [(size_t)BH * Tt * NFm];
__device__ float g_S  [(size_t)BH * NCH * NFm * HDm];
__device__ float g_z  [(size_t)BH * NCH * NFm];

__device__ __nv_bfloat16 g_xhi[(size_t)MR * Dm], g_xlo[(size_t)MR * Dm];     // x bf16 split (q,k)
__device__ __half        g_xh16[(size_t)MR * Dm], g_xl16[(size_t)MR * Dm];   // x fp16 split (v)
__device__ __half        g_yh16[(size_t)MR * Dm], g_yl16[(size_t)MR * Dm];   // y fp16 split (out)
__device__ __nv_bfloat16 g_wth[2 * (size_t)Dm * Dm], g_wtl[2 * (size_t)Dm * Dm]; // Wq,Wk ^T bf16
__device__ __half        g_wt16[2 * (size_t)Dm * Dm];                        // Wv,Wo ^T fp16

// ---------------- helpers ----------------
__device__ __forceinline__ uint32_t smem_u32(const void* p) {
    uint32_t a;
    asm("{ .reg .u64 t; cvta.to.shared.u64 t, %1; cvt.u32.u64 %0, t; }" : "=r"(a) : "l"(p));
    return a;
}

#define LDSM4(r0, r1, r2, r3, addr)                                          \
    asm volatile("ldmatrix.sync.aligned.m8n8.x4.shared.b16 {%0,%1,%2,%3}, [%4];" \
                 : "=r"(r0), "=r"(r1), "=r"(r2), "=r"(r3) : "r"(addr))

#define LDSM4T(r0, r1, r2, r3, addr)                                         \
    asm volatile("ldmatrix.sync.aligned.m8n8.x4.trans.shared.b16 {%0,%1,%2,%3}, [%4];" \
                 : "=r"(r0), "=r"(r1), "=r"(r2), "=r"(r3) : "r"(addr))

#define MMA16816(d, a0, a1, a2, a3, b0, b1)                                  \
    asm volatile("mma.sync.aligned.m16n8k16.row.col.f32.bf16.bf16.f32 "      \
                 "{%0,%1,%2,%3}, {%4,%5,%6,%7}, {%8,%9}, {%0,%1,%2,%3};"     \
                 : "+f"((d)[0]), "+f"((d)[1]), "+f"((d)[2]), "+f"((d)[3])    \
                 : "r"(a0), "r"(a1), "r"(a2), "r"(a3), "r"(b0), "r"(b1))

#define MMA16816H(d, a0, a1, a2, a3, b0, b1)                                 \
    asm volatile("mma.sync.aligned.m16n8k16.row.col.f32.f16.f16.f32 "        \
                 "{%0,%1,%2,%3}, {%4,%5,%6,%7}, {%8,%9}, {%0,%1,%2,%3};"     \
                 : "+f"((d)[0]), "+f"((d)[1]), "+f"((d)[2]), "+f"((d)[3])    \
                 : "r"(a0), "r"(a1), "r"(a2), "r"(a3), "r"(b0), "r"(b1))

#define CP_ASYNC16(sa, g) \
    asm volatile("cp.async.cg.shared.global [%0], [%1], 16;" :: "r"(sa), "l"(g))

__device__ __forceinline__ void split2(float a, float b, uint32_t& hi, uint32_t& lo) {
    __nv_bfloat16 ha = __float2bfloat16(a), hb = __float2bfloat16(b);
    __nv_bfloat16 la = __float2bfloat16(a - __bfloat162float(ha));
    __nv_bfloat16 lb = __float2bfloat16(b - __bfloat162float(hb));
    hi = ((uint32_t)__bfloat16_as_ushort(hb) << 16) | __bfloat16_as_ushort(ha);
    lo = ((uint32_t)__bfloat16_as_ushort(lb) << 16) | __bfloat16_as_ushort(la);
}

__device__ __forceinline__ void split2h(float a, float b, uint32_t& hi, uint32_t& lo) {
    __half ha = __float2half_rn(a), hb = __float2half_rn(b);
    __half la = __float2half_rn(a - __half2float(ha));
    __half lb = __float2half_rn(b - __half2float(hb));
    hi = ((uint32_t)__half_as_ushort(hb) << 16) | __half_as_ushort(ha);
    lo = ((uint32_t)__half_as_ushort(lb) << 16) | __half_as_ushort(la);
}

// ---------------- K0: fp32 x -> bf16 hi/lo + fp16 hi/lo ----------------
__global__ void __launch_bounds__(256) split_kernel(const float* __restrict__ xsrc) {
    const size_t i = (size_t)blockIdx.x * 256 + threadIdx.x;   // float4 index
    const float4 v = ((const float4*)xsrc)[i];
    uint32_t h01, l01, h23, l23;
    split2(v.x, v.y, h01, l01);
    split2(v.z, v.w, h23, l23);
    *(uint2*)(g_xhi + 4 * i) = make_uint2(h01, h23);
    *(uint2*)(g_xlo + 4 * i) = make_uint2(l01, l23);
    split2h(v.x, v.y, h01, l01);
    split2h(v.z, v.w, h23, l23);
    *(uint2*)(g_xh16 + 4 * i) = make_uint2(h01, h23);
    *(uint2*)(g_xl16 + 4 * i) = make_uint2(l01, l23);
}

// ---------------- K0b: W transpose + split ----------------
// z=0,1: Wq,Wk -> bf16 hi/lo.  z=2,3: Wv,Wo -> fp16 single.
__global__ void __launch_bounds__(256) wsplit_kernel(const float* __restrict__ Wq,
                                                     const float* __restrict__ Wk,
                                                     const float* __restrict__ Wv,
                                                     const float* __restrict__ Wo) {
    __shared__ float t[32][33];
    const int z = blockIdx.z;
    const float* W = (z == 0) ? Wq : (z == 1) ? Wk : (z == 2) ? Wv : Wo;
    const int tx = threadIdx.x & 31, ty = threadIdx.x >> 5;   // 32 x 8
    const int bx = blockIdx.x, by = blockIdx.y;
#pragma unroll
    for (int j = 0; j < 4; j++) {
        int k = by * 32 + ty + j * 8;
        int n = bx * 32 + tx;
        t[ty + j * 8][tx] = W[(size_t)k * Dm + n];
    }
    __syncthreads();
#pragma unroll
    for (int j = 0; j < 4; j++) {
        int n = bx * 32 + ty + j * 8;
        int k = by * 32 + tx;
        float v = t[tx][ty + j * 8];
        if (z < 2) {
            __nv_bfloat16 hb = __float2bfloat16(v);
            __nv_bfloat16 lb = __float2bfloat16(v - __bfloat162float(hb));
            size_t o = (size_t)z * Dm * Dm + (size_t)n * Dm + k;
            g_wth[o] = hb;
            g_wtl[o] = lb;
        } else {
            g_wt16[(size_t)(z - 2) * Dm * Dm + (size_t)n * Dm + k] = __float2half_rn(v);
        }
    }
}

// ---------------- K1a: 3-pass bf16 GEMM (q,k projections) ----------------
#define TROW   80
#define TILE_B (128 * TROW)
#define STG_B  (4 * TILE_B)
#define GSMEM  (3 * STG_B)

__global__ void __launch_bounds__(256, 1) gemm3p_kernel() {
    extern __shared__ char sm[];
    const uint32_t smb = smem_u32(sm);
    const int tid = threadIdx.x;
    const int z = blockIdx.z;                   // 0 = q, 1 = k
    const int m0 = blockIdx.y * 128, n0 = blockIdx.x * 128;

    const __nv_bfloat16* Ahi = g_xhi;
    const __nv_bfloat16* Alo = g_xlo;
    const __nv_bfloat16* Bhi = g_wth + (size_t)z * Dm * Dm;
    const __nv_bfloat16* Blo = g_wtl + (size_t)z * Dm * Dm;
    float* C = g_qkv + (size_t)z * QKV_OFF;

    const int lq = tid >> 6, lu = tid & 63;
    const __nv_bfloat16* gp = (lq == 0) ? Ahi : (lq == 1) ? Alo : (lq == 2) ? Bhi : Blo;
    const int grow0 = (lq < 2) ? m0 : n0;
    const uint32_t sload0 = smb + lq * TILE_B;

#define LOAD_STAGE3(buf, k0)                                                  \
    do {                                                                      \
        uint32_t sb_ = sload0 + (buf) * STG_B;                                \
        _Pragma("unroll")                                                     \
        for (int j_ = 0; j_ < 8; ++j_) {                                      \
            int lin_ = lu + 64 * j_;                                          \
            int r_ = lin_ >> 2, c_ = lin_ & 3;                                \
            CP_ASYNC16(sb_ + r_ * TROW + c_ * 16,                             \
                       gp + (size_t)(grow0 + r_) * Dm + (k0) + c_ * 8);       \
        }                                                                     \
    } while (0)

    const int lane = tid & 31, w = tid >> 5;
    const int wm = w & 3, wn = w >> 2;
    const int lj = lane >> 3, lm = lane & 7;
    const int arow = wm * 32 + (lj & 1) * 8 + lm;
    const int acho = lj >> 1;
    const int brow = wn * 64 + ((lj & 2) ? 8 : 0) + lm;
    const int bcho = lj & 1;

    float acc[2][8][4];
#pragma unroll
    for (int i = 0; i < 2; i++)
#pragma unroll
        for (int jn = 0; jn < 8; jn++)
#pragma unroll
            for (int r = 0; r < 4; r++) acc[i][jn][r] = 0.f;

    LOAD_STAGE3(0, 0);
    asm volatile("cp.async.commit_group;" ::: "memory");
    LOAD_STAGE3(1, 32);
    asm volatile("cp.async.commit_group;" ::: "memory");

    for (int it = 0; it < 32; ++it) {
        asm volatile("cp.async.wait_group 1;" ::: "memory");
        __syncthreads();
        const int nxt = it + 2;
        if (nxt < 32) LOAD_STAGE3(nxt % 3, nxt * 32);
        asm volatile("cp.async.commit_group;" ::: "memory");

        const uint32_t buf = smb + (it % 3) * STG_B;
#pragma unroll
        for (int ks = 0; ks < 2; ++ks) {
            uint32_t ah[2][4], al[2][4], bh[4][4], bl[4][4];
#pragma unroll
            for (int i = 0; i < 2; ++i) {
                uint32_t ra = buf + (arow + i * 16) * TROW + (ks * 2 + acho) * 16;
                LDSM4(ah[i][0], ah[i][1], ah[i][2], ah[i][3], ra);
                LDSM4(al[i][0], al[i][1], al[i][2], al[i][3], ra + TILE_B);
            }
#pragma unroll
            for (int g = 0; g < 4; ++g) {
                uint32_t rb = buf + 2 * TILE_B + (brow + g * 16) * TROW + (ks * 2 + bcho) * 16;
                LDSM4(bh[g][0], bh[g][1], bh[g][2], bh[g][3], rb);
                LDSM4(bl[g][0], bl[g][1], bl[g][2], bl[g][3], rb + TILE_B);
            }
#pragma unroll
            for (int i = 0; i < 2; ++i)
#pragma unroll
                for (int jn = 0; jn < 8; ++jn) {
                    const int g = jn >> 1, hf = (jn & 1) * 2;
                    MMA16816(acc[i][jn], ah[i][0], ah[i][1], ah[i][2], ah[i][3],
                             bh[g][hf], bh[g][hf + 1]);
                    MMA16816(acc[i][jn], ah[i][0], ah[i][1], ah[i][2], ah[i][3],
                             bl[g][hf], bl[g][hf + 1]);
                    MMA16816(acc[i][jn], al[i][0], al[i][1], al[i][2], al[i][3],
                             bh[g][hf], bh[g][hf + 1]);
                }
        }
    }

#pragma unroll
    for (int i = 0; i < 2; ++i) {
        const int r0 = m0 + wm * 32 + i * 16 + (lane >> 2);
#pragma unroll
        for (int jn = 0; jn < 8; ++jn) {
            const int cc = n0 + wn * 64 + jn * 8 + 2 * (lane & 3);
            *(float2*)&C[(size_t)r0 * Dm + cc]       = make_float2(acc[i][jn][0], acc[i][jn][1]);
            *(float2*)&C[(size_t)(r0 + 8) * Dm + cc] = make_float2(acc[i][jn][2], acc[i][jn][3]);
        }
    }
#undef LOAD_STAGE3
}

// ---------------- K1b: 2-pass fp16 GEMM (v projection / output) ----------------
#define STG2_B (3 * TILE_B)
#define G2SMEM (3 * STG2_B)    // 92160

__global__ void __launch_bounds__(256, 1) gemm2p_kernel(float* __restrict__ Cout, int mode) {
    extern __shared__ char sm[];
    const uint32_t smb = smem_u32(sm);
    const int tid = threadIdx.x;
    const int m0 = blockIdx.y * 128, n0 = blockIdx.x * 128;

    const __half *Ahi, *Alo, *B;
    float* C;
    if (mode == 0) {
        Ahi = g_xh16; Alo = g_xl16;
        B = g_wt16;                       // Wv^T
        C = g_qkv + 2 * QKV_OFF;
    } else {
        Ahi = g_yh16; Alo = g_yl16;
        B = g_wt16 + (size_t)Dm * Dm;     // Wo^T
        C = Cout;
    }

#define LOAD_STAGE2(buf, k0)                                                  \
    do {                                                                      \
        uint32_t sb_ = smb + (buf) * STG2_B;                                  \
        _Pragma("unroll")                                                     \
        for (int j_ = 0; j_ < 6; ++j_) {                                      \
            int lin_ = tid + 256 * j_;                                        \
            int tile_ = lin_ >> 9;                                            \
            int idx_ = lin_ & 511;                                            \
            int r_ = idx_ >> 2, c_ = idx_ & 3;                                \
            const __half* gp_ = (tile_ == 0) ? Ahi : (tile_ == 1) ? Alo : B;  \
            int gr_ = (tile_ < 2) ? (m0 + r_) : (n0 + r_);                    \
            CP_ASYNC16(sb_ + tile_ * TILE_B + r_ * TROW + c_ * 16,            \
                       gp_ + (size_t)gr_ * Dm + (k0) + c_ * 8);               \
        }                                                                     \
    } while (0)

    const int lane = tid & 31, w = tid >> 5;
    const int wm = w & 3, wn = w >> 2;
    const int lj = lane >> 3, lm = lane & 7;
    const int arow = wm * 32 + (lj & 1) * 8 + lm;
    const int acho = lj >> 1;
    const int brow = wn * 64 + ((lj & 2) ? 8 : 0) + lm;
    const int bcho = lj & 1;

    float acc[2][8][4];
#pragma unroll
    for (int i = 0; i < 2; i++)
#pragma unroll
        for (int jn = 0; jn < 8; jn++)
#pragma unroll
            for (int r = 0; r < 4; r++) acc[i][jn][r] = 0.f;

    LOAD_STAGE2(0, 0);
    asm volatile("cp.async.commit_group;" ::: "memory");
    LOAD_STAGE2(1, 32);
    asm volatile("cp.async.commit_group;" ::: "memory");

    for (int it = 0; it < 32; ++it) {
        asm volatile("cp.async.wait_group 1;" ::: "memory");
        __syncthreads();
        const int nxt = it + 2;
        if (nxt < 32) LOAD_STAGE2(nxt % 3, nxt * 32);
        asm volatile("cp.async.commit_group;" ::: "memory");

        const uint32_t buf = smb + (it % 3) * STG2_B;
#pragma unroll
        for (int ks = 0; ks < 2; ++ks) {
            uint32_t ah[2][4], al[2][4], bf[4][4];
#pragma unroll
            for (int i = 0; i < 2; ++i) {
                uint32_t ra = buf + (arow + i * 16) * TROW + (ks * 2 + acho) * 16;
                LDSM4(ah[i][0], ah[i][1], ah[i][2], ah[i][3], ra);
                LDSM4(al[i][0], al[i][1], al[i][2], al[i][3], ra + TILE_B);
            }
#pragma unroll
            for (int g = 0; g < 4; ++g) {
                uint32_t rb = buf + 2 * TILE_B + (brow + g * 16) * TROW + (ks * 2 + bcho) * 16;
                LDSM4(bf[g][0], bf[g][1], bf[g][2], bf[g][3], rb);
            }
#pragma unroll
            for (int i = 0; i < 2; ++i)
#pragma unroll
                for (int jn = 0; jn < 8; ++jn) {
                    const int g = jn >> 1, hf = (jn & 1) * 2;
                    MMA16816H(acc[i][jn], ah[i][0], ah[i][1], ah[i][2], ah[i][3],
                              bf[g][hf], bf[g][hf + 1]);
                    MMA16816H(acc[i][jn], al[i][0], al[i][1], al[i][2], al[i][3],
                              bf[g][hf], bf[g][hf + 1]);
                }
        }
    }

#pragma unroll
    for (int i = 0; i < 2; ++i) {
        const int r0 = m0 + wm * 32 + i * 16 + (lane >> 2);
#pragma unroll
        for (int jn = 0; jn < 8; ++jn) {
            const int cc = n0 + wn * 64 + jn * 8 + 2 * (lane & 3);
            *(float2*)&C[(size_t)r0 * Dm + cc]       = make_float2(acc[i][jn][0], acc[i][jn][1]);
            *(float2*)&C[(size_t)(r0 + 8) * Dm + cc] = make_float2(acc[i][jn][2], acc[i][jn][3]);
        }
    }
#undef LOAD_STAGE2
}

// ---------------- K2: FAVOR+ features via HMMA + exp epilogue ----------------
#define FA_P 144
#define FW_P 272
#define FA_H 0
#define FA_L (FA_H + 128 * FA_P)
#define FW_H (FA_L + 128 * FA_P)
#define FW_L (FW_H + 64 * FW_P)
#define FSQ  (FW_L + 64 * FW_P)
#define FSM  (FSQ + 512)

__global__ void __launch_bounds__(256) feat_kernel(const float* __restrict__ Wf) {
    extern __shared__ char sm[];
    const uint32_t smb = smem_u32(sm);
    const int tid = threadIdx.x;
    const int bt0 = blockIdx.x * 128, h = blockIdx.y, sel = blockIdx.z;
    const float* src = g_qkv + (size_t)sel * QKV_OFF;

#pragma unroll
    for (int j = 0; j < 8; ++j) {
        int lin = tid + 256 * j;
        int rr = lin >> 4, cc = lin & 15;
        float4 v = *(const float4*)(src + (size_t)(bt0 + rr) * Dm + h * HDm + cc * 4);
        uint32_t h01, l01, h23, l23;
        split2(v.x, v.y, h01, l01);
        split2(v.z, v.w, h23, l23);
        *(uint2*)(sm + FA_H + rr * FA_P + cc * 8) = make_uint2(h01, h23);
        *(uint2*)(sm + FA_L + rr * FA_P + cc * 8) = make_uint2(l01, l23);
    }
#pragma unroll
    for (int j = 0; j < 8; ++j) {
        int lin = tid + 256 * j;
        int rr = lin >> 5, cc = lin & 31;
        float4 v = *(const float4*)(Wf + (size_t)rr * NFm + cc * 4);
        uint32_t h01, l01, h23, l23;
        split2(v.x, v.y, h01, l01);
        split2(v.z, v.w, h23, l23);
        *(uint2*)(sm + FW_H + rr * FW_P + cc * 8) = make_uint2(h01, h23);
        *(uint2*)(sm + FW_L + rr * FW_P + cc * 8) = make_uint2(l01, l23);
    }
    __syncthreads();

    if (tid < 128) {
        float s = 0.f;
#pragma unroll
        for (int d2 = 0; d2 < 32; ++d2) {
            __nv_bfloat162 vh = *(__nv_bfloat162*)(sm + FA_H + tid * FA_P + d2 * 4);
            __nv_bfloat162 vl = *(__nv_bfloat162*)(sm + FA_L + tid * FA_P + d2 * 4);
            float2 fh = __bfloat1622float2(vh), fl = __bfloat1622float2(vl);
            float a = fh.x + fl.x, b = fh.y + fl.y;
            s = fmaf(a, a, fmaf(b, b, s));
        }
        ((float*)(sm + FSQ))[tid] = 0.5f * s;
    }
    __syncthreads();

    const int l = tid & 31, w = tid >> 5;
    const int lj = l >> 3, lm = l & 7;
    const int arow = w * 16 + (lj & 1) * 8 + lm;
    const int acho = lj >> 1;
    const int m = l >> 3, r = l & 7;
    const int sB = (m & 1) ? 8 : 0, eB = (m & 2) ? 8 : 0;

    float acc[16][4];
#pragma unroll
    for (int nb = 0; nb < 16; ++nb)
#pragma unroll
        for (int q = 0; q < 4; ++q) acc[nb][q] = 0.f;

#pragma unroll
    for (int ks = 0; ks < 4; ++ks) {
        uint32_t ah[4], al[4];
        uint32_t ad = smb + FA_H + arow * FA_P + (ks * 2 + acho) * 16;
        LDSM4(ah[0], ah[1], ah[2], ah[3], ad);
        LDSM4(al[0], al[1], al[2], al[3], ad + (FA_L - FA_H));
#pragma unroll
        for (int fg = 0; fg < 8; ++fg) {
            uint32_t bhf[4], blf[4];
            uint32_t bd = smb + FW_H + (ks * 16 + sB + r) * FW_P + (fg * 16 + eB) * 2;
            LDSM4T(bhf[0], bhf[1], bhf[2], bhf[3], bd);
            LDSM4T(blf[0], blf[1], blf[2], blf[3], bd + (FW_L - FW_H));
#pragma unroll
            for (int hf = 0; hf < 2; ++hf) {
                const int nb = fg * 2 + hf;
                MMA16816(acc[nb], ah[0], ah[1], ah[2], ah[3], bhf[hf * 2], bhf[hf * 2 + 1]);
                MMA16816(acc[nb], ah[0], ah[1], ah[2], ah[3], blf[hf * 2], blf[hf * 2 + 1]);
                MMA16816(acc[nb], al[0], al[1], al[2], al[3], bhf[hf * 2], bhf[hf * 2 + 1]);
            }
        }
    }

    float* dst = sel ? g_kp : g_qp;
    const int b = bt0 >> 11;
    const int bh = b * Hh + h;
    const int trow0 = w * 16 + (l >> 2);
    const float* sqp = (const float*)(sm + FSQ);
    const float sq0 = sqp[trow0], sq1 = sqp[trow0 + 8];
    const int t0 = (bt0 & 2047) + trow0;
    float* d0 = dst + ((size_t)bh * Tt + t0) * NFm;
    float* d1 = dst + ((size_t)bh * Tt + t0 + 8) * NFm;
#pragma unroll
    for (int nb = 0; nb < 16; ++nb) {
        const int f = nb * 8 + (l & 3) * 2;
        *(float2*)(d0 + f) = make_float2(expf(acc[nb][0] - sq0) * INV_SQRT_NF,
                                         expf(acc[nb][1] - sq0) * INV_SQRT_NF);
        *(float2*)(d1 + f) = make_float2(expf(acc[nb][2] - sq1) * INV_SQRT_NF,
                                         expf(acc[nb][3] - sq1) * INV_SQRT_NF);
    }
}

// ---------------- K3: chunk_sum via HMMA ----------------
#define PKb 272
#define PVb 144
#define CS_KH 0
#define CS_KL (CS_KH + 128 * PKb)
#define CS_VH (CS_KL + 128 * PKb)
#define CS_VL (CS_VH + 128 * PVb)
#define SMEM3 (CS_VL + 128 * PVb)

__global__ void __launch_bounds__(256, 1) chunk_sum_kernel() {
    extern __shared__ char sm[];
    const uint32_t smb = smem_u32(sm);
    const int c = blockIdx.x, bh = blockIdx.y;
    const int b = bh >> 4, h = bh & 15;
    const int tid = threadIdx.x;
    const float* GV = g_qkv + 2 * QKV_OFF;
    const size_t kbase = ((size_t)bh * Tt + c * CHK) * NFm;
    const size_t vbase = ((size_t)(b * Tt + c * CHK)) * Dm + h * HDm;

#pragma unroll
    for (int j = 0; j < 16; ++j) {
        int lin = tid + 256 * j;
        int rr = lin >> 5, cc = lin & 31;
        float4 v = *(const float4*)(g_kp + kbase + (size_t)rr * NFm + cc * 4);
        uint32_t h01, l01, h23, l23;
        split2(v.x, v.y, h01, l01);
        split2(v.z, v.w, h23, l23);
        *(uint2*)(sm + CS_KH + rr * PKb + cc * 8) = make_uint2(h01, h23);
        *(uint2*)(sm + CS_KL + rr * PKb + cc * 8) = make_uint2(l01, l23);
    }
#pragma unroll
    for (int j = 0; j < 8; ++j) {
        int lin = tid + 256 * j;
        int rr = lin >> 4, cc = lin & 15;
        float4 v = *(const float4*)(GV + vbase + (size_t)rr * Dm + cc * 4);
        uint32_t h01, l01, h23, l23;
        split2(v.x, v.y, h01, l01);
        split2(v.z, v.w, h23, l23);
        *(uint2*)(sm + CS_VH + rr * PVb + cc * 8) = make_uint2(h01, h23);
        *(uint2*)(sm + CS_VL + rr * PVb + cc * 8) = make_uint2(l01, l23);
    }
    __syncthreads();

    const int l = tid & 31, w = tid >> 5;
    const int m = l >> 3, r = l & 7;
    const int f0w = (w & 3) * 32, e0w = (w >> 2) * 32;
    const int sA = (m & 2) ? 8 : 0, fA = (m & 1) ? 8 : 0;
    const int sB = (m & 1) ? 8 : 0, eB = (m & 2) ? 8 : 0;

    float acc[2][4][4];
#pragma unroll
    for (int i = 0; i < 2; i++)
#pragma unroll
        for (int jn = 0; jn < 4; jn++)
#pragma unroll
            for (int q = 0; q < 4; q++) acc[i][jn][q] = 0.f;

    for (int s0 = 0; s0 < 128; s0 += 16) {
        uint32_t ah[2][4], al[2][4], bhf[2][4], blf[2][4];
#pragma unroll
        for (int i = 0; i < 2; ++i) {
            uint32_t ad = smb + CS_KH + (s0 + sA + r) * PKb + (f0w + i * 16 + fA) * 2;
            LDSM4T(ah[i][0], ah[i][1], ah[i][2], ah[i][3], ad);
            LDSM4T(al[i][0], al[i][1], al[i][2], al[i][3], ad + (CS_KL - CS_KH));
        }
#pragma unroll
        for (int j2 = 0; j2 < 2; ++j2) {
            uint32_t ad = smb + CS_VH + (s0 + sB + r) * PVb + (e0w + j2 * 16 + eB) * 2;
            LDSM4T(bhf[j2][0], bhf[j2][1], bhf[j2][2], bhf[j2][3], ad);
            LDSM4T(blf[j2][0], blf[j2][1], blf[j2][2], blf[j2][3], ad + (CS_VL - CS_VH));
        }
#pragma unroll
        for (int i = 0; i < 2; ++i)
#pragma unroll
            for (int jn = 0; jn < 4; ++jn) {
                const int j2 = jn >> 1, o = (jn & 1) * 2;
                MMA16816(acc[i][jn], ah[i][0], ah[i][1], ah[i][2], ah[i][3],
                         bhf[j2][o], bhf[j2][o + 1]);
                MMA16816(acc[i][jn], ah[i][0], ah[i][1], ah[i][2], ah[i][3],
                         blf[j2][o], blf[j2][o + 1]);
                MMA16816(acc[i][jn], al[i][0], al[i][1], al[i][2], al[i][3],
                         bhf[j2][o], bhf[j2][o + 1]);
            }
    }

    const size_t Sbase = ((size_t)bh * NCH + c) * (NFm * HDm);
#pragma unroll
    for (int i = 0; i < 2; ++i) {
        const int fr = f0w + i * 16 + (l >> 2);
#pragma unroll
        for (int jn = 0; jn < 4; ++jn) {
            const int ec = e0w + jn * 8 + (l & 3) * 2;
            *(float2*)(g_S + Sbase + (size_t)fr * HDm + ec) =
                make_float2(acc[i][jn][0], acc[i][jn][1]);
            *(float2*)(g_S + Sbase + (size_t)(fr + 8) * HDm + ec) =
                make_float2(acc[i][jn][2], acc[i][jn][3]);
        }
    }
    if (tid < 128) {
        float zz = 0.f;
        for (int s = 0; s < 128; ++s) zz += g_kp[kbase + (size_t)s * NFm + tid];
        g_z[((size_t)bh * NCH + c) * NFm + tid] = zz;
    }
}

// ---------------- K4: exclusive prefix over chunks ----------------
__global__ void __launch_bounds__(256) prefix_kernel() {   // grid (32, BH)
    const int bh = blockIdx.y, seg = blockIdx.x;
    const int idx = seg * 256 + threadIdx.x;
    float v[NCH];
    const size_t base = (size_t)bh * NCH * NFm * HDm + idx;
#pragma unroll
    for (int c = 0; c < NCH; ++c) v[c] = g_S[base + (size_t)c * NFm * HDm];
    float acc = 0.f;
#pragma unroll
    for (int c = 0; c < NCH; ++c) { float cur = v[c]; v[c] = acc; acc += cur; }
#pragma unroll
    for (int c = 0; c < NCH; ++c) g_S[base + (size_t)c * NFm * HDm] = v[c];
    if (seg == 0 && threadIdx.x < NFm) {
        float zv[NCH];
        const size_t zb = (size_t)bh * NCH * NFm + threadIdx.x;
#pragma unroll
        for (int c = 0; c < NCH; ++c) zv[c] = g_z[zb + c * NFm];
        float az = 0.f;
#pragma unroll
        for (int c = 0; c < NCH; ++c) { float cur = zv[c]; zv[c] = az; az += cur; }
#pragma unroll
        for (int c = 0; c < NCH; ++c) g_z[zb + c * NFm] = zv[c];
    }
}

// ---------------- K5: chunk_out via HMMA (writes y as fp16 hi/lo) ----------------
#define CO_QH 0
#define CO_QL (CO_QH + 128 * PKb)
#define CO_KH (CO_QL + 128 * PKb)
#define CO_KL (CO_KH + 128 * PKb)
#define CO_VH (CO_KL + 128 * PKb)
#define CO_VL (CO_VH + 128 * PVb)
#define CO_SH (CO_VL + 128 * PVb)
#define CO_SL (CO_SH + 128 * PVb)
#define CO_Z  (CO_SL + 128 * PVb)
#define CO_D  (CO_Z + 512)
#define SMEM5 (CO_D + 512)

__global__ void __launch_bounds__(256, 1) chunk_out_kernel() {
    extern __shared__ char sm[];
    const uint32_t smb = smem_u32(sm);
    const int c = blockIdx.x, bh = blockIdx.y;
    const int b = bh >> 4, h = bh & 15;
    const int tid = threadIdx.x;
    const float* GV = g_qkv + 2 * QKV_OFF;
    const size_t qbase = ((size_t)bh * Tt + c * CHK) * NFm;
    const size_t vbase = ((size_t)(b * Tt + c * CHK)) * Dm + h * HDm;
    const size_t Sbase = ((size_t)bh * NCH + c) * (NFm * HDm);

#pragma unroll
    for (int j = 0; j < 16; ++j) {
        int lin = tid + 256 * j;
        int rr = lin >> 5, cc = lin & 31;
        float4 q4 = *(const float4*)(g_qp + qbase + (size_t)rr * NFm + cc * 4);
        float4 k4 = *(const float4*)(g_kp + qbase + (size_t)rr * NFm + cc * 4);
        uint32_t h01, l01, h23, l23;
        split2(q4.x, q4.y, h01, l01);
        split2(q4.z, q4.w, h23, l23);
        *(uint2*)(sm + CO_QH + rr * PKb + cc * 8) = make_uint2(h01, h23);
        *(uint2*)(sm + CO_QL + rr * PKb + cc * 8) = make_uint2(l01, l23);
        split2(k4.x, k4.y, h01, l01);
        split2(k4.z, k4.w, h23, l23);
        *(uint2*)(sm + CO_KH + rr * PKb + cc * 8) = make_uint2(h01, h23);
        *(uint2*)(sm + CO_KL + rr * PKb + cc * 8) = make_uint2(l01, l23);
    }
#pragma unroll
    for (int j = 0; j < 8; ++j) {
        int lin = tid + 256 * j;
        int rr = lin >> 4, cc = lin & 15;
        float4 v4 = *(const float4*)(GV + vbase + (size_t)rr * Dm + cc * 4);
        uint32_t h01, l01, h23, l23;
        split2(v4.x, v4.y, h01, l01);
        split2(v4.z, v4.w, h23, l23);
        *(uint2*)(sm + CO_VH + rr * PVb + cc * 8) = make_uint2(h01, h23);
        *(uint2*)(sm + CO_VL + rr * PVb + cc * 8) = make_uint2(l01, l23);
        float4 s4 = *(const float4*)(g_S + Sbase + (size_t)rr * HDm + cc * 4);
        split2(s4.x, s4.y, h01, l01);
        split2(s4.z, s4.w, h23, l23);
        *(uint2*)(sm + CO_SH + rr * PVb + cc * 8) = make_uint2(h01, h23);
        *(uint2*)(sm + CO_SL + rr * PVb + cc * 8) = make_uint2(l01, l23);
    }
    if (tid < 128)
        ((float*)(sm + CO_Z))[tid] = g_z[((size_t)bh * NCH + c) * NFm + tid];
    __syncthreads();

    const int l = tid & 31, w = tid >> 5;
    const int wm = w & 3, wn = w >> 2;
    const int lj = l >> 3, lm = l & 7;
    const int m = l >> 3, r = l & 7;
    const int arow = wm * 32 + (lj & 1) * 8 + lm;
    const int acho = lj >> 1;
    const int brow = ((lj & 2) ? 8 : 0) + lm;
    const int bcho = lj & 1;
    const int sB = (m & 1) ? 8 : 0, eB = (m & 2) ? 8 : 0;

    float accA[2][8][4];
#pragma unroll
    for (int i = 0; i < 2; i++)
#pragma unroll
        for (int jn = 0; jn < 8; jn++)
#pragma unroll
            for (int q = 0; q < 4; q++) accA[i][jn][q] = 0.f;

    for (int f0 = 0; f0 < 128; f0 += 16) {
        uint32_t qh[2][4], ql[2][4], kh[4][4], kl[4][4];
#pragma unroll
        for (int i = 0; i < 2; ++i) {
            uint32_t ad = smb + CO_QH + (arow + i * 16) * PKb + (f0 / 8 + acho) * 16;
            LDSM4(qh[i][0], qh[i][1], qh[i][2], qh[i][3], ad);
            LDSM4(ql[i][0], ql[i][1], ql[i][2], ql[i][3], ad + (CO_QL - CO_QH));
        }
#pragma unroll
        for (int g = 0; g < 4; ++g) {
            uint32_t ad = smb + CO_KH + (wn * 64 + brow + g * 16) * PKb + (f0 / 8 + bcho) * 16;
            LDSM4(kh[g][0], kh[g][1], kh[g][2], kh[g][3], ad);
            LDSM4(kl[g][0], kl[g][1], kl[g][2], kl[g][3], ad + (CO_KL - CO_KH));
        }
#pragma unroll
        for (int i = 0; i < 2; ++i)
#pragma unroll
            for (int jn = 0; jn < 8; ++jn) {
                const int g = jn >> 1, o = (jn & 1) * 2;
                MMA16816(accA[i][jn], qh[i][0], qh[i][1], qh[i][2], qh[i][3],
                         kh[g][o], kh[g][o + 1]);
                MMA16816(accA[i][jn], qh[i][0], qh[i][1], qh[i][2], qh[i][3],
                         kl[g][o], kl[g][o + 1]);
                MMA16816(accA[i][jn], ql[i][0], ql[i][1], ql[i][2], ql[i][3],
                         kh[g][o], kh[g][o + 1]);
            }
    }
    __syncthreads();

#pragma unroll
    for (int i = 0; i < 2; ++i) {
        const int tr = wm * 32 + i * 16 + (l >> 2);
#pragma unroll
        for (int jn = 0; jn < 8; ++jn) {
            const int sc = wn * 64 + jn * 8 + (l & 3) * 2;
            float v0 = (sc     <= tr) ? accA[i][jn][0] : 0.f;
            float v1 = (sc + 1 <= tr) ? accA[i][jn][1] : 0.f;
            uint32_t hi, lo;
            split2(v0, v1, hi, lo);
            *(uint32_t*)(sm + CO_KH + tr * PKb + sc * 2) = hi;
            *(uint32_t*)(sm + CO_KL + tr * PKb + sc * 2) = lo;
            const int tr8 = tr + 8;
            v0 = (sc     <= tr8) ? accA[i][jn][2] : 0.f;
            v1 = (sc + 1 <= tr8) ? accA[i][jn][3] : 0.f;
            split2(v0, v1, hi, lo);
            *(uint32_t*)(sm + CO_KH + tr8 * PKb + sc * 2) = hi;
            *(uint32_t*)(sm + CO_KL + tr8 * PKb + sc * 2) = lo;
        }
    }
    __syncthreads();

    if (tid < 128) {
        const int t = tid;
        float den = EPSf;
        const float* zp = (const float*)(sm + CO_Z);
#pragma unroll 8
        for (int f2 = 0; f2 < 64; ++f2) {
            __nv_bfloat162 qh2 = *(__nv_bfloat162*)(sm + CO_QH + t * PKb + f2 * 4);
            __nv_bfloat162 ql2 = *(__nv_bfloat162*)(sm + CO_QL + t * PKb + f2 * 4);
            float2 fh = __bfloat1622float2(qh2), fl = __bfloat1622float2(ql2);
            den += (fh.x + fl.x) * zp[2 * f2] + (fh.y + fl.y) * zp[2 * f2 + 1];
        }
#pragma unroll 8
        for (int s2 = 0; s2 < 64; ++s2) {
            __nv_bfloat162 ah2 = *(__nv_bfloat162*)(sm + CO_KH + t * PKb + s2 * 4);
            __nv_bfloat162 al2 = *(__nv_bfloat162*)(sm + CO_KL + t * PKb + s2 * 4);
            float2 fa = __bfloat1622float2(ah2), fb = __bfloat1622float2(al2);
            den += fa.x + fa.y + fb.x + fb.y;
        }
        ((float*)(sm + CO_D))[t] = 1.f / den;
    }
    __syncthreads();

    const int e0w = wn * 32;
    float accY[2][4][4];
#pragma unroll
    for (int i = 0; i < 2; i++)
#pragma unroll
        for (int jn = 0; jn < 4; jn++)
#pragma unroll
            for (int q = 0; q < 4; q++) accY[i][jn][q] = 0.f;

    for (int s0 = 0; s0 < 128; s0 += 16) {
        uint32_t aah[2][4], aal[2][4], vh[2][4], vl[2][4];
#pragma unroll
        for (int i = 0; i < 2; ++i) {
            uint32_t ad = smb + CO_KH + (arow + i * 16) * PKb + (s0 / 8 + acho) * 16;
            LDSM4(aah[i][0], aah[i][1], aah[i][2], aah[i][3], ad);
            LDSM4(aal[i][0], aal[i][1], aal[i][2], aal[i][3], ad + (CO_KL - CO_KH));
        }
#pragma unroll
        for (int j2 = 0; j2 < 2; ++j2) {
            uint32_t ad = smb + CO_VH + (s0 + sB + r) * PVb + (e0w + j2 * 16 + eB) * 2;
            LDSM4T(vh[j2][0], vh[j2][1], vh[j2][2], vh[j2][3], ad);
            LDSM4T(vl[j2][0], vl[j2][1], vl[j2][2], vl[j2][3], ad + (CO_VL - CO_VH));
        }
#pragma unroll
        for (int i = 0; i < 2; ++i)
#pragma unroll
            for (int jn = 0; jn < 4; ++jn) {
                const int j2 = jn >> 1, o = (jn & 1) * 2;
                MMA16816(accY[i][jn], aah[i][0], aah[i][1], aah[i][2], aah[i][3],
                         vh[j2][o], vh[j2][o + 1]);
                MMA16816(accY[i][jn], aah[i][0], aah[i][1], aah[i][2], aah[i][3],
                         vl[j2][o], vl[j2][o + 1]);
                MMA16816(accY[i][jn], aal[i][0], aal[i][1], aal[i][2], aal[i][3],
                         vh[j2][o], vh[j2][o + 1]);
            }
    }
    for (int f0 = 0; f0 < 128; f0 += 16) {
        uint32_t qh[2][4], ql[2][4], sh[2][4], sl[2][4];
#pragma unroll
        for (int i = 0; i < 2; ++i) {
            uint32_t ad = smb + CO_QH + (arow + i * 16) * PKb + (f0 / 8 + acho) * 16;
            LDSM4(qh[i][0], qh[i][1], qh[i][2], qh[i][3], ad);
            LDSM4(ql[i][0], ql[i][1], ql[i][2], ql[i][3], ad + (CO_QL - CO_QH));
        }
#pragma unroll
        for (int j2 = 0; j2 < 2; ++j2) {
            uint32_t ad = smb + CO_SH + (f0 + sB + r) * PVb + (e0w + j2 * 16 + eB) * 2;
            LDSM4T(sh[j2][0], sh[j2][1], sh[j2][2], sh[j2][3], ad);
            LDSM4T(sl[j2][0], sl[j2][1], sl[j2][2], sl[j2][3], ad + (CO_SL - CO_SH));
        }
#pragma unroll
        for (int i = 0; i < 2; ++i)
#pragma unroll
            for (int jn = 0; jn < 4; ++jn) {
                const int j2 = jn >> 1, o = (jn & 1) * 2;
                MMA16816(accY[i][jn], qh[i][0], qh[i][1], qh[i][2], qh[i][3],
                         sh[j2][o], sh[j2][o + 1]);
                MMA16816(accY[i][jn], qh[i][0], qh[i][1], qh[i][2], qh[i][3],
                         sl[j2][o], sl[j2][o + 1]);
                MMA16816(accY[i][jn], ql[i][0], ql[i][1], ql[i][2], ql[i][3],
                         sh[j2][o], sh[j2][o + 1]);
            }
    }

    // epilogue: divide by den, write y as fp16 hi/lo
    const float* dv = (const float*)(sm + CO_D);
#pragma unroll
    for (int i = 0; i < 2; ++i) {
        const int tr = wm * 32 + i * 16 + (l >> 2);
        const float d0 = dv[tr], d1 = dv[tr + 8];
#pragma unroll
        for (int jn = 0; jn < 4; ++jn) {
            const int ec = e0w + jn * 8 + (l & 3) * 2;
            size_t o0 = ((size_t)(b * Tt + c * CHK + tr)) * Dm + h * HDm + ec;
            size_t o1 = ((size_t)(b * Tt + c * CHK + tr + 8)) * Dm + h * HDm + ec;
            uint32_t hi, lo;
            split2h(accY[i][jn][0] * d0, accY[i][jn][1] * d0, hi, lo);
            *(uint32_t*)(g_yh16 + o0) = hi;
            *(uint32_t*)(g_yl16 + o0) = lo;
            split2h(accY[i][jn][2] * d1, accY[i][jn][3] * d1, hi, lo);
            *(uint32_t*)(g_yh16 + o1) = hi;
            *(uint32_t*)(g_yl16 + o1) = lo;
        }
    }
}

// ---------------------------------------------------------------------------
extern "C" void kernel_launch(void* const* d_in, const int* in_sizes, int n_in,
                              void* d_out, int out_size) {
    const float* x  = (const float*)d_in[0];
    const float* Wq = (const float*)d_in[1];
    const float* Wk = (const float*)d_in[2];
    const float* Wv = (const float*)d_in[3];
    const float* Wo = (const float*)d_in[4];
    const float* Wf = (const float*)d_in[5];
    float* out = (float*)d_out;

    cudaFuncSetAttribute(gemm3p_kernel,    cudaFuncAttributeMaxDynamicSharedMemorySize, GSMEM);
    cudaFuncSetAttribute(gemm2p_kernel,    cudaFuncAttributeMaxDynamicSharedMemorySize, G2SMEM);
    cudaFuncSetAttribute(feat_kernel,      cudaFuncAttributeMaxDynamicSharedMemorySize, FSM);
    cudaFuncSetAttribute(chunk_sum_kernel, cudaFuncAttributeMaxDynamicSharedMemorySize, SMEM3);
    cudaFuncSetAttribute(chunk_out_kernel, cudaFuncAttributeMaxDynamicSharedMemorySize, SMEM5);

    split_kernel<<<(MR * Dm / 4) / 256, 256>>>(x);
    wsplit_kernel<<<dim3(32, 32, 4), 256>>>(Wq, Wk, Wv, Wo);
    gemm3p_kernel<<<dim3(8, 64, 2), 256, GSMEM>>>();            // q, k
    gemm2p_kernel<<<dim3(8, 64), 256, G2SMEM>>>(nullptr, 0);    // v
    feat_kernel<<<dim3(MR / 128, Hh, 2), 256, FSM>>>(Wf);
    chunk_sum_kernel<<<dim3(NCH, BH), 256, SMEM3>>>();
    prefix_kernel<<<dim3(32, BH), 256>>>();
    chunk_out_kernel<<<dim3(NCH, BH), 256, SMEM5>>>();
    gemm2p_kernel<<<dim3(8, 64), 256, G2SMEM>>>(out, 1);        // out
}

// round 8
// speedup vs baseline: 3.4342x; 1.1159x over previous
#include <cuda_runtime.h>
#include <cuda_bf16.h>
#include <cuda_fp16.h>
#include <math.h>
#include <stdint.h>

// ---------------- problem constants ----------------
#define Bb   4
#define Tt   2048
#define Dm   1024
#define Hh   16
#define HDm  64
#define NFm  128
#define CHK  128
#define NCH  16
#define BH   64
#define MR   8192
#define EPSf 1e-6f
#define INV_SQRT_NF 0.08838834764831845f

#define QKV_OFF ((size_t)MR * Dm)

// ---------------- scratch ----------------
__device__ float g_qkv[3 * (size_t)MR * Dm];   // q | k | v
__device__ float g_qp [(size_t)BH * Tt * NFm];
__device__ float g_kp [(size_t)BH * Tt * NFm];
__device__ float g_S  [(size_t)BH * NCH * NFm * HDm];
__device__ float g_z  [(size_t)BH * NCH * NFm];

__device__ __nv_bfloat16 g_xhi[(size_t)MR * Dm], g_xlo[(size_t)MR * Dm];     // x bf16 split (q,k)
__device__ __half        g_xh16[(size_t)MR * Dm], g_xl16[(size_t)MR * Dm];   // x fp16 split (v)
__device__ __half        g_yh16[(size_t)MR * Dm], g_yl16[(size_t)MR * Dm];   // y fp16 split (out)
__device__ __nv_bfloat16 g_wth[2 * (size_t)Dm * Dm], g_wtl[2 * (size_t)Dm * Dm]; // Wq,Wk ^T bf16
__device__ __half        g_wt16[2 * (size_t)Dm * Dm];                        // Wv,Wo ^T fp16

// ---------------- helpers ----------------
__device__ __forceinline__ uint32_t smem_u32(const void* p) {
    uint32_t a;
    asm("{ .reg .u64 t; cvta.to.shared.u64 t, %1; cvt.u32.u64 %0, t; }" : "=r"(a) : "l"(p));
    return a;
}

#define LDSM4(r0, r1, r2, r3, addr)                                          \
    asm volatile("ldmatrix.sync.aligned.m8n8.x4.shared.b16 {%0,%1,%2,%3}, [%4];" \
                 : "=r"(r0), "=r"(r1), "=r"(r2), "=r"(r3) : "r"(addr))

#define LDSM4T(r0, r1, r2, r3, addr)                                         \
    asm volatile("ldmatrix.sync.aligned.m8n8.x4.trans.shared.b16 {%0,%1,%2,%3}, [%4];" \
                 : "=r"(r0), "=r"(r1), "=r"(r2), "=r"(r3) : "r"(addr))

#define MMA16816(d, a0, a1, a2, a3, b0, b1)                                  \
    asm volatile("mma.sync.aligned.m16n8k16.row.col.f32.bf16.bf16.f32 "      \
                 "{%0,%1,%2,%3}, {%4,%5,%6,%7}, {%8,%9}, {%0,%1,%2,%3};"     \
                 : "+f"((d)[0]), "+f"((d)[1]), "+f"((d)[2]), "+f"((d)[3])    \
                 : "r"(a0), "r"(a1), "r"(a2), "r"(a3), "r"(b0), "r"(b1))

#define MMA16816H(d, a0, a1, a2, a3, b0, b1)                                 \
    asm volatile("mma.sync.aligned.m16n8k16.row.col.f32.f16.f16.f32 "        \
                 "{%0,%1,%2,%3}, {%4,%5,%6,%7}, {%8,%9}, {%0,%1,%2,%3};"     \
                 : "+f"((d)[0]), "+f"((d)[1]), "+f"((d)[2]), "+f"((d)[3])    \
                 : "r"(a0), "r"(a1), "r"(a2), "r"(a3), "r"(b0), "r"(b1))

#define CP_ASYNC16(sa, g) \
    asm volatile("cp.async.cg.shared.global [%0], [%1], 16;" :: "r"(sa), "l"(g))

__device__ __forceinline__ void split2(float a, float b, uint32_t& hi, uint32_t& lo) {
    __nv_bfloat16 ha = __float2bfloat16(a), hb = __float2bfloat16(b);
    __nv_bfloat16 la = __float2bfloat16(a - __bfloat162float(ha));
    __nv_bfloat16 lb = __float2bfloat16(b - __bfloat162float(hb));
    hi = ((uint32_t)__bfloat16_as_ushort(hb) << 16) | __bfloat16_as_ushort(ha);
    lo = ((uint32_t)__bfloat16_as_ushort(lb) << 16) | __bfloat16_as_ushort(la);
}

__device__ __forceinline__ void split2h(float a, float b, uint32_t& hi, uint32_t& lo) {
    __half ha = __float2half_rn(a), hb = __float2half_rn(b);
    __half la = __float2half_rn(a - __half2float(ha));
    __half lb = __float2half_rn(b - __half2float(hb));
    hi = ((uint32_t)__half_as_ushort(hb) << 16) | __half_as_ushort(ha);
    lo = ((uint32_t)__half_as_ushort(lb) << 16) | __half_as_ushort(la);
}

// ---------------- K0: fp32 x -> bf16 hi/lo + fp16 hi/lo ----------------
__global__ void __launch_bounds__(256) split_kernel(const float* __restrict__ xsrc) {
    const size_t i = (size_t)blockIdx.x * 256 + threadIdx.x;   // float4 index
    const float4 v = ((const float4*)xsrc)[i];
    uint32_t h01, l01, h23, l23;
    split2(v.x, v.y, h01, l01);
    split2(v.z, v.w, h23, l23);
    *(uint2*)(g_xhi + 4 * i) = make_uint2(h01, h23);
    *(uint2*)(g_xlo + 4 * i) = make_uint2(l01, l23);
    split2h(v.x, v.y, h01, l01);
    split2h(v.z, v.w, h23, l23);
    *(uint2*)(g_xh16 + 4 * i) = make_uint2(h01, h23);
    *(uint2*)(g_xl16 + 4 * i) = make_uint2(l01, l23);
}

// ---------------- K0b: W transpose + split ----------------
__global__ void __launch_bounds__(256) wsplit_kernel(const float* __restrict__ Wq,
                                                     const float* __restrict__ Wk,
                                                     const float* __restrict__ Wv,
                                                     const float* __restrict__ Wo) {
    __shared__ float t[32][33];
    const int z = blockIdx.z;
    const float* W = (z == 0) ? Wq : (z == 1) ? Wk : (z == 2) ? Wv : Wo;
    const int tx = threadIdx.x & 31, ty = threadIdx.x >> 5;   // 32 x 8
    const int bx = blockIdx.x, by = blockIdx.y;
#pragma unroll
    for (int j = 0; j < 4; j++) {
        int k = by * 32 + ty + j * 8;
        int n = bx * 32 + tx;
        t[ty + j * 8][tx] = W[(size_t)k * Dm + n];
    }
    __syncthreads();
#pragma unroll
    for (int j = 0; j < 4; j++) {
        int n = bx * 32 + ty + j * 8;
        int k = by * 32 + tx;
        float v = t[tx][ty + j * 8];
        if (z < 2) {
            __nv_bfloat16 hb = __float2bfloat16(v);
            __nv_bfloat16 lb = __float2bfloat16(v - __bfloat162float(hb));
            size_t o = (size_t)z * Dm * Dm + (size_t)n * Dm + k;
            g_wth[o] = hb;
            g_wtl[o] = lb;
        } else {
            g_wt16[(size_t)(z - 2) * Dm * Dm + (size_t)n * Dm + k] = __float2half_rn(v);
        }
    }
}

// ---------------- K1a: 3-pass bf16 GEMM (q,k), 2 stages, 2 CTAs/SM ----------------
#define TROW   80
#define TILE_B (128 * TROW)
#define STG_B  (4 * TILE_B)          // 40960
#define GSMEM  (2 * STG_B)           // 81920

__global__ void __launch_bounds__(256, 2) gemm3p_kernel() {
    extern __shared__ char sm[];
    const uint32_t smb = smem_u32(sm);
    const int tid = threadIdx.x;
    const int z = blockIdx.z;                   // 0 = q, 1 = k
    const int m0 = blockIdx.y * 128, n0 = blockIdx.x * 128;

    const __nv_bfloat16* Ahi = g_xhi;
    const __nv_bfloat16* Alo = g_xlo;
    const __nv_bfloat16* Bhi = g_wth + (size_t)z * Dm * Dm;
    const __nv_bfloat16* Blo = g_wtl + (size_t)z * Dm * Dm;
    float* C = g_qkv + (size_t)z * QKV_OFF;

    const int lq = tid >> 6, lu = tid & 63;
    const __nv_bfloat16* gp = (lq == 0) ? Ahi : (lq == 1) ? Alo : (lq == 2) ? Bhi : Blo;
    const int grow0 = (lq < 2) ? m0 : n0;
    const uint32_t sload0 = smb + lq * TILE_B;

#define LOAD_STAGE3(buf, k0)                                                  \
    do {                                                                      \
        uint32_t sb_ = sload0 + (buf) * STG_B;                                \
        _Pragma("unroll")                                                     \
        for (int j_ = 0; j_ < 8; ++j_) {                                      \
            int lin_ = lu + 64 * j_;                                          \
            int r_ = lin_ >> 2, c_ = lin_ & 3;                                \
            CP_ASYNC16(sb_ + r_ * TROW + c_ * 16,                             \
                       gp + (size_t)(grow0 + r_) * Dm + (k0) + c_ * 8);       \
        }                                                                     \
    } while (0)

    const int lane = tid & 31, w = tid >> 5;
    const int wm = w & 3, wn = w >> 2;
    const int lj = lane >> 3, lm = lane & 7;
    const int arow = wm * 32 + (lj & 1) * 8 + lm;
    const int acho = lj >> 1;
    const int brow = wn * 64 + ((lj & 2) ? 8 : 0) + lm;
    const int bcho = lj & 1;

    float acc[2][8][4];
#pragma unroll
    for (int i = 0; i < 2; i++)
#pragma unroll
        for (int jn = 0; jn < 8; jn++)
#pragma unroll
            for (int r = 0; r < 4; r++) acc[i][jn][r] = 0.f;

    LOAD_STAGE3(0, 0);
    asm volatile("cp.async.commit_group;" ::: "memory");

    for (int it = 0; it < 32; ++it) {
        const int nxt = it + 1;
        if (nxt < 32) LOAD_STAGE3(nxt & 1, nxt * 32);
        asm volatile("cp.async.commit_group;" ::: "memory");
        asm volatile("cp.async.wait_group 1;" ::: "memory");
        __syncthreads();

        const uint32_t buf = smb + (it & 1) * STG_B;
#pragma unroll
        for (int ks = 0; ks < 2; ++ks) {
            uint32_t ah[2][4], al[2][4];
#pragma unroll
            for (int i = 0; i < 2; ++i) {
                uint32_t ra = buf + (arow + i * 16) * TROW + (ks * 2 + acho) * 16;
                LDSM4(ah[i][0], ah[i][1], ah[i][2], ah[i][3], ra);
                LDSM4(al[i][0], al[i][1], al[i][2], al[i][3], ra + TILE_B);
            }
#pragma unroll
            for (int g = 0; g < 4; ++g) {
                uint32_t bh[4], bl[4];
                uint32_t rb = buf + 2 * TILE_B + (brow + g * 16) * TROW + (ks * 2 + bcho) * 16;
                LDSM4(bh[0], bh[1], bh[2], bh[3], rb);
                LDSM4(bl[0], bl[1], bl[2], bl[3], rb + TILE_B);
#pragma unroll
                for (int i = 0; i < 2; ++i)
#pragma unroll
                    for (int hf = 0; hf < 2; ++hf) {
                        const int jn = g * 2 + hf;
                        MMA16816(acc[i][jn], ah[i][0], ah[i][1], ah[i][2], ah[i][3],
                                 bh[hf * 2], bh[hf * 2 + 1]);
                        MMA16816(acc[i][jn], ah[i][0], ah[i][1], ah[i][2], ah[i][3],
                                 bl[hf * 2], bl[hf * 2 + 1]);
                        MMA16816(acc[i][jn], al[i][0], al[i][1], al[i][2], al[i][3],
                                 bh[hf * 2], bh[hf * 2 + 1]);
                    }
            }
        }
        __syncthreads();
    }

#pragma unroll
    for (int i = 0; i < 2; ++i) {
        const int r0 = m0 + wm * 32 + i * 16 + (lane >> 2);
#pragma unroll
        for (int jn = 0; jn < 8; ++jn) {
            const int cc = n0 + wn * 64 + jn * 8 + 2 * (lane & 3);
            *(float2*)&C[(size_t)r0 * Dm + cc]       = make_float2(acc[i][jn][0], acc[i][jn][1]);
            *(float2*)&C[(size_t)(r0 + 8) * Dm + cc] = make_float2(acc[i][jn][2], acc[i][jn][3]);
        }
    }
#undef LOAD_STAGE3
}

// ---------------- K1b: 2-pass fp16 GEMM (v / out), 2 stages, 2 CTAs/SM ----------------
#define STG2_B (3 * TILE_B)          // 30720
#define G2SMEM (2 * STG2_B)          // 61440

__global__ void __launch_bounds__(256, 2) gemm2p_kernel(float* __restrict__ Cout, int mode) {
    extern __shared__ char sm[];
    const uint32_t smb = smem_u32(sm);
    const int tid = threadIdx.x;
    const int m0 = blockIdx.y * 128, n0 = blockIdx.x * 128;

    const __half *Ahi, *Alo, *B;
    float* C;
    if (mode == 0) {
        Ahi = g_xh16; Alo = g_xl16;
        B = g_wt16;                       // Wv^T
        C = g_qkv + 2 * QKV_OFF;
    } else {
        Ahi = g_yh16; Alo = g_yl16;
        B = g_wt16 + (size_t)Dm * Dm;     // Wo^T
        C = Cout;
    }

#define LOAD_STAGE2(buf, k0)                                                  \
    do {                                                                      \
        uint32_t sb_ = smb + (buf) * STG2_B;                                  \
        _Pragma("unroll")                                                     \
        for (int j_ = 0; j_ < 6; ++j_) {                                      \
            int lin_ = tid + 256 * j_;                                        \
            int tile_ = lin_ >> 9;                                            \
            int idx_ = lin_ & 511;                                            \
            int r_ = idx_ >> 2, c_ = idx_ & 3;                                \
            const __half* gp_ = (tile_ == 0) ? Ahi : (tile_ == 1) ? Alo : B;  \
            int gr_ = (tile_ < 2) ? (m0 + r_) : (n0 + r_);                    \
            CP_ASYNC16(sb_ + tile_ * TILE_B + r_ * TROW + c_ * 16,            \
                       gp_ + (size_t)gr_ * Dm + (k0) + c_ * 8);               \
        }                                                                     \
    } while (0)

    const int lane = tid & 31, w = tid >> 5;
    const int wm = w & 3, wn = w >> 2;
    const int lj = lane >> 3, lm = lane & 7;
    const int arow = wm * 32 + (lj & 1) * 8 + lm;
    const int acho = lj >> 1;
    const int brow = wn * 64 + ((lj & 2) ? 8 : 0) + lm;
    const int bcho = lj & 1;

    float acc[2][8][4];
#pragma unroll
    for (int i = 0; i < 2; i++)
#pragma unroll
        for (int jn = 0; jn < 8; jn++)
#pragma unroll
            for (int r = 0; r < 4; r++) acc[i][jn][r] = 0.f;

    LOAD_STAGE2(0, 0);
    asm volatile("cp.async.commit_group;" ::: "memory");

    for (int it = 0; it < 32; ++it) {
        const int nxt = it + 1;
        if (nxt < 32) LOAD_STAGE2(nxt & 1, nxt * 32);
        asm volatile("cp.async.commit_group;" ::: "memory");
        asm volatile("cp.async.wait_group 1;" ::: "memory");
        __syncthreads();

        const uint32_t buf = smb + (it & 1) * STG2_B;
#pragma unroll
        for (int ks = 0; ks < 2; ++ks) {
            uint32_t ah[2][4], al[2][4];
#pragma unroll
            for (int i = 0; i < 2; ++i) {
                uint32_t ra = buf + (arow + i * 16) * TROW + (ks * 2 + acho) * 16;
                LDSM4(ah[i][0], ah[i][1], ah[i][2], ah[i][3], ra);
                LDSM4(al[i][0], al[i][1], al[i][2], al[i][3], ra + TILE_B);
            }
#pragma unroll
            for (int g = 0; g < 4; ++g) {
                uint32_t bf[4];
                uint32_t rb = buf + 2 * TILE_B + (brow + g * 16) * TROW + (ks * 2 + bcho) * 16;
                LDSM4(bf[0], bf[1], bf[2], bf[3], rb);
#pragma unroll
                for (int i = 0; i < 2; ++i)
#pragma unroll
                    for (int hf = 0; hf < 2; ++hf) {
                        const int jn = g * 2 + hf;
                        MMA16816H(acc[i][jn], ah[i][0], ah[i][1], ah[i][2], ah[i][3],
                                  bf[hf * 2], bf[hf * 2 + 1]);
                        MMA16816H(acc[i][jn], al[i][0], al[i][1], al[i][2], al[i][3],
                                  bf[hf * 2], bf[hf * 2 + 1]);
                    }
            }
        }
        __syncthreads();
    }

#pragma unroll
    for (int i = 0; i < 2; ++i) {
        const int r0 = m0 + wm * 32 + i * 16 + (lane >> 2);
#pragma unroll
        for (int jn = 0; jn < 8; ++jn) {
            const int cc = n0 + wn * 64 + jn * 8 + 2 * (lane & 3);
            *(float2*)&C[(size_t)r0 * Dm + cc]       = make_float2(acc[i][jn][0], acc[i][jn][1]);
            *(float2*)&C[(size_t)(r0 + 8) * Dm + cc] = make_float2(acc[i][jn][2], acc[i][jn][3]);
        }
    }
#undef LOAD_STAGE2
}

// ---------------- K2: FAVOR+ features via HMMA + exp epilogue ----------------
#define FA_P 144
#define FW_P 272
#define FA_H 0
#define FA_L (FA_H + 128 * FA_P)
#define FW_H (FA_L + 128 * FA_P)
#define FW_L (FW_H + 64 * FW_P)
#define FSQ  (FW_L + 64 * FW_P)
#define FSM  (FSQ + 512)

__global__ void __launch_bounds__(256) feat_kernel(const float* __restrict__ Wf) {
    extern __shared__ char sm[];
    const uint32_t smb = smem_u32(sm);
    const int tid = threadIdx.x;
    const int bt0 = blockIdx.x * 128, h = blockIdx.y, sel = blockIdx.z;
    const float* src = g_qkv + (size_t)sel * QKV_OFF;

#pragma unroll
    for (int j = 0; j < 8; ++j) {
        int lin = tid + 256 * j;
        int rr = lin >> 4, cc = lin & 15;
        float4 v = *(const float4*)(src + (size_t)(bt0 + rr) * Dm + h * HDm + cc * 4);
        uint32_t h01, l01, h23, l23;
        split2(v.x, v.y, h01, l01);
        split2(v.z, v.w, h23, l23);
        *(uint2*)(sm + FA_H + rr * FA_P + cc * 8) = make_uint2(h01, h23);
        *(uint2*)(sm + FA_L + rr * FA_P + cc * 8) = make_uint2(l01, l23);
    }
#pragma unroll
    for (int j = 0; j < 8; ++j) {
        int lin = tid + 256 * j;
        int rr = lin >> 5, cc = lin & 31;
        float4 v = *(const float4*)(Wf + (size_t)rr * NFm + cc * 4);
        uint32_t h01, l01, h23, l23;
        split2(v.x, v.y, h01, l01);
        split2(v.z, v.w, h23, l23);
        *(uint2*)(sm + FW_H + rr * FW_P + cc * 8) = make_uint2(h01, h23);
        *(uint2*)(sm + FW_L + rr * FW_P + cc * 8) = make_uint2(l01, l23);
    }
    __syncthreads();

    if (tid < 128) {
        float s = 0.f;
#pragma unroll
        for (int d2 = 0; d2 < 32; ++d2) {
            __nv_bfloat162 vh = *(__nv_bfloat162*)(sm + FA_H + tid * FA_P + d2 * 4);
            __nv_bfloat162 vl = *(__nv_bfloat162*)(sm + FA_L + tid * FA_P + d2 * 4);
            float2 fh = __bfloat1622float2(vh), fl = __bfloat1622float2(vl);
            float a = fh.x + fl.x, b = fh.y + fl.y;
            s = fmaf(a, a, fmaf(b, b, s));
        }
        ((float*)(sm + FSQ))[tid] = 0.5f * s;
    }
    __syncthreads();

    const int l = tid & 31, w = tid >> 5;
    const int lj = l >> 3, lm = l & 7;
    const int arow = w * 16 + (lj & 1) * 8 + lm;
    const int acho = lj >> 1;
    const int m = l >> 3, r = l & 7;
    const int sB = (m & 1) ? 8 : 0, eB = (m & 2) ? 8 : 0;

    float acc[16][4];
#pragma unroll
    for (int nb = 0; nb < 16; ++nb)
#pragma unroll
        for (int q = 0; q < 4; ++q) acc[nb][q] = 0.f;

#pragma unroll
    for (int ks = 0; ks < 4; ++ks) {
        uint32_t ah[4], al[4];
        uint32_t ad = smb + FA_H + arow * FA_P + (ks * 2 + acho) * 16;
        LDSM4(ah[0], ah[1], ah[2], ah[3], ad);
        LDSM4(al[0], al[1], al[2], al[3], ad + (FA_L - FA_H));
#pragma unroll
        for (int fg = 0; fg < 8; ++fg) {
            uint32_t bhf[4], blf[4];
            uint32_t bd = smb + FW_H + (ks * 16 + sB + r) * FW_P + (fg * 16 + eB) * 2;
            LDSM4T(bhf[0], bhf[1], bhf[2], bhf[3], bd);
            LDSM4T(blf[0], blf[1], blf[2], blf[3], bd + (FW_L - FW_H));
#pragma unroll
            for (int hf = 0; hf < 2; ++hf) {
                const int nb = fg * 2 + hf;
                MMA16816(acc[nb], ah[0], ah[1], ah[2], ah[3], bhf[hf * 2], bhf[hf * 2 + 1]);
                MMA16816(acc[nb], ah[0], ah[1], ah[2], ah[3], blf[hf * 2], blf[hf * 2 + 1]);
                MMA16816(acc[nb], al[0], al[1], al[2], al[3], bhf[hf * 2], bhf[hf * 2 + 1]);
            }
        }
    }

    float* dst = sel ? g_kp : g_qp;
    const int b = bt0 >> 11;
    const int bh = b * Hh + h;
    const int trow0 = w * 16 + (l >> 2);
    const float* sqp = (const float*)(sm + FSQ);
    const float sq0 = sqp[trow0], sq1 = sqp[trow0 + 8];
    const int t0 = (bt0 & 2047) + trow0;
    float* d0 = dst + ((size_t)bh * Tt + t0) * NFm;
    float* d1 = dst + ((size_t)bh * Tt + t0 + 8) * NFm;
#pragma unroll
    for (int nb = 0; nb < 16; ++nb) {
        const int f = nb * 8 + (l & 3) * 2;
        *(float2*)(d0 + f) = make_float2(expf(acc[nb][0] - sq0) * INV_SQRT_NF,
                                         expf(acc[nb][1] - sq0) * INV_SQRT_NF);
        *(float2*)(d1 + f) = make_float2(expf(acc[nb][2] - sq1) * INV_SQRT_NF,
                                         expf(acc[nb][3] - sq1) * INV_SQRT_NF);
    }
}

// ---------------- K3: chunk_sum via HMMA ----------------
#define PKb 272
#define PVb 144
#define CS_KH 0
#define CS_KL (CS_KH + 128 * PKb)
#define CS_VH (CS_KL + 128 * PKb)
#define CS_VL (CS_VH + 128 * PVb)
#define SMEM3 (CS_VL + 128 * PVb)

__global__ void __launch_bounds__(256, 1) chunk_sum_kernel() {
    extern __shared__ char sm[];
    const uint32_t smb = smem_u32(sm);
    const int c = blockIdx.x, bh = blockIdx.y;
    const int b = bh >> 4, h = bh & 15;
    const int tid = threadIdx.x;
    const float* GV = g_qkv + 2 * QKV_OFF;
    const size_t kbase = ((size_t)bh * Tt + c * CHK) * NFm;
    const size_t vbase = ((size_t)(b * Tt + c * CHK)) * Dm + h * HDm;

#pragma unroll
    for (int j = 0; j < 16; ++j) {
        int lin = tid + 256 * j;
        int rr = lin >> 5, cc = lin & 31;
        float4 v = *(const float4*)(g_kp + kbase + (size_t)rr * NFm + cc * 4);
        uint32_t h01, l01, h23, l23;
        split2(v.x, v.y, h01, l01);
        split2(v.z, v.w, h23, l23);
        *(uint2*)(sm + CS_KH + rr * PKb + cc * 8) = make_uint2(h01, h23);
        *(uint2*)(sm + CS_KL + rr * PKb + cc * 8) = make_uint2(l01, l23);
    }
#pragma unroll
    for (int j = 0; j < 8; ++j) {
        int lin = tid + 256 * j;
        int rr = lin >> 4, cc = lin & 15;
        float4 v = *(const float4*)(GV + vbase + (size_t)rr * Dm + cc * 4);
        uint32_t h01, l01, h23, l23;
        split2(v.x, v.y, h01, l01);
        split2(v.z, v.w, h23, l23);
        *(uint2*)(sm + CS_VH + rr * PVb + cc * 8) = make_uint2(h01, h23);
        *(uint2*)(sm + CS_VL + rr * PVb + cc * 8) = make_uint2(l01, l23);
    }
    __syncthreads();

    const int l = tid & 31, w = tid >> 5;
    const int m = l >> 3, r = l & 7;
    const int f0w = (w & 3) * 32, e0w = (w >> 2) * 32;
    const int sA = (m & 2) ? 8 : 0, fA = (m & 1) ? 8 : 0;
    const int sB = (m & 1) ? 8 : 0, eB = (m & 2) ? 8 : 0;

    float acc[2][4][4];
#pragma unroll
    for (int i = 0; i < 2; i++)
#pragma unroll
        for (int jn = 0; jn < 4; jn++)
#pragma unroll
            for (int q = 0; q < 4; q++) acc[i][jn][q] = 0.f;

    for (int s0 = 0; s0 < 128; s0 += 16) {
        uint32_t ah[2][4], al[2][4], bhf[2][4], blf[2][4];
#pragma unroll
        for (int i = 0; i < 2; ++i) {
            uint32_t ad = smb + CS_KH + (s0 + sA + r) * PKb + (f0w + i * 16 + fA) * 2;
            LDSM4T(ah[i][0], ah[i][1], ah[i][2], ah[i][3], ad);
            LDSM4T(al[i][0], al[i][1], al[i][2], al[i][3], ad + (CS_KL - CS_KH));
        }
#pragma unroll
        for (int j2 = 0; j2 < 2; ++j2) {
            uint32_t ad = smb + CS_VH + (s0 + sB + r) * PVb + (e0w + j2 * 16 + eB) * 2;
            LDSM4T(bhf[j2][0], bhf[j2][1], bhf[j2][2], bhf[j2][3], ad);
            LDSM4T(blf[j2][0], blf[j2][1], blf[j2][2], blf[j2][3], ad + (CS_VL - CS_VH));
        }
#pragma unroll
        for (int i = 0; i < 2; ++i)
#pragma unroll
            for (int jn = 0; jn < 4; ++jn) {
                const int j2 = jn >> 1, o = (jn & 1) * 2;
                MMA16816(acc[i][jn], ah[i][0], ah[i][1], ah[i][2], ah[i][3],
                         bhf[j2][o], bhf[j2][o + 1]);
                MMA16816(acc[i][jn], ah[i][0], ah[i][1], ah[i][2], ah[i][3],
                         blf[j2][o], blf[j2][o + 1]);
                MMA16816(acc[i][jn], al[i][0], al[i][1], al[i][2], al[i][3],
                         bhf[j2][o], bhf[j2][o + 1]);
            }
    }

    const size_t Sbase = ((size_t)bh * NCH + c) * (NFm * HDm);
#pragma unroll
    for (int i = 0; i < 2; ++i) {
        const int fr = f0w + i * 16 + (l >> 2);
#pragma unroll
        for (int jn = 0; jn < 4; ++jn) {
            const int ec = e0w + jn * 8 + (l & 3) * 2;
            *(float2*)(g_S + Sbase + (size_t)fr * HDm + ec) =
                make_float2(acc[i][jn][0], acc[i][jn][1]);
            *(float2*)(g_S + Sbase + (size_t)(fr + 8) * HDm + ec) =
                make_float2(acc[i][jn][2], acc[i][jn][3]);
        }
    }
    if (tid < 128) {
        float zz = 0.f;
        for (int s = 0; s < 128; ++s) zz += g_kp[kbase + (size_t)s * NFm + tid];
        g_z[((size_t)bh * NCH + c) * NFm + tid] = zz;
    }
}

// ---------------- K4: exclusive prefix over chunks ----------------
__global__ void __launch_bounds__(256) prefix_kernel() {   // grid (32, BH)
    const int bh = blockIdx.y, seg = blockIdx.x;
    const int idx = seg * 256 + threadIdx.x;
    float v[NCH];
    const size_t base = (size_t)bh * NCH * NFm * HDm + idx;
#pragma unroll
    for (int c = 0; c < NCH; ++c) v[c] = g_S[base + (size_t)c * NFm * HDm];
    float acc = 0.f;
#pragma unroll
    for (int c = 0; c < NCH; ++c) { float cur = v[c]; v[c] = acc; acc += cur; }
#pragma unroll
    for (int c = 0; c < NCH; ++c) g_S[base + (size_t)c * NFm * HDm] = v[c];
    if (seg == 0 && threadIdx.x < NFm) {
        float zv[NCH];
        const size_t zb = (size_t)bh * NCH * NFm + threadIdx.x;
#pragma unroll
        for (int c = 0; c < NCH; ++c) zv[c] = g_z[zb + c * NFm];
        float az = 0.f;
#pragma unroll
        for (int c = 0; c < NCH; ++c) { float cur = zv[c]; zv[c] = az; az += cur; }
#pragma unroll
        for (int c = 0; c < NCH; ++c) g_z[zb + c * NFm] = zv[c];
    }
}

// ---------------- K5: chunk_out via HMMA (writes y as fp16 hi/lo) ----------------
#define CO_QH 0
#define CO_QL (CO_QH + 128 * PKb)
#define CO_KH (CO_QL + 128 * PKb)
#define CO_KL (CO_KH + 128 * PKb)
#define CO_VH (CO_KL + 128 * PKb)
#define CO_VL (CO_VH + 128 * PVb)
#define CO_SH (CO_VL + 128 * PVb)
#define CO_SL (CO_SH + 128 * PVb)
#define CO_Z  (CO_SL + 128 * PVb)
#define CO_D  (CO_Z + 512)
#define SMEM5 (CO_D + 512)

__global__ void __launch_bounds__(256, 1) chunk_out_kernel() {
    extern __shared__ char sm[];
    const uint32_t smb = smem_u32(sm);
    const int c = blockIdx.x, bh = blockIdx.y;
    const int b = bh >> 4, h = bh & 15;
    const int tid = threadIdx.x;
    const float* GV = g_qkv + 2 * QKV_OFF;
    const size_t qbase = ((size_t)bh * Tt + c * CHK) * NFm;
    const size_t vbase = ((size_t)(b * Tt + c * CHK)) * Dm + h * HDm;
    const size_t Sbase = ((size_t)bh * NCH + c) * (NFm * HDm);

#pragma unroll
    for (int j = 0; j < 16; ++j) {
        int lin = tid + 256 * j;
        int rr = lin >> 5, cc = lin & 31;
        float4 q4 = *(const float4*)(g_qp + qbase + (size_t)rr * NFm + cc * 4);
        float4 k4 = *(const float4*)(g_kp + qbase + (size_t)rr * NFm + cc * 4);
        uint32_t h01, l01, h23, l23;
        split2(q4.x, q4.y, h01, l01);
        split2(q4.z, q4.w, h23, l23);
        *(uint2*)(sm + CO_QH + rr * PKb + cc * 8) = make_uint2(h01, h23);
        *(uint2*)(sm + CO_QL + rr * PKb + cc * 8) = make_uint2(l01, l23);
        split2(k4.x, k4.y, h01, l01);
        split2(k4.z, k4.w, h23, l23);
        *(uint2*)(sm + CO_KH + rr * PKb + cc * 8) = make_uint2(h01, h23);
        *(uint2*)(sm + CO_KL + rr * PKb + cc * 8) = make_uint2(l01, l23);
    }
#pragma unroll
    for (int j = 0; j < 8; ++j) {
        int lin = tid + 256 * j;
        int rr = lin >> 4, cc = lin & 15;
        float4 v4 = *(const float4*)(GV + vbase + (size_t)rr * Dm + cc * 4);
        uint32_t h01, l01, h23, l23;
        split2(v4.x, v4.y, h01, l01);
        split2(v4.z, v4.w, h23, l23);
        *(uint2*)(sm + CO_VH + rr * PVb + cc * 8) = make_uint2(h01, h23);
        *(uint2*)(sm + CO_VL + rr * PVb + cc * 8) = make_uint2(l01, l23);
        float4 s4 = *(const float4*)(g_S + Sbase + (size_t)rr * HDm + cc * 4);
        split2(s4.x, s4.y, h01, l01);
        split2(s4.z, s4.w, h23, l23);
        *(uint2*)(sm + CO_SH + rr * PVb + cc * 8) = make_uint2(h01, h23);
        *(uint2*)(sm + CO_SL + rr * PVb + cc * 8) = make_uint2(l01, l23);
    }
    if (tid < 128)
        ((float*)(sm + CO_Z))[tid] = g_z[((size_t)bh * NCH + c) * NFm + tid];
    __syncthreads();

    const int l = tid & 31, w = tid >> 5;
    const int wm = w & 3, wn = w >> 2;
    const int lj = l >> 3, lm = l & 7;
    const int m = l >> 3, r = l & 7;
    const int arow = wm * 32 + (lj & 1) * 8 + lm;
    const int acho = lj >> 1;
    const int brow = ((lj & 2) ? 8 : 0) + lm;
    const int bcho = lj & 1;
    const int sB = (m & 1) ? 8 : 0, eB = (m & 2) ? 8 : 0;

    float accA[2][8][4];
#pragma unroll
    for (int i = 0; i < 2; i++)
#pragma unroll
        for (int jn = 0; jn < 8; jn++)
#pragma unroll
            for (int q = 0; q < 4; q++) accA[i][jn][q] = 0.f;

    for (int f0 = 0; f0 < 128; f0 += 16) {
        uint32_t qh[2][4], ql[2][4];
#pragma unroll
        for (int i = 0; i < 2; ++i) {
            uint32_t ad = smb + CO_QH + (arow + i * 16) * PKb + (f0 / 8 + acho) * 16;
            LDSM4(qh[i][0], qh[i][1], qh[i][2], qh[i][3], ad);
            LDSM4(ql[i][0], ql[i][1], ql[i][2], ql[i][3], ad + (CO_QL - CO_QH));
        }
#pragma unroll
        for (int g = 0; g < 4; ++g) {
            uint32_t kh[4], kl[4];
            uint32_t ad = smb + CO_KH + (wn * 64 + brow + g * 16) * PKb + (f0 / 8 + bcho) * 16;
            LDSM4(kh[0], kh[1], kh[2], kh[3], ad);
            LDSM4(kl[0], kl[1], kl[2], kl[3], ad + (CO_KL - CO_KH));
#pragma unroll
            for (int i = 0; i < 2; ++i)
#pragma unroll
                for (int hf = 0; hf < 2; ++hf) {
                    const int jn = g * 2 + hf;
                    MMA16816(accA[i][jn], qh[i][0], qh[i][1], qh[i][2], qh[i][3],
                             kh[hf * 2], kh[hf * 2 + 1]);
                    MMA16816(accA[i][jn], qh[i][0], qh[i][1], qh[i][2], qh[i][3],
                             kl[hf * 2], kl[hf * 2 + 1]);
                    MMA16816(accA[i][jn], ql[i][0], ql[i][1], ql[i][2], ql[i][3],
                             kh[hf * 2], kh[hf * 2 + 1]);
                }
        }
    }
    __syncthreads();

#pragma unroll
    for (int i = 0; i < 2; ++i) {
        const int tr = wm * 32 + i * 16 + (l >> 2);
#pragma unroll
        for (int jn = 0; jn < 8; ++jn) {
            const int sc = wn * 64 + jn * 8 + (l & 3) * 2;
            float v0 = (sc     <= tr) ? accA[i][jn][0] : 0.f;
            float v1 = (sc + 1 <= tr) ? accA[i][jn][1] : 0.f;
            uint32_t hi, lo;
            split2(v0, v1, hi, lo);
            *(uint32_t*)(sm + CO_KH + tr * PKb + sc * 2) = hi;
            *(uint32_t*)(sm + CO_KL + tr * PKb + sc * 2) = lo;
            const int tr8 = tr + 8;
            v0 = (sc     <= tr8) ? accA[i][jn][2] : 0.f;
            v1 = (sc + 1 <= tr8) ? accA[i][jn][3] : 0.f;
            split2(v0, v1, hi, lo);
            *(uint32_t*)(sm + CO_KH + tr8 * PKb + sc * 2) = hi;
            *(uint32_t*)(sm + CO_KL + tr8 * PKb + sc * 2) = lo;
        }
    }
    __syncthreads();

    if (tid < 128) {
        const int t = tid;
        float den = EPSf;
        const float* zp = (const float*)(sm + CO_Z);
#pragma unroll 8
        for (int f2 = 0; f2 < 64; ++f2) {
            __nv_bfloat162 qh2 = *(__nv_bfloat162*)(sm + CO_QH + t * PKb + f2 * 4);
            __nv_bfloat162 ql2 = *(__nv_bfloat162*)(sm + CO_QL + t * PKb + f2 * 4);
            float2 fh = __bfloat1622float2(qh2), fl = __bfloat1622float2(ql2);
            den += (fh.x + fl.x) * zp[2 * f2] + (fh.y + fl.y) * zp[2 * f2 + 1];
        }
#pragma unroll 8
        for (int s2 = 0; s2 < 64; ++s2) {
            __nv_bfloat162 ah2 = *(__nv_bfloat162*)(sm + CO_KH + t * PKb + s2 * 4);
            __nv_bfloat162 al2 = *(__nv_bfloat162*)(sm + CO_KL + t * PKb + s2 * 4);
            float2 fa = __bfloat1622float2(ah2), fb = __bfloat1622float2(al2);
            den += fa.x + fa.y + fb.x + fb.y;
        }
        ((float*)(sm + CO_D))[t] = 1.f / den;
    }
    __syncthreads();

    const int e0w = wn * 32;
    float accY[2][4][4];
#pragma unroll
    for (int i = 0; i < 2; i++)
#pragma unroll
        for (int jn = 0; jn < 4; jn++)
#pragma unroll
            for (int q = 0; q < 4; q++) accY[i][jn][q] = 0.f;

    for (int s0 = 0; s0 < 128; s0 += 16) {
        uint32_t aah[2][4], aal[2][4], vh[2][4], vl[2][4];
#pragma unroll
        for (int i = 0; i < 2; ++i) {
            uint32_t ad = smb + CO_KH + (arow + i * 16) * PKb + (s0 / 8 + acho) * 16;
            LDSM4(aah[i][0], aah[i][1], aah[i][2], aah[i][3], ad);
            LDSM4(aal[i][0], aal[i][1], aal[i][2], aal[i][3], ad + (CO_KL - CO_KH));
        }
#pragma unroll
        for (int j2 = 0; j2 < 2; ++j2) {
            uint32_t ad = smb + CO_VH + (s0 + sB + r) * PVb + (e0w + j2 * 16 + eB) * 2;
            LDSM4T(vh[j2][0], vh[j2][1], vh[j2][2], vh[j2][3], ad);
            LDSM4T(vl[j2][0], vl[j2][1], vl[j2][2], vl[j2][3], ad + (CO_VL - CO_VH));
        }
#pragma unroll
        for (int i = 0; i < 2; ++i)
#pragma unroll
            for (int jn = 0; jn < 4; ++jn) {
                const int j2 = jn >> 1, o = (jn & 1) * 2;
                MMA16816(accY[i][jn], aah[i][0], aah[i][1], aah[i][2], aah[i][3],
                         vh[j2][o], vh[j2][o + 1]);
                MMA16816(accY[i][jn], aah[i][0], aah[i][1], aah[i][2], aah[i][3],
                         vl[j2][o], vl[j2][o + 1]);
                MMA16816(accY[i][jn], aal[i][0], aal[i][1], aal[i][2], aal[i][3],
                         vh[j2][o], vh[j2][o + 1]);
            }
    }
    for (int f0 = 0; f0 < 128; f0 += 16) {
        uint32_t qh[2][4], ql[2][4], sh[2][4], sl[2][4];
#pragma unroll
        for (int i = 0; i < 2; ++i) {
            uint32_t ad = smb + CO_QH + (arow + i * 16) * PKb + (f0 / 8 + acho) * 16;
            LDSM4(qh[i][0], qh[i][1], qh[i][2], qh[i][3], ad);
            LDSM4(ql[i][0], ql[i][1], ql[i][2], ql[i][3], ad + (CO_QL - CO_QH));
        }
#pragma unroll
        for (int j2 = 0; j2 < 2; ++j2) {
            uint32_t ad = smb + CO_SH + (f0 + sB + r) * PVb + (e0w + j2 * 16 + eB) * 2;
            LDSM4T(sh[j2][0], sh[j2][1], sh[j2][2], sh[j2][3], ad);
            LDSM4T(sl[j2][0], sl[j2][1], sl[j2][2], sl[j2][3], ad + (CO_SL - CO_SH));
        }
#pragma unroll
        for (int i = 0; i < 2; ++i)
#pragma unroll
            for (int jn = 0; jn < 4; ++jn) {
                const int j2 = jn >> 1, o = (jn & 1) * 2;
                MMA16816(accY[i][jn], qh[i][0], qh[i][1], qh[i][2], qh[i][3],
                         sh[j2][o], sh[j2][o + 1]);
                MMA16816(accY[i][jn], qh[i][0], qh[i][1], qh[i][2], qh[i][3],
                         sl[j2][o], sl[j2][o + 1]);
                MMA16816(accY[i][jn], ql[i][0], ql[i][1], ql[i][2], ql[i][3],
                         sh[j2][o], sh[j2][o + 1]);
            }
    }

    const float* dv = (const float*)(sm + CO_D);
#pragma unroll
    for (int i = 0; i < 2; ++i) {
        const int tr = wm * 32 + i * 16 + (l >> 2);
        const float d0 = dv[tr], d1 = dv[tr + 8];
#pragma unroll
        for (int jn = 0; jn < 4; ++jn) {
            const int ec = e0w + jn * 8 + (l & 3) * 2;
            size_t o0 = ((size_t)(b * Tt + c * CHK + tr)) * Dm + h * HDm + ec;
            size_t o1 = ((size_t)(b * Tt + c * CHK + tr + 8)) * Dm + h * HDm + ec;
            uint32_t hi, lo;
            split2h(accY[i][jn][0] * d0, accY[i][jn][1] * d0, hi, lo);
            *(uint32_t*)(g_yh16 + o0) = hi;
            *(uint32_t*)(g_yl16 + o0) = lo;
            split2h(accY[i][jn][2] * d1, accY[i][jn][3] * d1, hi, lo);
            *(uint32_t*)(g_yh16 + o1) = hi;
            *(uint32_t*)(g_yl16 + o1) = lo;
        }
    }
}

// ---------------------------------------------------------------------------
extern "C" void kernel_launch(void* const* d_in, const int* in_sizes, int n_in,
                              void* d_out, int out_size) {
    const float* x  = (const float*)d_in[0];
    const float* Wq = (const float*)d_in[1];
    const float* Wk = (const float*)d_in[2];
    const float* Wv = (const float*)d_in[3];
    const float* Wo = (const float*)d_in[4];
    const float* Wf = (const float*)d_in[5];
    float* out = (float*)d_out;

    cudaFuncSetAttribute(gemm3p_kernel,    cudaFuncAttributeMaxDynamicSharedMemorySize, GSMEM);
    cudaFuncSetAttribute(gemm2p_kernel,    cudaFuncAttributeMaxDynamicSharedMemorySize, G2SMEM);
    cudaFuncSetAttribute(feat_kernel,      cudaFuncAttributeMaxDynamicSharedMemorySize, FSM);
    cudaFuncSetAttribute(chunk_sum_kernel, cudaFuncAttributeMaxDynamicSharedMemorySize, SMEM3);
    cudaFuncSetAttribute(chunk_out_kernel, cudaFuncAttributeMaxDynamicSharedMemorySize, SMEM5);

    split_kernel<<<(MR * Dm / 4) / 256, 256>>>(x);
    wsplit_kernel<<<dim3(32, 32, 4), 256>>>(Wq, Wk, Wv, Wo);
    gemm3p_kernel<<<dim3(8, 64, 2), 256, GSMEM>>>();            // q, k
    gemm2p_kernel<<<dim3(8, 64), 256, G2SMEM>>>(nullptr, 0);    // v
    feat_kernel<<<dim3(MR / 128, Hh, 2), 256, FSM>>>(Wf);
    chunk_sum_kernel<<<dim3(NCH, BH), 256, SMEM3>>>();
    prefix_kernel<<<dim3(32, BH), 256>>>();
    chunk_out_kernel<<<dim3(NCH, BH), 256, SMEM5>>>();
    gemm2p_kernel<<<dim3(8, 64), 256, G2SMEM>>>(out, 1);        // out
}

// round 9
// speedup vs baseline: 3.5377x; 1.0301x over previous
#include <cuda_runtime.h>
#include <cuda_bf16.h>
#include <cuda_fp16.h>
#include <math.h>
#include <stdint.h>

// ---------------- problem constants ----------------
#define Bb   4
#define Tt   2048
#define Dm   1024
#define Hh   16
#define HDm  64
#define NFm  128
#define CHK  128
#define NCH  16
#define BH   64
#define MR   8192
#define EPSf 1e-6f
#define INV_SQRT_NF 0.08838834764831845f

#define QKV_OFF ((size_t)MR * Dm)

// ---------------- scratch ----------------
__device__ float g_qkv[3 * (size_t)MR * Dm];   // q | k | v
__device__ float g_qp [(size_t)BH * Tt * NFm];
__device__ float g_kp [(size_t)BH * Tt * NFm];
__device__ float g_S  [(size_t)BH * NCH * NFm * HDm];
__device__ float g_z  [(size_t)BH * NCH * NFm];

__device__ __nv_bfloat16 g_xhi[(size_t)MR * Dm], g_xlo[(size_t)MR * Dm];     // x bf16 split (q,k)
__device__ __half        g_xh16[(size_t)MR * Dm], g_xl16[(size_t)MR * Dm];   // x fp16 split (v)
__device__ __half        g_yh16[(size_t)MR * Dm], g_yl16[(size_t)MR * Dm];   // y fp16 split (out)
__device__ __nv_bfloat16 g_wth[2 * (size_t)Dm * Dm], g_wtl[2 * (size_t)Dm * Dm]; // Wq,Wk ^T bf16
__device__ __half        g_wt16[2 * (size_t)Dm * Dm];                        // Wv,Wo ^T fp16

// ---------------- helpers ----------------
__device__ __forceinline__ uint32_t smem_u32(const void* p) {
    uint32_t a;
    asm("{ .reg .u64 t; cvta.to.shared.u64 t, %1; cvt.u32.u64 %0, t; }" : "=r"(a) : "l"(p));
    return a;
}

#define LDSM4(r0, r1, r2, r3, addr)                                          \
    asm volatile("ldmatrix.sync.aligned.m8n8.x4.shared.b16 {%0,%1,%2,%3}, [%4];" \
                 : "=r"(r0), "=r"(r1), "=r"(r2), "=r"(r3) : "r"(addr))

#define LDSM4T(r0, r1, r2, r3, addr)                                         \
    asm volatile("ldmatrix.sync.aligned.m8n8.x4.trans.shared.b16 {%0,%1,%2,%3}, [%4];" \
                 : "=r"(r0), "=r"(r1), "=r"(r2), "=r"(r3) : "r"(addr))

#define MMA16816(d, a0, a1, a2, a3, b0, b1)                                  \
    asm volatile("mma.sync.aligned.m16n8k16.row.col.f32.bf16.bf16.f32 "      \
                 "{%0,%1,%2,%3}, {%4,%5,%6,%7}, {%8,%9}, {%0,%1,%2,%3};"     \
                 : "+f"((d)[0]), "+f"((d)[1]), "+f"((d)[2]), "+f"((d)[3])    \
                 : "r"(a0), "r"(a1), "r"(a2), "r"(a3), "r"(b0), "r"(b1))

#define MMA16816H(d, a0, a1, a2, a3, b0, b1)                                 \
    asm volatile("mma.sync.aligned.m16n8k16.row.col.f32.f16.f16.f32 "        \
                 "{%0,%1,%2,%3}, {%4,%5,%6,%7}, {%8,%9}, {%0,%1,%2,%3};"     \
                 : "+f"((d)[0]), "+f"((d)[1]), "+f"((d)[2]), "+f"((d)[3])    \
                 : "r"(a0), "r"(a1), "r"(a2), "r"(a3), "r"(b0), "r"(b1))

#define CP_ASYNC16(sa, g) \
    asm volatile("cp.async.cg.shared.global [%0], [%1], 16;" :: "r"(sa), "l"(g))

__device__ __forceinline__ void split2(float a, float b, uint32_t& hi, uint32_t& lo) {
    __nv_bfloat16 ha = __float2bfloat16(a), hb = __float2bfloat16(b);
    __nv_bfloat16 la = __float2bfloat16(a - __bfloat162float(ha));
    __nv_bfloat16 lb = __float2bfloat16(b - __bfloat162float(hb));
    hi = ((uint32_t)__bfloat16_as_ushort(hb) << 16) | __bfloat16_as_ushort(ha);
    lo = ((uint32_t)__bfloat16_as_ushort(lb) << 16) | __bfloat16_as_ushort(la);
}

__device__ __forceinline__ void split2h(float a, float b, uint32_t& hi, uint32_t& lo) {
    __half ha = __float2half_rn(a), hb = __float2half_rn(b);
    __half la = __float2half_rn(a - __half2float(ha));
    __half lb = __float2half_rn(b - __half2float(hb));
    hi = ((uint32_t)__half_as_ushort(hb) << 16) | __half_as_ushort(ha);
    lo = ((uint32_t)__half_as_ushort(lb) << 16) | __half_as_ushort(la);
}

// ---------------- K0: fp32 x -> bf16 hi/lo + fp16 hi/lo ----------------
__global__ void __launch_bounds__(256) split_kernel(const float* __restrict__ xsrc) {
    const size_t i = (size_t)blockIdx.x * 256 + threadIdx.x;   // float4 index
    const float4 v = ((const float4*)xsrc)[i];
    uint32_t h01, l01, h23, l23;
    split2(v.x, v.y, h01, l01);
    split2(v.z, v.w, h23, l23);
    *(uint2*)(g_xhi + 4 * i) = make_uint2(h01, h23);
    *(uint2*)(g_xlo + 4 * i) = make_uint2(l01, l23);
    split2h(v.x, v.y, h01, l01);
    split2h(v.z, v.w, h23, l23);
    *(uint2*)(g_xh16 + 4 * i) = make_uint2(h01, h23);
    *(uint2*)(g_xl16 + 4 * i) = make_uint2(l01, l23);
}

// ---------------- K0b: W transpose + split ----------------
__global__ void __launch_bounds__(256) wsplit_kernel(const float* __restrict__ Wq,
                                                     const float* __restrict__ Wk,
                                                     const float* __restrict__ Wv,
                                                     const float* __restrict__ Wo) {
    __shared__ float t[32][33];
    const int z = blockIdx.z;
    const float* W = (z == 0) ? Wq : (z == 1) ? Wk : (z == 2) ? Wv : Wo;
    const int tx = threadIdx.x & 31, ty = threadIdx.x >> 5;   // 32 x 8
    const int bx = blockIdx.x, by = blockIdx.y;
#pragma unroll
    for (int j = 0; j < 4; j++) {
        int k = by * 32 + ty + j * 8;
        int n = bx * 32 + tx;
        t[ty + j * 8][tx] = W[(size_t)k * Dm + n];
    }
    __syncthreads();
#pragma unroll
    for (int j = 0; j < 4; j++) {
        int n = bx * 32 + ty + j * 8;
        int k = by * 32 + tx;
        float v = t[tx][ty + j * 8];
        if (z < 2) {
            __nv_bfloat16 hb = __float2bfloat16(v);
            __nv_bfloat16 lb = __float2bfloat16(v - __bfloat162float(hb));
            size_t o = (size_t)z * Dm * Dm + (size_t)n * Dm + k;
            g_wth[o] = hb;
            g_wtl[o] = lb;
        } else {
            g_wt16[(size_t)(z - 2) * Dm * Dm + (size_t)n * Dm + k] = __float2half_rn(v);
        }
    }
}

// ---------------- K1: fused projection GEMM ----------------
// grid (8, 64, 3). z=0,1: q,k via 3-pass bf16. z=2: v via 2-pass fp16.
// 2 stages x 40KB = 80KB smem, 2 CTAs/SM, ONE sync per k-iter (loads after sync overlap compute).
#define TROW   80
#define TILE_B (128 * TROW)
#define STG_B  (4 * TILE_B)          // 40960
#define GSMEM  (2 * STG_B)           // 81920

__global__ void __launch_bounds__(256, 2) proj_kernel() {
    extern __shared__ char sm[];
    const uint32_t smb = smem_u32(sm);
    const int tid = threadIdx.x;
    const int z = blockIdx.z;
    const int m0 = blockIdx.y * 128, n0 = blockIdx.x * 128;
    const bool bf = (z < 2);

    float* C = g_qkv + (size_t)z * QKV_OFF;

    const char *gA0, *gA1, *gB0, *gB1;
    if (bf) {
        gA0 = (const char*)g_xhi;
        gA1 = (const char*)g_xlo;
        gB0 = (const char*)(g_wth + (size_t)z * Dm * Dm);
        gB1 = (const char*)(g_wtl + (size_t)z * Dm * Dm);
    } else {
        gA0 = (const char*)g_xh16;
        gA1 = (const char*)g_xl16;
        gB0 = (const char*)g_wt16;
        gB1 = (const char*)g_wt16;   // unused but valid
    }

    const int lane = tid & 31, w = tid >> 5;
    const int wm = w & 3, wn = w >> 2;
    const int lj = lane >> 3, lm = lane & 7;
    const int arow = wm * 32 + (lj & 1) * 8 + lm;
    const int acho = lj >> 1;
    const int brow = wn * 64 + ((lj & 2) ? 8 : 0) + lm;
    const int bcho = lj & 1;

    float acc[2][8][4];
#pragma unroll
    for (int i = 0; i < 2; i++)
#pragma unroll
        for (int jn = 0; jn < 8; jn++)
#pragma unroll
            for (int r = 0; r < 4; r++) acc[i][jn][r] = 0.f;

#define LOAD_BF(buf, k0)                                                      \
    do {                                                                      \
        const int lq_ = tid >> 6, lu_ = tid & 63;                             \
        const char* gp_ = (lq_ == 0) ? gA0 : (lq_ == 1) ? gA1 :               \
                          (lq_ == 2) ? gB0 : gB1;                             \
        const int gr0_ = (lq_ < 2) ? m0 : n0;                                 \
        uint32_t sb_ = smb + lq_ * TILE_B + (buf) * STG_B;                    \
        _Pragma("unroll")                                                     \
        for (int j_ = 0; j_ < 8; ++j_) {                                      \
            int lin_ = lu_ + 64 * j_;                                         \
            int r_ = lin_ >> 2, c_ = lin_ & 3;                                \
            CP_ASYNC16(sb_ + r_ * TROW + c_ * 16,                             \
                       gp_ + (size_t)(gr0_ + r_) * (Dm * 2) + (k0) * 2 + c_ * 16); \
        }                                                                     \
    } while (0)

#define LOAD_FP(buf, k0)                                                      \
    do {                                                                      \
        uint32_t sb_ = smb + (buf) * STG_B;                                   \
        _Pragma("unroll")                                                     \
        for (int j_ = 0; j_ < 6; ++j_) {                                      \
            int lin_ = tid + 256 * j_;                                        \
            int tile_ = lin_ >> 9;                                            \
            int idx_ = lin_ & 511;                                            \
            int r_ = idx_ >> 2, c_ = idx_ & 3;                                \
            const char* gp_ = (tile_ == 0) ? gA0 : (tile_ == 1) ? gA1 : gB0;  \
            int gr_ = (tile_ < 2) ? (m0 + r_) : (n0 + r_);                    \
            CP_ASYNC16(sb_ + tile_ * TILE_B + r_ * TROW + c_ * 16,            \
                       gp_ + (size_t)gr_ * (Dm * 2) + (k0) * 2 + c_ * 16);    \
        }                                                                     \
    } while (0)

    if (bf) LOAD_BF(0, 0); else LOAD_FP(0, 0);
    asm volatile("cp.async.commit_group;" ::: "memory");

    for (int it = 0; it < 32; ++it) {
        asm volatile("cp.async.wait_group 0;" ::: "memory");
        __syncthreads();   // buf `it` ready; all warps done reading buf (it+1)&1 (iter it-1)
        const int nxt = it + 1;
        if (nxt < 32) {
            if (bf) LOAD_BF(nxt & 1, nxt * 32); else LOAD_FP(nxt & 1, nxt * 32);
        }
        asm volatile("cp.async.commit_group;" ::: "memory");

        const uint32_t buf = smb + (it & 1) * STG_B;
        if (bf) {
#pragma unroll
            for (int ks = 0; ks < 2; ++ks) {
                uint32_t ah[2][4], al[2][4];
#pragma unroll
                for (int i = 0; i < 2; ++i) {
                    uint32_t ra = buf + (arow + i * 16) * TROW + (ks * 2 + acho) * 16;
                    LDSM4(ah[i][0], ah[i][1], ah[i][2], ah[i][3], ra);
                    LDSM4(al[i][0], al[i][1], al[i][2], al[i][3], ra + TILE_B);
                }
#pragma unroll
                for (int g = 0; g < 4; ++g) {
                    uint32_t bh[4], bl[4];
                    uint32_t rb = buf + 2 * TILE_B + (brow + g * 16) * TROW + (ks * 2 + bcho) * 16;
                    LDSM4(bh[0], bh[1], bh[2], bh[3], rb);
                    LDSM4(bl[0], bl[1], bl[2], bl[3], rb + TILE_B);
#pragma unroll
                    for (int i = 0; i < 2; ++i)
#pragma unroll
                        for (int hf = 0; hf < 2; ++hf) {
                            const int jn = g * 2 + hf;
                            MMA16816(acc[i][jn], ah[i][0], ah[i][1], ah[i][2], ah[i][3],
                                     bh[hf * 2], bh[hf * 2 + 1]);
                            MMA16816(acc[i][jn], ah[i][0], ah[i][1], ah[i][2], ah[i][3],
                                     bl[hf * 2], bl[hf * 2 + 1]);
                            MMA16816(acc[i][jn], al[i][0], al[i][1], al[i][2], al[i][3],
                                     bh[hf * 2], bh[hf * 2 + 1]);
                        }
                }
            }
        } else {
#pragma unroll
            for (int ks = 0; ks < 2; ++ks) {
                uint32_t ah[2][4], al[2][4];
#pragma unroll
                for (int i = 0; i < 2; ++i) {
                    uint32_t ra = buf + (arow + i * 16) * TROW + (ks * 2 + acho) * 16;
                    LDSM4(ah[i][0], ah[i][1], ah[i][2], ah[i][3], ra);
                    LDSM4(al[i][0], al[i][1], al[i][2], al[i][3], ra + TILE_B);
                }
#pragma unroll
                for (int g = 0; g < 4; ++g) {
                    uint32_t bfr[4];
                    uint32_t rb = buf + 2 * TILE_B + (brow + g * 16) * TROW + (ks * 2 + bcho) * 16;
                    LDSM4(bfr[0], bfr[1], bfr[2], bfr[3], rb);
#pragma unroll
                    for (int i = 0; i < 2; ++i)
#pragma unroll
                        for (int hf = 0; hf < 2; ++hf) {
                            const int jn = g * 2 + hf;
                            MMA16816H(acc[i][jn], ah[i][0], ah[i][1], ah[i][2], ah[i][3],
                                      bfr[hf * 2], bfr[hf * 2 + 1]);
                            MMA16816H(acc[i][jn], al[i][0], al[i][1], al[i][2], al[i][3],
                                      bfr[hf * 2], bfr[hf * 2 + 1]);
                        }
                }
            }
        }
    }

#pragma unroll
    for (int i = 0; i < 2; ++i) {
        const int r0 = m0 + wm * 32 + i * 16 + (lane >> 2);
#pragma unroll
        for (int jn = 0; jn < 8; ++jn) {
            const int cc = n0 + wn * 64 + jn * 8 + 2 * (lane & 3);
            *(float2*)&C[(size_t)r0 * Dm + cc]       = make_float2(acc[i][jn][0], acc[i][jn][1]);
            *(float2*)&C[(size_t)(r0 + 8) * Dm + cc] = make_float2(acc[i][jn][2], acc[i][jn][3]);
        }
    }
}

// ---------------- K1b: output GEMM (2-pass fp16), single sync/iter ----------------
#define STG2_B (3 * TILE_B)          // 30720
#define G2SMEM (2 * STG2_B)          // 61440

__global__ void __launch_bounds__(256, 2) out_kernel(float* __restrict__ Cout) {
    extern __shared__ char sm[];
    const uint32_t smb = smem_u32(sm);
    const int tid = threadIdx.x;
    const int m0 = blockIdx.y * 128, n0 = blockIdx.x * 128;

    const __half* Ahi = g_yh16;
    const __half* Alo = g_yl16;
    const __half* B   = g_wt16 + (size_t)Dm * Dm;   // Wo^T

#define LOAD_OUT(buf, k0)                                                     \
    do {                                                                      \
        uint32_t sb_ = smb + (buf) * STG2_B;                                  \
        _Pragma("unroll")                                                     \
        for (int j_ = 0; j_ < 6; ++j_) {                                      \
            int lin_ = tid + 256 * j_;                                        \
            int tile_ = lin_ >> 9;                                            \
            int idx_ = lin_ & 511;                                            \
            int r_ = idx_ >> 2, c_ = idx_ & 3;                                \
            const __half* gp_ = (tile_ == 0) ? Ahi : (tile_ == 1) ? Alo : B;  \
            int gr_ = (tile_ < 2) ? (m0 + r_) : (n0 + r_);                    \
            CP_ASYNC16(sb_ + tile_ * TILE_B + r_ * TROW + c_ * 16,            \
                       gp_ + (size_t)gr_ * Dm + (k0) + c_ * 8);               \
        }                                                                     \
    } while (0)

    const int lane = tid & 31, w = tid >> 5;
    const int wm = w & 3, wn = w >> 2;
    const int lj = lane >> 3, lm = lane & 7;
    const int arow = wm * 32 + (lj & 1) * 8 + lm;
    const int acho = lj >> 1;
    const int brow = wn * 64 + ((lj & 2) ? 8 : 0) + lm;
    const int bcho = lj & 1;

    float acc[2][8][4];
#pragma unroll
    for (int i = 0; i < 2; i++)
#pragma unroll
        for (int jn = 0; jn < 8; jn++)
#pragma unroll
            for (int r = 0; r < 4; r++) acc[i][jn][r] = 0.f;

    LOAD_OUT(0, 0);
    asm volatile("cp.async.commit_group;" ::: "memory");

    for (int it = 0; it < 32; ++it) {
        asm volatile("cp.async.wait_group 0;" ::: "memory");
        __syncthreads();
        const int nxt = it + 1;
        if (nxt < 32) LOAD_OUT(nxt & 1, nxt * 32);
        asm volatile("cp.async.commit_group;" ::: "memory");

        const uint32_t buf = smb + (it & 1) * STG2_B;
#pragma unroll
        for (int ks = 0; ks < 2; ++ks) {
            uint32_t ah[2][4], al[2][4];
#pragma unroll
            for (int i = 0; i < 2; ++i) {
                uint32_t ra = buf + (arow + i * 16) * TROW + (ks * 2 + acho) * 16;
                LDSM4(ah[i][0], ah[i][1], ah[i][2], ah[i][3], ra);
                LDSM4(al[i][0], al[i][1], al[i][2], al[i][3], ra + TILE_B);
            }
#pragma unroll
            for (int g = 0; g < 4; ++g) {
                uint32_t bfr[4];
                uint32_t rb = buf + 2 * TILE_B + (brow + g * 16) * TROW + (ks * 2 + bcho) * 16;
                LDSM4(bfr[0], bfr[1], bfr[2], bfr[3], rb);
#pragma unroll
                for (int i = 0; i < 2; ++i)
#pragma unroll
                    for (int hf = 0; hf < 2; ++hf) {
                        const int jn = g * 2 + hf;
                        MMA16816H(acc[i][jn], ah[i][0], ah[i][1], ah[i][2], ah[i][3],
                                  bfr[hf * 2], bfr[hf * 2 + 1]);
                        MMA16816H(acc[i][jn], al[i][0], al[i][1], al[i][2], al[i][3],
                                  bfr[hf * 2], bfr[hf * 2 + 1]);
                    }
            }
        }
    }

#pragma unroll
    for (int i = 0; i < 2; ++i) {
        const int r0 = m0 + wm * 32 + i * 16 + (lane >> 2);
#pragma unroll
        for (int jn = 0; jn < 8; ++jn) {
            const int cc = n0 + wn * 64 + jn * 8 + 2 * (lane & 3);
            *(float2*)&Cout[(size_t)r0 * Dm + cc]       = make_float2(acc[i][jn][0], acc[i][jn][1]);
            *(float2*)&Cout[(size_t)(r0 + 8) * Dm + cc] = make_float2(acc[i][jn][2], acc[i][jn][3]);
        }
    }
}

// ---------------- K2: FAVOR+ features via HMMA + exp epilogue ----------------
#define FA_P 144
#define FW_P 272
#define FA_H 0
#define FA_L (FA_H + 128 * FA_P)
#define FW_H (FA_L + 128 * FA_P)
#define FW_L (FW_H + 64 * FW_P)
#define FSQ  (FW_L + 64 * FW_P)
#define FSM  (FSQ + 512)

__global__ void __launch_bounds__(256) feat_kernel(const float* __restrict__ Wf) {
    extern __shared__ char sm[];
    const uint32_t smb = smem_u32(sm);
    const int tid = threadIdx.x;
    const int bt0 = blockIdx.x * 128, h = blockIdx.y, sel = blockIdx.z;
    const float* src = g_qkv + (size_t)sel * QKV_OFF;

#pragma unroll
    for (int j = 0; j < 8; ++j) {
        int lin = tid + 256 * j;
        int rr = lin >> 4, cc = lin & 15;
        float4 v = *(const float4*)(src + (size_t)(bt0 + rr) * Dm + h * HDm + cc * 4);
        uint32_t h01, l01, h23, l23;
        split2(v.x, v.y, h01, l01);
        split2(v.z, v.w, h23, l23);
        *(uint2*)(sm + FA_H + rr * FA_P + cc * 8) = make_uint2(h01, h23);
        *(uint2*)(sm + FA_L + rr * FA_P + cc * 8) = make_uint2(l01, l23);
    }
#pragma unroll
    for (int j = 0; j < 8; ++j) {
        int lin = tid + 256 * j;
        int rr = lin >> 5, cc = lin & 31;
        float4 v = *(const float4*)(Wf + (size_t)rr * NFm + cc * 4);
        uint32_t h01, l01, h23, l23;
        split2(v.x, v.y, h01, l01);
        split2(v.z, v.w, h23, l23);
        *(uint2*)(sm + FW_H + rr * FW_P + cc * 8) = make_uint2(h01, h23);
        *(uint2*)(sm + FW_L + rr * FW_P + cc * 8) = make_uint2(l01, l23);
    }
    __syncthreads();

    if (tid < 128) {
        float s = 0.f;
#pragma unroll
        for (int d2 = 0; d2 < 32; ++d2) {
            __nv_bfloat162 vh = *(__nv_bfloat162*)(sm + FA_H + tid * FA_P + d2 * 4);
            __nv_bfloat162 vl = *(__nv_bfloat162*)(sm + FA_L + tid * FA_P + d2 * 4);
            float2 fh = __bfloat1622float2(vh), fl = __bfloat1622float2(vl);
            float a = fh.x + fl.x, b = fh.y + fl.y;
            s = fmaf(a, a, fmaf(b, b, s));
        }
        ((float*)(sm + FSQ))[tid] = 0.5f * s;
    }
    __syncthreads();

    const int l = tid & 31, w = tid >> 5;
    const int lj = l >> 3, lm = l & 7;
    const int arow = w * 16 + (lj & 1) * 8 + lm;
    const int acho = lj >> 1;
    const int m = l >> 3, r = l & 7;
    const int sB = (m & 1) ? 8 : 0, eB = (m & 2) ? 8 : 0;

    float acc[16][4];
#pragma unroll
    for (int nb = 0; nb < 16; ++nb)
#pragma unroll
        for (int q = 0; q < 4; ++q) acc[nb][q] = 0.f;

#pragma unroll
    for (int ks = 0; ks < 4; ++ks) {
        uint32_t ah[4], al[4];
        uint32_t ad = smb + FA_H + arow * FA_P + (ks * 2 + acho) * 16;
        LDSM4(ah[0], ah[1], ah[2], ah[3], ad);
        LDSM4(al[0], al[1], al[2], al[3], ad + (FA_L - FA_H));
#pragma unroll
        for (int fg = 0; fg < 8; ++fg) {
            uint32_t bhf[4], blf[4];
            uint32_t bd = smb + FW_H + (ks * 16 + sB + r) * FW_P + (fg * 16 + eB) * 2;
            LDSM4T(bhf[0], bhf[1], bhf[2], bhf[3], bd);
            LDSM4T(blf[0], blf[1], blf[2], blf[3], bd + (FW_L - FW_H));
#pragma unroll
            for (int hf = 0; hf < 2; ++hf) {
                const int nb = fg * 2 + hf;
                MMA16816(acc[nb], ah[0], ah[1], ah[2], ah[3], bhf[hf * 2], bhf[hf * 2 + 1]);
                MMA16816(acc[nb], ah[0], ah[1], ah[2], ah[3], blf[hf * 2], blf[hf * 2 + 1]);
                MMA16816(acc[nb], al[0], al[1], al[2], al[3], bhf[hf * 2], bhf[hf * 2 + 1]);
            }
        }
    }

    float* dst = sel ? g_kp : g_qp;
    const int b = bt0 >> 11;
    const int bh = b * Hh + h;
    const int trow0 = w * 16 + (l >> 2);
    const float* sqp = (const float*)(sm + FSQ);
    const float sq0 = sqp[trow0], sq1 = sqp[trow0 + 8];
    const int t0 = (bt0 & 2047) + trow0;
    float* d0 = dst + ((size_t)bh * Tt + t0) * NFm;
    float* d1 = dst + ((size_t)bh * Tt + t0 + 8) * NFm;
#pragma unroll
    for (int nb = 0; nb < 16; ++nb) {
        const int f = nb * 8 + (l & 3) * 2;
        *(float2*)(d0 + f) = make_float2(expf(acc[nb][0] - sq0) * INV_SQRT_NF,
                                         expf(acc[nb][1] - sq0) * INV_SQRT_NF);
        *(float2*)(d1 + f) = make_float2(expf(acc[nb][2] - sq1) * INV_SQRT_NF,
                                         expf(acc[nb][3] - sq1) * INV_SQRT_NF);
    }
}

// ---------------- K3: chunk_sum via HMMA ----------------
#define PKb 272
#define PVb 144
#define CS_KH 0
#define CS_KL (CS_KH + 128 * PKb)
#define CS_VH (CS_KL + 128 * PKb)
#define CS_VL (CS_VH + 128 * PVb)
#define SMEM3 (CS_VL + 128 * PVb)

__global__ void __launch_bounds__(256, 1) chunk_sum_kernel() {
    extern __shared__ char sm[];
    const uint32_t smb = smem_u32(sm);
    const int c = blockIdx.x, bh = blockIdx.y;
    const int b = bh >> 4, h = bh & 15;
    const int tid = threadIdx.x;
    const float* GV = g_qkv + 2 * QKV_OFF;
    const size_t kbase = ((size_t)bh * Tt + c * CHK) * NFm;
    const size_t vbase = ((size_t)(b * Tt + c * CHK)) * Dm + h * HDm;

#pragma unroll
    for (int j = 0; j < 16; ++j) {
        int lin = tid + 256 * j;
        int rr = lin >> 5, cc = lin & 31;
        float4 v = *(const float4*)(g_kp + kbase + (size_t)rr * NFm + cc * 4);
        uint32_t h01, l01, h23, l23;
        split2(v.x, v.y, h01, l01);
        split2(v.z, v.w, h23, l23);
        *(uint2*)(sm + CS_KH + rr * PKb + cc * 8) = make_uint2(h01, h23);
        *(uint2*)(sm + CS_KL + rr * PKb + cc * 8) = make_uint2(l01, l23);
    }
#pragma unroll
    for (int j = 0; j < 8; ++j) {
        int lin = tid + 256 * j;
        int rr = lin >> 4, cc = lin & 15;
        float4 v = *(const float4*)(GV + vbase + (size_t)rr * Dm + cc * 4);
        uint32_t h01, l01, h23, l23;
        split2(v.x, v.y, h01, l01);
        split2(v.z, v.w, h23, l23);
        *(uint2*)(sm + CS_VH + rr * PVb + cc * 8) = make_uint2(h01, h23);
        *(uint2*)(sm + CS_VL + rr * PVb + cc * 8) = make_uint2(l01, l23);
    }
    __syncthreads();

    const int l = tid & 31, w = tid >> 5;
    const int m = l >> 3, r = l & 7;
    const int f0w = (w & 3) * 32, e0w = (w >> 2) * 32;
    const int sA = (m & 2) ? 8 : 0, fA = (m & 1) ? 8 : 0;
    const int sB = (m & 1) ? 8 : 0, eB = (m & 2) ? 8 : 0;

    float acc[2][4][4];
#pragma unroll
    for (int i = 0; i < 2; i++)
#pragma unroll
        for (int jn = 0; jn < 4; jn++)
#pragma unroll
            for (int q = 0; q < 4; q++) acc[i][jn][q] = 0.f;

    for (int s0 = 0; s0 < 128; s0 += 16) {
        uint32_t ah[2][4], al[2][4], bhf[2][4], blf[2][4];
#pragma unroll
        for (int i = 0; i < 2; ++i) {
            uint32_t ad = smb + CS_KH + (s0 + sA + r) * PKb + (f0w + i * 16 + fA) * 2;
            LDSM4T(ah[i][0], ah[i][1], ah[i][2], ah[i][3], ad);
            LDSM4T(al[i][0], al[i][1], al[i][2], al[i][3], ad + (CS_KL - CS_KH));
        }
#pragma unroll
        for (int j2 = 0; j2 < 2; ++j2) {
            uint32_t ad = smb + CS_VH + (s0 + sB + r) * PVb + (e0w + j2 * 16 + eB) * 2;
            LDSM4T(bhf[j2][0], bhf[j2][1], bhf[j2][2], bhf[j2][3], ad);
            LDSM4T(blf[j2][0], blf[j2][1], blf[j2][2], blf[j2][3], ad + (CS_VL - CS_VH));
        }
#pragma unroll
        for (int i = 0; i < 2; ++i)
#pragma unroll
            for (int jn = 0; jn < 4; ++jn) {
                const int j2 = jn >> 1, o = (jn & 1) * 2;
                MMA16816(acc[i][jn], ah[i][0], ah[i][1], ah[i][2], ah[i][3],
                         bhf[j2][o], bhf[j2][o + 1]);
                MMA16816(acc[i][jn], ah[i][0], ah[i][1], ah[i][2], ah[i][3],
                         blf[j2][o], blf[j2][o + 1]);
                MMA16816(acc[i][jn], al[i][0], al[i][1], al[i][2], al[i][3],
                         bhf[j2][o], bhf[j2][o + 1]);
            }
    }

    const size_t Sbase = ((size_t)bh * NCH + c) * (NFm * HDm);
#pragma unroll
    for (int i = 0; i < 2; ++i) {
        const int fr = f0w + i * 16 + (l >> 2);
#pragma unroll
        for (int jn = 0; jn < 4; ++jn) {
            const int ec = e0w + jn * 8 + (l & 3) * 2;
            *(float2*)(g_S + Sbase + (size_t)fr * HDm + ec) =
                make_float2(acc[i][jn][0], acc[i][jn][1]);
            *(float2*)(g_S + Sbase + (size_t)(fr + 8) * HDm + ec) =
                make_float2(acc[i][jn][2], acc[i][jn][3]);
        }
    }
    if (tid < 128) {
        float zz = 0.f;
        for (int s = 0; s < 128; ++s) zz += g_kp[kbase + (size_t)s * NFm + tid];
        g_z[((size_t)bh * NCH + c) * NFm + tid] = zz;
    }
}

// ---------------- K4: exclusive prefix over chunks ----------------
__global__ void __launch_bounds__(256) prefix_kernel() {   // grid (32, BH)
    const int bh = blockIdx.y, seg = blockIdx.x;
    const int idx = seg * 256 + threadIdx.x;
    float v[NCH];
    const size_t base = (size_t)bh * NCH * NFm * HDm + idx;
#pragma unroll
    for (int c = 0; c < NCH; ++c) v[c] = g_S[base + (size_t)c * NFm * HDm];
    float acc = 0.f;
#pragma unroll
    for (int c = 0; c < NCH; ++c) { float cur = v[c]; v[c] = acc; acc += cur; }
#pragma unroll
    for (int c = 0; c < NCH; ++c) g_S[base + (size_t)c * NFm * HDm] = v[c];
    if (seg == 0 && threadIdx.x < NFm) {
        float zv[NCH];
        const size_t zb = (size_t)bh * NCH * NFm + threadIdx.x;
#pragma unroll
        for (int c = 0; c < NCH; ++c) zv[c] = g_z[zb + c * NFm];
        float az = 0.f;
#pragma unroll
        for (int c = 0; c < NCH; ++c) { float cur = zv[c]; zv[c] = az; az += cur; }
#pragma unroll
        for (int c = 0; c < NCH; ++c) g_z[zb + c * NFm] = zv[c];
    }
}

// ---------------- K5: chunk_out via HMMA (writes y as fp16 hi/lo) ----------------
#define CO_QH 0
#define CO_QL (CO_QH + 128 * PKb)
#define CO_KH (CO_QL + 128 * PKb)
#define CO_KL (CO_KH + 128 * PKb)
#define CO_VH (CO_KL + 128 * PKb)
#define CO_VL (CO_VH + 128 * PVb)
#define CO_SH (CO_VL + 128 * PVb)
#define CO_SL (CO_SH + 128 * PVb)
#define CO_Z  (CO_SL + 128 * PVb)
#define CO_D  (CO_Z + 512)
#define SMEM5 (CO_D + 512)

__global__ void __launch_bounds__(256, 1) chunk_out_kernel() {
    extern __shared__ char sm[];
    const uint32_t smb = smem_u32(sm);
    const int c = blockIdx.x, bh = blockIdx.y;
    const int b = bh >> 4, h = bh & 15;
    const int tid = threadIdx.x;
    const float* GV = g_qkv + 2 * QKV_OFF;
    const size_t qbase = ((size_t)bh * Tt + c * CHK) * NFm;
    const size_t vbase = ((size_t)(b * Tt + c * CHK)) * Dm + h * HDm;
    const size_t Sbase = ((size_t)bh * NCH + c) * (NFm * HDm);

#pragma unroll
    for (int j = 0; j < 16; ++j) {
        int lin = tid + 256 * j;
        int rr = lin >> 5, cc = lin & 31;
        float4 q4 = *(const float4*)(g_qp + qbase + (size_t)rr * NFm + cc * 4);
        float4 k4 = *(const float4*)(g_kp + qbase + (size_t)rr * NFm + cc * 4);
        uint32_t h01, l01, h23, l23;
        split2(q4.x, q4.y, h01, l01);
        split2(q4.z, q4.w, h23, l23);
        *(uint2*)(sm + CO_QH + rr * PKb + cc * 8) = make_uint2(h01, h23);
        *(uint2*)(sm + CO_QL + rr * PKb + cc * 8) = make_uint2(l01, l23);
        split2(k4.x, k4.y, h01, l01);
        split2(k4.z, k4.w, h23, l23);
        *(uint2*)(sm + CO_KH + rr * PKb + cc * 8) = make_uint2(h01, h23);
        *(uint2*)(sm + CO_KL + rr * PKb + cc * 8) = make_uint2(l01, l23);
    }
#pragma unroll
    for (int j = 0; j < 8; ++j) {
        int lin = tid + 256 * j;
        int rr = lin >> 4, cc = lin & 15;
        float4 v4 = *(const float4*)(GV + vbase + (size_t)rr * Dm + cc * 4);
        uint32_t h01, l01, h23, l23;
        split2(v4.x, v4.y, h01, l01);
        split2(v4.z, v4.w, h23, l23);
        *(uint2*)(sm + CO_VH + rr * PVb + cc * 8) = make_uint2(h01, h23);
        *(uint2*)(sm + CO_VL + rr * PVb + cc * 8) = make_uint2(l01, l23);
        float4 s4 = *(const float4*)(g_S + Sbase + (size_t)rr * HDm + cc * 4);
        split2(s4.x, s4.y, h01, l01);
        split2(s4.z, s4.w, h23, l23);
        *(uint2*)(sm + CO_SH + rr * PVb + cc * 8) = make_uint2(h01, h23);
        *(uint2*)(sm + CO_SL + rr * PVb + cc * 8) = make_uint2(l01, l23);
    }
    if (tid < 128)
        ((float*)(sm + CO_Z))[tid] = g_z[((size_t)bh * NCH + c) * NFm + tid];
    __syncthreads();

    const int l = tid & 31, w = tid >> 5;
    const int wm = w & 3, wn = w >> 2;
    const int lj = l >> 3, lm = l & 7;
    const int m = l >> 3, r = l & 7;
    const int arow = wm * 32 + (lj & 1) * 8 + lm;
    const int acho = lj >> 1;
    const int brow = ((lj & 2) ? 8 : 0) + lm;
    const int bcho = lj & 1;
    const int sB = (m & 1) ? 8 : 0, eB = (m & 2) ? 8 : 0;

    float accA[2][8][4];
#pragma unroll
    for (int i = 0; i < 2; i++)
#pragma unroll
        for (int jn = 0; jn < 8; jn++)
#pragma unroll
            for (int q = 0; q < 4; q++) accA[i][jn][q] = 0.f;

    for (int f0 = 0; f0 < 128; f0 += 16) {
        uint32_t qh[2][4], ql[2][4];
#pragma unroll
        for (int i = 0; i < 2; ++i) {
            uint32_t ad = smb + CO_QH + (arow + i * 16) * PKb + (f0 / 8 + acho) * 16;
            LDSM4(qh[i][0], qh[i][1], qh[i][2], qh[i][3], ad);
            LDSM4(ql[i][0], ql[i][1], ql[i][2], ql[i][3], ad + (CO_QL - CO_QH));
        }
#pragma unroll
        for (int g = 0; g < 4; ++g) {
            uint32_t kh[4], kl[4];
            uint32_t ad = smb + CO_KH + (wn * 64 + brow + g * 16) * PKb + (f0 / 8 + bcho) * 16;
            LDSM4(kh[0], kh[1], kh[2], kh[3], ad);
            LDSM4(kl[0], kl[1], kl[2], kl[3], ad + (CO_KL - CO_KH));
#pragma unroll
            for (int i = 0; i < 2; ++i)
#pragma unroll
                for (int hf = 0; hf < 2; ++hf) {
                    const int jn = g * 2 + hf;
                    MMA16816(accA[i][jn], qh[i][0], qh[i][1], qh[i][2], qh[i][3],
                             kh[hf * 2], kh[hf * 2 + 1]);
                    MMA16816(accA[i][jn], qh[i][0], qh[i][1], qh[i][2], qh[i][3],
                             kl[hf * 2], kl[hf * 2 + 1]);
                    MMA16816(accA[i][jn], ql[i][0], ql[i][1], ql[i][2], ql[i][3],
                             kh[hf * 2], kh[hf * 2 + 1]);
                }
        }
    }
    __syncthreads();

#pragma unroll
    for (int i = 0; i < 2; ++i) {
        const int tr = wm * 32 + i * 16 + (l >> 2);
#pragma unroll
        for (int jn = 0; jn < 8; ++jn) {
            const int sc = wn * 64 + jn * 8 + (l & 3) * 2;
            float v0 = (sc     <= tr) ? accA[i][jn][0] : 0.f;
            float v1 = (sc + 1 <= tr) ? accA[i][jn][1] : 0.f;
            uint32_t hi, lo;
            split2(v0, v1, hi, lo);
            *(uint32_t*)(sm + CO_KH + tr * PKb + sc * 2) = hi;
            *(uint32_t*)(sm + CO_KL + tr * PKb + sc * 2) = lo;
            const int tr8 = tr + 8;
            v0 = (sc     <= tr8) ? accA[i][jn][2] : 0.f;
            v1 = (sc + 1 <= tr8) ? accA[i][jn][3] : 0.f;
            split2(v0, v1, hi, lo);
            *(uint32_t*)(sm + CO_KH + tr8 * PKb + sc * 2) = hi;
            *(uint32_t*)(sm + CO_KL + tr8 * PKb + sc * 2) = lo;
        }
    }
    __syncthreads();

    if (tid < 128) {
        const int t = tid;
        float den = EPSf;
        const float* zp = (const float*)(sm + CO_Z);
#pragma unroll 8
        for (int f2 = 0; f2 < 64; ++f2) {
            __nv_bfloat162 qh2 = *(__nv_bfloat162*)(sm + CO_QH + t * PKb + f2 * 4);
            __nv_bfloat162 ql2 = *(__nv_bfloat162*)(sm + CO_QL + t * PKb + f2 * 4);
            float2 fh = __bfloat1622float2(qh2), fl = __bfloat1622float2(ql2);
            den += (fh.x + fl.x) * zp[2 * f2] + (fh.y + fl.y) * zp[2 * f2 + 1];
        }
#pragma unroll 8
        for (int s2 = 0; s2 < 64; ++s2) {
            __nv_bfloat162 ah2 = *(__nv_bfloat162*)(sm + CO_KH + t * PKb + s2 * 4);
            __nv_bfloat162 al2 = *(__nv_bfloat162*)(sm + CO_KL + t * PKb + s2 * 4);
            float2 fa = __bfloat1622float2(ah2), fb = __bfloat1622float2(al2);
            den += fa.x + fa.y + fb.x + fb.y;
        }
        ((float*)(sm + CO_D))[t] = 1.f / den;
    }
    __syncthreads();

    const int e0w = wn * 32;
    float accY[2][4][4];
#pragma unroll
    for (int i = 0; i < 2; i++)
#pragma unroll
        for (int jn = 0; jn < 4; jn++)
#pragma unroll
            for (int q = 0; q < 4; q++) accY[i][jn][q] = 0.f;

    for (int s0 = 0; s0 < 128; s0 += 16) {
        uint32_t aah[2][4], aal[2][4], vh[2][4], vl[2][4];
#pragma unroll
        for (int i = 0; i < 2; ++i) {
            uint32_t ad = smb + CO_KH + (arow + i * 16) * PKb + (s0 / 8 + acho) * 16;
            LDSM4(aah[i][0], aah[i][1], aah[i][2], aah[i][3], ad);
            LDSM4(aal[i][0], aal[i][1], aal[i][2], aal[i][3], ad + (CO_KL - CO_KH));
        }
#pragma unroll
        for (int j2 = 0; j2 < 2; ++j2) {
            uint32_t ad = smb + CO_VH + (s0 + sB + r) * PVb + (e0w + j2 * 16 + eB) * 2;
            LDSM4T(vh[j2][0], vh[j2][1], vh[j2][2], vh[j2][3], ad);
            LDSM4T(vl[j2][0], vl[j2][1], vl[j2][2], vl[j2][3], ad + (CO_VL - CO_VH));
        }
#pragma unroll
        for (int i = 0; i < 2; ++i)
#pragma unroll
            for (int jn = 0; jn < 4; ++jn) {
                const int j2 = jn >> 1, o = (jn & 1) * 2;
                MMA16816(accY[i][jn], aah[i][0], aah[i][1], aah[i][2], aah[i][3],
                         vh[j2][o], vh[j2][o + 1]);
                MMA16816(accY[i][jn], aah[i][0], aah[i][1], aah[i][2], aah[i][3],
                         vl[j2][o], vl[j2][o + 1]);
                MMA16816(accY[i][jn], aal[i][0], aal[i][1], aal[i][2], aal[i][3],
                         vh[j2][o], vh[j2][o + 1]);
            }
    }
    for (int f0 = 0; f0 < 128; f0 += 16) {
        uint32_t qh[2][4], ql[2][4], sh[2][4], sl[2][4];
#pragma unroll
        for (int i = 0; i < 2; ++i) {
            uint32_t ad = smb + CO_QH + (arow + i * 16) * PKb + (f0 / 8 + acho) * 16;
            LDSM4(qh[i][0], qh[i][1], qh[i][2], qh[i][3], ad);
            LDSM4(ql[i][0], ql[i][1], ql[i][2], ql[i][3], ad + (CO_QL - CO_QH));
        }
#pragma unroll
        for (int j2 = 0; j2 < 2; ++j2) {
            uint32_t ad = smb + CO_SH + (f0 + sB + r) * PVb + (e0w + j2 * 16 + eB) * 2;
            LDSM4T(sh[j2][0], sh[j2][1], sh[j2][2], sh[j2][3], ad);
            LDSM4T(sl[j2][0], sl[j2][1], sl[j2][2], sl[j2][3], ad + (CO_SL - CO_SH));
        }
#pragma unroll
        for (int i = 0; i < 2; ++i)
#pragma unroll
            for (int jn = 0; jn < 4; ++jn) {
                const int j2 = jn >> 1, o = (jn & 1) * 2;
                MMA16816(accY[i][jn], qh[i][0], qh[i][1], qh[i][2], qh[i][3],
                         sh[j2][o], sh[j2][o + 1]);
                MMA16816(accY[i][jn], qh[i][0], qh[i][1], qh[i][2], qh[i][3],
                         sl[j2][o], sl[j2][o + 1]);
                MMA16816(accY[i][jn], ql[i][0], ql[i][1], ql[i][2], ql[i][3],
                         sh[j2][o], sh[j2][o + 1]);
            }
    }

    const float* dv = (const float*)(sm + CO_D);
#pragma unroll
    for (int i = 0; i < 2; ++i) {
        const int tr = wm * 32 + i * 16 + (l >> 2);
        const float d0 = dv[tr], d1 = dv[tr + 8];
#pragma unroll
        for (int jn = 0; jn < 4; ++jn) {
            const int ec = e0w + jn * 8 + (l & 3) * 2;
            size_t o0 = ((size_t)(b * Tt + c * CHK + tr)) * Dm + h * HDm + ec;
            size_t o1 = ((size_t)(b * Tt + c * CHK + tr + 8)) * Dm + h * HDm + ec;
            uint32_t hi, lo;
            split2h(accY[i][jn][0] * d0, accY[i][jn][1] * d0, hi, lo);
            *(uint32_t*)(g_yh16 + o0) = hi;
            *(uint32_t*)(g_yl16 + o0) = lo;
            split2h(accY[i][jn][2] * d1, accY[i][jn][3] * d1, hi, lo);
            *(uint32_t*)(g_yh16 + o1) = hi;
            *(uint32_t*)(g_yl16 + o1) = lo;
        }
    }
}

// ---------------------------------------------------------------------------
extern "C" void kernel_launch(void* const* d_in, const int* in_sizes, int n_in,
                              void* d_out, int out_size) {
    const float* x  = (const float*)d_in[0];
    const float* Wq = (const float*)d_in[1];
    const float* Wk = (const float*)d_in[2];
    const float* Wv = (const float*)d_in[3];
    const float* Wo = (const float*)d_in[4];
    const float* Wf = (const float*)d_in[5];
    float* out = (float*)d_out;

    cudaFuncSetAttribute(proj_kernel,      cudaFuncAttributeMaxDynamicSharedMemorySize, GSMEM);
    cudaFuncSetAttribute(out_kernel,       cudaFuncAttributeMaxDynamicSharedMemorySize, G2SMEM);
    cudaFuncSetAttribute(feat_kernel,      cudaFuncAttributeMaxDynamicSharedMemorySize, FSM);
    cudaFuncSetAttribute(chunk_sum_kernel, cudaFuncAttributeMaxDynamicSharedMemorySize, SMEM3);
    cudaFuncSetAttribute(chunk_out_kernel, cudaFuncAttributeMaxDynamicSharedMemorySize, SMEM5);

    split_kernel<<<(MR * Dm / 4) / 256, 256>>>(x);
    wsplit_kernel<<<dim3(32, 32, 4), 256>>>(Wq, Wk, Wv, Wo);
    proj_kernel<<<dim3(8, 64, 3), 256, GSMEM>>>();              // q, k, v fused
    feat_kernel<<<dim3(MR / 128, Hh, 2), 256, FSM>>>(Wf);
    chunk_sum_kernel<<<dim3(NCH, BH), 256, SMEM3>>>();
    prefix_kernel<<<dim3(32, BH), 256>>>();
    chunk_out_kernel<<<dim3(NCH, BH), 256, SMEM5>>>();
    out_kernel<<<dim3(8, 64), 256, G2SMEM>>>(out);
}

// round 12
// speedup vs baseline: 3.8501x; 1.0883x over previous
#include <cuda_runtime.h>
#include <cuda_bf16.h>
#include <cuda_fp16.h>
#include <math.h>
#include <stdint.h>

// ---------------- problem constants ----------------
#define Bb   4
#define Tt   2048
#define Dm   1024
#define Hh   16
#define HDm  64
#define NFm  128
#define CHK  128
#define NCH  16
#define BH   64
#define MR   8192
#define EPSf 1e-6f
#define INV_SQRT_NF 0.08838834764831845f

#define QKV_OFF ((size_t)MR * Dm)

// ---------------- scratch ----------------
__device__ float g_qkv[3 * (size_t)MR * Dm];   // q | k | v
__device__ float g_qp [(size_t)BH * Tt * NFm];
__device__ float g_kp [(size_t)BH * Tt * NFm];
__device__ float g_S  [(size_t)BH * NCH * NFm * HDm];
__device__ float g_z  [(size_t)BH * NCH * NFm];

__device__ __half g_xh16[(size_t)MR * Dm], g_xl16[(size_t)MR * Dm];   // x fp16 split
__device__ __half g_yh16[(size_t)MR * Dm], g_yl16[(size_t)MR * Dm];   // y fp16 split
__device__ __half g_wt16[4 * (size_t)Dm * Dm];                        // Wq,Wk,Wv,Wo ^T fp16

// ---------------- helpers ----------------
__device__ __forceinline__ uint32_t smem_u32(const void* p) {
    uint32_t a;
    asm("{ .reg .u64 t; cvta.to.shared.u64 t, %1; cvt.u32.u64 %0, t; }" : "=r"(a) : "l"(p));
    return a;
}

#define LDSM4(r0, r1, r2, r3, addr)                                          \
    asm volatile("ldmatrix.sync.aligned.m8n8.x4.shared.b16 {%0,%1,%2,%3}, [%4];" \
                 : "=r"(r0), "=r"(r1), "=r"(r2), "=r"(r3) : "r"(addr))

#define LDSM4T(r0, r1, r2, r3, addr)                                         \
    asm volatile("ldmatrix.sync.aligned.m8n8.x4.trans.shared.b16 {%0,%1,%2,%3}, [%4];" \
                 : "=r"(r0), "=r"(r1), "=r"(r2), "=r"(r3) : "r"(addr))

#define MMA16816(d, a0, a1, a2, a3, b0, b1)                                  \
    asm volatile("mma.sync.aligned.m16n8k16.row.col.f32.bf16.bf16.f32 "      \
                 "{%0,%1,%2,%3}, {%4,%5,%6,%7}, {%8,%9}, {%0,%1,%2,%3};"     \
                 : "+f"((d)[0]), "+f"((d)[1]), "+f"((d)[2]), "+f"((d)[3])    \
                 : "r"(a0), "r"(a1), "r"(a2), "r"(a3), "r"(b0), "r"(b1))

#define MMA16816H(d, a0, a1, a2, a3, b0, b1)                                 \
    asm volatile("mma.sync.aligned.m16n8k16.row.col.f32.f16.f16.f32 "        \
                 "{%0,%1,%2,%3}, {%4,%5,%6,%7}, {%8,%9}, {%0,%1,%2,%3};"     \
                 : "+f"((d)[0]), "+f"((d)[1]), "+f"((d)[2]), "+f"((d)[3])    \
                 : "r"(a0), "r"(a1), "r"(a2), "r"(a3), "r"(b0), "r"(b1))

#define CP_ASYNC16(sa, g) \
    asm volatile("cp.async.cg.shared.global [%0], [%1], 16;" :: "r"(sa), "l"(g))

__device__ __forceinline__ void split2(float a, float b, uint32_t& hi, uint32_t& lo) {
    __nv_bfloat16 ha = __float2bfloat16(a), hb = __float2bfloat16(b);
    __nv_bfloat16 la = __float2bfloat16(a - __bfloat162float(ha));
    __nv_bfloat16 lb = __float2bfloat16(b - __bfloat162float(hb));
    hi = ((uint32_t)__bfloat16_as_ushort(hb) << 16) | __bfloat16_as_ushort(ha);
    lo = ((uint32_t)__bfloat16_as_ushort(lb) << 16) | __bfloat16_as_ushort(la);
}

__device__ __forceinline__ void split2h(float a, float b, uint32_t& hi, uint32_t& lo) {
    __half ha = __float2half_rn(a), hb = __float2half_rn(b);
    __half la = __float2half_rn(a - __half2float(ha));
    __half lb = __float2half_rn(b - __half2float(hb));
    hi = ((uint32_t)__half_as_ushort(hb) << 16) | __half_as_ushort(ha);
    lo = ((uint32_t)__half_as_ushort(lb) << 16) | __half_as_ushort(la);
}

// ---------------- K0: fp32 x -> fp16 hi/lo ----------------
__global__ void __launch_bounds__(256) split_kernel(const float* __restrict__ xsrc) {
    const size_t i = (size_t)blockIdx.x * 256 + threadIdx.x;   // float4 index
    const float4 v = ((const float4*)xsrc)[i];
    uint32_t h01, l01, h23, l23;
    split2h(v.x, v.y, h01, l01);
    split2h(v.z, v.w, h23, l23);
    *(uint2*)(g_xh16 + 4 * i) = make_uint2(h01, h23);
    *(uint2*)(g_xl16 + 4 * i) = make_uint2(l01, l23);
}

// ---------------- K0b: W transpose -> fp16, all four ----------------
__global__ void __launch_bounds__(256) wsplit_kernel(const float* __restrict__ Wq,
                                                     const float* __restrict__ Wk,
                                                     const float* __restrict__ Wv,
                                                     const float* __restrict__ Wo) {
    __shared__ float t[32][33];
    const int z = blockIdx.z;
    const float* W = (z == 0) ? Wq : (z == 1) ? Wk : (z == 2) ? Wv : Wo;
    const int tx = threadIdx.x & 31, ty = threadIdx.x >> 5;   // 32 x 8
    const int bx = blockIdx.x, by = blockIdx.y;
#pragma unroll
    for (int j = 0; j < 4; j++) {
        int k = by * 32 + ty + j * 8;
        int n = bx * 32 + tx;
        t[ty + j * 8][tx] = W[(size_t)k * Dm + n];
    }
    __syncthreads();
#pragma unroll
    for (int j = 0; j < 4; j++) {
        int n = bx * 32 + ty + j * 8;
        int k = by * 32 + tx;
        g_wt16[(size_t)z * Dm * Dm + (size_t)n * Dm + k] = __float2half_rn(t[tx][ty + j * 8]);
    }
}

// ---------------- K1: 2-pass fp16 GEMM, used for q/k/v projections AND output ----
// 2 stages x 30KB = 60KB smem, 2 CTAs/SM, single sync per k-iter.
#define TROW   80
#define TILE_B (128 * TROW)
#define STG2_B (3 * TILE_B)          // 30720
#define G2SMEM (2 * STG2_B)          // 61440

__device__ __forceinline__ void gemm2p_body(const __half* __restrict__ Ahi,
                                            const __half* __restrict__ Alo,
                                            const __half* __restrict__ B,
                                            float* __restrict__ C,
                                            char* sm, int m0, int n0) {
    const uint32_t smb = smem_u32(sm);
    const int tid = threadIdx.x;

#define LOAD_G(buf, k0)                                                       \
    do {                                                                      \
        uint32_t sb_ = smb + (buf) * STG2_B;                                  \
        _Pragma("unroll")                                                     \
        for (int j_ = 0; j_ < 6; ++j_) {                                      \
            int lin_ = tid + 256 * j_;                                        \
            int tile_ = lin_ >> 9;                                            \
            int idx_ = lin_ & 511;                                            \
            int r_ = idx_ >> 2, c_ = idx_ & 3;                                \
            const __half* gp_ = (tile_ == 0) ? Ahi : (tile_ == 1) ? Alo : B;  \
            int gr_ = (tile_ < 2) ? (m0 + r_) : (n0 + r_);                    \
            CP_ASYNC16(sb_ + tile_ * TILE_B + r_ * TROW + c_ * 16,            \
                       gp_ + (size_t)gr_ * Dm + (k0) + c_ * 8);               \
        }                                                                     \
    } while (0)

    const int lane = tid & 31, w = tid >> 5;
    const int wm = w & 3, wn = w >> 2;
    const int lj = lane >> 3, lm = lane & 7;
    const int arow = wm * 32 + (lj & 1) * 8 + lm;
    const int acho = lj >> 1;
    const int brow = wn * 64 + ((lj & 2) ? 8 : 0) + lm;
    const int bcho = lj & 1;

    float acc[2][8][4];
#pragma unroll
    for (int i = 0; i < 2; i++)
#pragma unroll
        for (int jn = 0; jn < 8; jn++)
#pragma unroll
            for (int r = 0; r < 4; r++) acc[i][jn][r] = 0.f;

    LOAD_G(0, 0);
    asm volatile("cp.async.commit_group;" ::: "memory");

    for (int it = 0; it < 32; ++it) {
        asm volatile("cp.async.wait_group 0;" ::: "memory");
        __syncthreads();
        const int nxt = it + 1;
        if (nxt < 32) LOAD_G(nxt & 1, nxt * 32);
        asm volatile("cp.async.commit_group;" ::: "memory");

        const uint32_t buf = smb + (it & 1) * STG2_B;
#pragma unroll
        for (int ks = 0; ks < 2; ++ks) {
            uint32_t ah[2][4], al[2][4];
#pragma unroll
            for (int i = 0; i < 2; ++i) {
                uint32_t ra = buf + (arow + i * 16) * TROW + (ks * 2 + acho) * 16;
                LDSM4(ah[i][0], ah[i][1], ah[i][2], ah[i][3], ra);
                LDSM4(al[i][0], al[i][1], al[i][2], al[i][3], ra + TILE_B);
            }
#pragma unroll
            for (int g = 0; g < 4; ++g) {
                uint32_t bfr[4];
                uint32_t rb = buf + 2 * TILE_B + (brow + g * 16) * TROW + (ks * 2 + bcho) * 16;
                LDSM4(bfr[0], bfr[1], bfr[2], bfr[3], rb);
#pragma unroll
                for (int i = 0; i < 2; ++i)
#pragma unroll
                    for (int hf = 0; hf < 2; ++hf) {
                        const int jn = g * 2 + hf;
                        MMA16816H(acc[i][jn], ah[i][0], ah[i][1], ah[i][2], ah[i][3],
                                  bfr[hf * 2], bfr[hf * 2 + 1]);
                        MMA16816H(acc[i][jn], al[i][0], al[i][1], al[i][2], al[i][3],
                                  bfr[hf * 2], bfr[hf * 2 + 1]);
                    }
            }
        }
    }

#pragma unroll
    for (int i = 0; i < 2; ++i) {
        const int r0 = m0 + wm * 32 + i * 16 + (lane >> 2);
#pragma unroll
        for (int jn = 0; jn < 8; ++jn) {
            const int cc = n0 + wn * 64 + jn * 8 + 2 * (lane & 3);
            *(float2*)&C[(size_t)r0 * Dm + cc]       = make_float2(acc[i][jn][0], acc[i][jn][1]);
            *(float2*)&C[(size_t)(r0 + 8) * Dm + cc] = make_float2(acc[i][jn][2], acc[i][jn][3]);
        }
    }
#undef LOAD_G
}

__global__ void __launch_bounds__(256, 2) proj_kernel() {
    extern __shared__ char sm[];
    const int z = blockIdx.z;   // 0=q, 1=k, 2=v
    gemm2p_body(g_xh16, g_xl16, g_wt16 + (size_t)z * Dm * Dm,
                g_qkv + (size_t)z * QKV_OFF, sm,
                blockIdx.y * 128, blockIdx.x * 128);
}

__global__ void __launch_bounds__(256, 2) out_kernel(float* __restrict__ Cout) {
    extern __shared__ char sm[];
    gemm2p_body(g_yh16, g_yl16, g_wt16 + (size_t)3 * Dm * Dm,
                Cout, sm, blockIdx.y * 128, blockIdx.x * 128);
}

// ---------------- K2: FAVOR+ features via HMMA + exp epilogue ----------------
#define FA_P 144
#define FW_P 272
#define FA_H 0
#define FA_L (FA_H + 128 * FA_P)
#define FW_H (FA_L + 128 * FA_P)
#define FW_L (FW_H + 64 * FW_P)
#define FSQ  (FW_L + 64 * FW_P)
#define FSM  (FSQ + 512)

__global__ void __launch_bounds__(256) feat_kernel(const float* __restrict__ Wf) {
    extern __shared__ char sm[];
    const uint32_t smb = smem_u32(sm);
    const int tid = threadIdx.x;
    const int bt0 = blockIdx.x * 128, h = blockIdx.y, sel = blockIdx.z;
    const float* src = g_qkv + (size_t)sel * QKV_OFF;

#pragma unroll
    for (int j = 0; j < 8; ++j) {
        int lin = tid + 256 * j;
        int rr = lin >> 4, cc = lin & 15;
        float4 v = *(const float4*)(src + (size_t)(bt0 + rr) * Dm + h * HDm + cc * 4);
        uint32_t h01, l01, h23, l23;
        split2(v.x, v.y, h01, l01);
        split2(v.z, v.w, h23, l23);
        *(uint2*)(sm + FA_H + rr * FA_P + cc * 8) = make_uint2(h01, h23);
        *(uint2*)(sm + FA_L + rr * FA_P + cc * 8) = make_uint2(l01, l23);
    }
#pragma unroll
    for (int j = 0; j < 8; ++j) {
        int lin = tid + 256 * j;
        int rr = lin >> 5, cc = lin & 31;
        float4 v = *(const float4*)(Wf + (size_t)rr * NFm + cc * 4);
        uint32_t h01, l01, h23, l23;
        split2(v.x, v.y, h01, l01);
        split2(v.z, v.w, h23, l23);
        *(uint2*)(sm + FW_H + rr * FW_P + cc * 8) = make_uint2(h01, h23);
        *(uint2*)(sm + FW_L + rr * FW_P + cc * 8) = make_uint2(l01, l23);
    }
    __syncthreads();

    if (tid < 128) {
        float s = 0.f;
#pragma unroll
        for (int d2 = 0; d2 < 32; ++d2) {
            __nv_bfloat162 vh = *(__nv_bfloat162*)(sm + FA_H + tid * FA_P + d2 * 4);
            __nv_bfloat162 vl = *(__nv_bfloat162*)(sm + FA_L + tid * FA_P + d2 * 4);
            float2 fh = __bfloat1622float2(vh), fl = __bfloat1622float2(vl);
            float a = fh.x + fl.x, b = fh.y + fl.y;
            s = fmaf(a, a, fmaf(b, b, s));
        }
        ((float*)(sm + FSQ))[tid] = 0.5f * s;
    }
    __syncthreads();

    const int l = tid & 31, w = tid >> 5;
    const int lj = l >> 3, lm = l & 7;
    const int arow = w * 16 + (lj & 1) * 8 + lm;
    const int acho = lj >> 1;
    const int m = l >> 3, r = l & 7;
    const int sB = (m & 1) ? 8 : 0, eB = (m & 2) ? 8 : 0;

    float acc[16][4];
#pragma unroll
    for (int nb = 0; nb < 16; ++nb)
#pragma unroll
        for (int q = 0; q < 4; ++q) acc[nb][q] = 0.f;

#pragma unroll
    for (int ks = 0; ks < 4; ++ks) {
        uint32_t ah[4], al[4];
        uint32_t ad = smb + FA_H + arow * FA_P + (ks * 2 + acho) * 16;
        LDSM4(ah[0], ah[1], ah[2], ah[3], ad);
        LDSM4(al[0], al[1], al[2], al[3], ad + (FA_L - FA_H));
#pragma unroll
        for (int fg = 0; fg < 8; ++fg) {
            uint32_t bhf[4], blf[4];
            uint32_t bd = smb + FW_H + (ks * 16 + sB + r) * FW_P + (fg * 16 + eB) * 2;
            LDSM4T(bhf[0], bhf[1], bhf[2], bhf[3], bd);
            LDSM4T(blf[0], blf[1], blf[2], blf[3], bd + (FW_L - FW_H));
#pragma unroll
            for (int hf = 0; hf < 2; ++hf) {
                const int nb = fg * 2 + hf;
                MMA16816(acc[nb], ah[0], ah[1], ah[2], ah[3], bhf[hf * 2], bhf[hf * 2 + 1]);
                MMA16816(acc[nb], ah[0], ah[1], ah[2], ah[3], blf[hf * 2], blf[hf * 2 + 1]);
                MMA16816(acc[nb], al[0], al[1], al[2], al[3], bhf[hf * 2], bhf[hf * 2 + 1]);
            }
        }
    }

    float* dst = sel ? g_kp : g_qp;
    const int b = bt0 >> 11;
    const int bh = b * Hh + h;
    const int trow0 = w * 16 + (l >> 2);
    const float* sqp = (const float*)(sm + FSQ);
    const float sq0 = sqp[trow0], sq1 = sqp[trow0 + 8];
    const int t0 = (bt0 & 2047) + trow0;
    float* d0 = dst + ((size_t)bh * Tt + t0) * NFm;
    float* d1 = dst + ((size_t)bh * Tt + t0 + 8) * NFm;
#pragma unroll
    for (int nb = 0; nb < 16; ++nb) {
        const int f = nb * 8 + (l & 3) * 2;
        *(float2*)(d0 + f) = make_float2(expf(acc[nb][0] - sq0) * INV_SQRT_NF,
                                         expf(acc[nb][1] - sq0) * INV_SQRT_NF);
        *(float2*)(d1 + f) = make_float2(expf(acc[nb][2] - sq1) * INV_SQRT_NF,
                                         expf(acc[nb][3] - sq1) * INV_SQRT_NF);
    }
}

// ---------------- K3: chunk_sum via HMMA ----------------
#define PKb 272
#define PVb 144
#define CS_KH 0
#define CS_KL (CS_KH + 128 * PKb)
#define CS_VH (CS_KL + 128 * PKb)
#define CS_VL (CS_VH + 128 * PVb)
#define SMEM3 (CS_VL + 128 * PVb)

__global__ void __launch_bounds__(256, 1) chunk_sum_kernel() {
    extern __shared__ char sm[];
    const uint32_t smb = smem_u32(sm);
    const int c = blockIdx.x, bh = blockIdx.y;
    const int b = bh >> 4, h = bh & 15;
    const int tid = threadIdx.x;
    const float* GV = g_qkv + 2 * QKV_OFF;
    const size_t kbase = ((size_t)bh * Tt + c * CHK) * NFm;
    const size_t vbase = ((size_t)(b * Tt + c * CHK)) * Dm + h * HDm;

#pragma unroll
    for (int j = 0; j < 16; ++j) {
        int lin = tid + 256 * j;
        int rr = lin >> 5, cc = lin & 31;
        float4 v = *(const float4*)(g_kp + kbase + (size_t)rr * NFm + cc * 4);
        uint32_t h01, l01, h23, l23;
        split2(v.x, v.y, h01, l01);
        split2(v.z, v.w, h23, l23);
        *(uint2*)(sm + CS_KH + rr * PKb + cc * 8) = make_uint2(h01, h23);
        *(uint2*)(sm + CS_KL + rr * PKb + cc * 8) = make_uint2(l01, l23);
    }
#pragma unroll
    for (int j = 0; j < 8; ++j) {
        int lin = tid + 256 * j;
        int rr = lin >> 4, cc = lin & 15;
        float4 v = *(const float4*)(GV + vbase + (size_t)rr * Dm + cc * 4);
        uint32_t h01, l01, h23, l23;
        split2(v.x, v.y, h01, l01);
        split2(v.z, v.w, h23, l23);
        *(uint2*)(sm + CS_VH + rr * PVb + cc * 8) = make_uint2(h01, h23);
        *(uint2*)(sm + CS_VL + rr * PVb + cc * 8) = make_uint2(l01, l23);
    }
    __syncthreads();

    const int l = tid & 31, w = tid >> 5;
    const int m = l >> 3, r = l & 7;
    const int f0w = (w & 3) * 32, e0w = (w >> 2) * 32;
    const int sA = (m & 2) ? 8 : 0, fA = (m & 1) ? 8 : 0;
    const int sB = (m & 1) ? 8 : 0, eB = (m & 2) ? 8 : 0;

    float acc[2][4][4];
#pragma unroll
    for (int i = 0; i < 2; i++)
#pragma unroll
        for (int jn = 0; jn < 4; jn++)
#pragma unroll
            for (int q = 0; q < 4; q++) acc[i][jn][q] = 0.f;

    for (int s0 = 0; s0 < 128; s0 += 16) {
        uint32_t ah[2][4], al[2][4], bhf[2][4], blf[2][4];
#pragma unroll
        for (int i = 0; i < 2; ++i) {
            uint32_t ad = smb + CS_KH + (s0 + sA + r) * PKb + (f0w + i * 16 + fA) * 2;
            LDSM4T(ah[i][0], ah[i][1], ah[i][2], ah[i][3], ad);
            LDSM4T(al[i][0], al[i][1], al[i][2], al[i][3], ad + (CS_KL - CS_KH));
        }
#pragma unroll
        for (int j2 = 0; j2 < 2; ++j2) {
            uint32_t ad = smb + CS_VH + (s0 + sB + r) * PVb + (e0w + j2 * 16 + eB) * 2;
            LDSM4T(bhf[j2][0], bhf[j2][1], bhf[j2][2], bhf[j2][3], ad);
            LDSM4T(blf[j2][0], blf[j2][1], blf[j2][2], blf[j2][3], ad + (CS_VL - CS_VH));
        }
#pragma unroll
        for (int i = 0; i < 2; ++i)
#pragma unroll
            for (int jn = 0; jn < 4; ++jn) {
                const int j2 = jn >> 1, o = (jn & 1) * 2;
                MMA16816(acc[i][jn], ah[i][0], ah[i][1], ah[i][2], ah[i][3],
                         bhf[j2][o], bhf[j2][o + 1]);
                MMA16816(acc[i][jn], ah[i][0], ah[i][1], ah[i][2], ah[i][3],
                         blf[j2][o], blf[j2][o + 1]);
                MMA16816(acc[i][jn], al[i][0], al[i][1], al[i][2], al[i][3],
                         bhf[j2][o], bhf[j2][o + 1]);
            }
    }

    const size_t Sbase = ((size_t)bh * NCH + c) * (NFm * HDm);
#pragma unroll
    for (int i = 0; i < 2; ++i) {
        const int fr = f0w + i * 16 + (l >> 2);
#pragma unroll
        for (int jn = 0; jn < 4; ++jn) {
            const int ec = e0w + jn * 8 + (l & 3) * 2;
            *(float2*)(g_S + Sbase + (size_t)fr * HDm + ec) =
                make_float2(acc[i][jn][0], acc[i][jn][1]);
            *(float2*)(g_S + Sbase + (size_t)(fr + 8) * HDm + ec) =
                make_float2(acc[i][jn][2], acc[i][jn][3]);
        }
    }
    if (tid < 128) {
        float zz = 0.f;
        for (int s = 0; s < 128; ++s) zz += g_kp[kbase + (size_t)s * NFm + tid];
        g_z[((size_t)bh * NCH + c) * NFm + tid] = zz;
    }
}

// ---------------- K4: exclusive prefix over chunks ----------------
__global__ void __launch_bounds__(256) prefix_kernel() {   // grid (32, BH)
    const int bh = blockIdx.y, seg = blockIdx.x;
    const int idx = seg * 256 + threadIdx.x;
    float v[NCH];
    const size_t base = (size_t)bh * NCH * NFm * HDm + idx;
#pragma unroll
    for (int c = 0; c < NCH; ++c) v[c] = g_S[base + (size_t)c * NFm * HDm];
    float acc = 0.f;
#pragma unroll
    for (int c = 0; c < NCH; ++c) { float cur = v[c]; v[c] = acc; acc += cur; }
#pragma unroll
    for (int c = 0; c < NCH; ++c) g_S[base + (size_t)c * NFm * HDm] = v[c];
    if (seg == 0 && threadIdx.x < NFm) {
        float zv[NCH];
        const size_t zb = (size_t)bh * NCH * NFm + threadIdx.x;
#pragma unroll
        for (int c = 0; c < NCH; ++c) zv[c] = g_z[zb + c * NFm];
        float az = 0.f;
#pragma unroll
        for (int c = 0; c < NCH; ++c) { float cur = zv[c]; zv[c] = az; az += cur; }
#pragma unroll
        for (int c = 0; c < NCH; ++c) g_z[zb + c * NFm] = zv[c];
    }
}

// ---------------- K5: chunk_out via HMMA (writes y as fp16 hi/lo) ----------------
#define CO_QH 0
#define CO_QL (CO_QH + 128 * PKb)
#define CO_KH (CO_QL + 128 * PKb)
#define CO_KL (CO_KH + 128 * PKb)
#define CO_VH (CO_KL + 128 * PKb)
#define CO_VL (CO_VH + 128 * PVb)
#define CO_SH (CO_VL + 128 * PVb)
#define CO_SL (CO_SH + 128 * PVb)
#define CO_Z  (CO_SL + 128 * PVb)
#define CO_D  (CO_Z + 512)
#define SMEM5 (CO_D + 512)

__global__ void __launch_bounds__(256, 1) chunk_out_kernel() {
    extern __shared__ char sm[];
    const uint32_t smb = smem_u32(sm);
    const int c = blockIdx.x, bh = blockIdx.y;
    const int b = bh >> 4, h = bh & 15;
    const int tid = threadIdx.x;
    const float* GV = g_qkv + 2 * QKV_OFF;
    const size_t qbase = ((size_t)bh * Tt + c * CHK) * NFm;
    const size_t vbase = ((size_t)(b * Tt + c * CHK)) * Dm + h * HDm;
    const size_t Sbase = ((size_t)bh * NCH + c) * (NFm * HDm);

#pragma unroll
    for (int j = 0; j < 16; ++j) {
        int lin = tid + 256 * j;
        int rr = lin >> 5, cc = lin & 31;
        float4 q4 = *(const float4*)(g_qp + qbase + (size_t)rr * NFm + cc * 4);
        float4 k4 = *(const float4*)(g_kp + qbase + (size_t)rr * NFm + cc * 4);
        uint32_t h01, l01, h23, l23;
        split2(q4.x, q4.y, h01, l01);
        split2(q4.z, q4.w, h23, l23);
        *(uint2*)(sm + CO_QH + rr * PKb + cc * 8) = make_uint2(h01, h23);
        *(uint2*)(sm + CO_QL + rr * PKb + cc * 8) = make_uint2(l01, l23);
        split2(k4.x, k4.y, h01, l01);
        split2(k4.z, k4.w, h23, l23);
        *(uint2*)(sm + CO_KH + rr * PKb + cc * 8) = make_uint2(h01, h23);
        *(uint2*)(sm + CO_KL + rr * PKb + cc * 8) = make_uint2(l01, l23);
    }
#pragma unroll
    for (int j = 0; j < 8; ++j) {
        int lin = tid + 256 * j;
        int rr = lin >> 4, cc = lin & 15;
        float4 v4 = *(const float4*)(GV + vbase + (size_t)rr * Dm + cc * 4);
        uint32_t h01, l01, h23, l23;
        split2(v4.x, v4.y, h01, l01);
        split2(v4.z, v4.w, h23, l23);
        *(uint2*)(sm + CO_VH + rr * PVb + cc * 8) = make_uint2(h01, h23);
        *(uint2*)(sm + CO_VL + rr * PVb + cc * 8) = make_uint2(l01, l23);
        float4 s4 = *(const float4*)(g_S + Sbase + (size_t)rr * HDm + cc * 4);
        split2(s4.x, s4.y, h01, l01);
        split2(s4.z, s4.w, h23, l23);
        *(uint2*)(sm + CO_SH + rr * PVb + cc * 8) = make_uint2(h01, h23);
        *(uint2*)(sm + CO_SL + rr * PVb + cc * 8) = make_uint2(l01, l23);
    }
    if (tid < 128)
        ((float*)(sm + CO_Z))[tid] = g_z[((size_t)bh * NCH + c) * NFm + tid];
    __syncthreads();

    const int l = tid & 31, w = tid >> 5;
    const int wm = w & 3, wn = w >> 2;
    const int lj = l >> 3, lm = l & 7;
    const int m = l >> 3, r = l & 7;
    const int arow = wm * 32 + (lj & 1) * 8 + lm;
    const int acho = lj >> 1;
    const int brow = ((lj & 2) ? 8 : 0) + lm;
    const int bcho = lj & 1;
    const int sB = (m & 1) ? 8 : 0, eB = (m & 2) ? 8 : 0;

    float accA[2][8][4];
#pragma unroll
    for (int i = 0; i < 2; i++)
#pragma unroll
        for (int jn = 0; jn < 8; jn++)
#pragma unroll
            for (int q = 0; q < 4; q++) accA[i][jn][q] = 0.f;

    for (int f0 = 0; f0 < 128; f0 += 16) {
        uint32_t qh[2][4], ql[2][4];
#pragma unroll
        for (int i = 0; i < 2; ++i) {
            uint32_t ad = smb + CO_QH + (arow + i * 16) * PKb + (f0 / 8 + acho) * 16;
            LDSM4(qh[i][0], qh[i][1], qh[i][2], qh[i][3], ad);
            LDSM4(ql[i][0], ql[i][1], ql[i][2], ql[i][3], ad + (CO_QL - CO_QH));
        }
#pragma unroll
        for (int g = 0; g < 4; ++g) {
            uint32_t kh[4], kl[4];
            uint32_t ad = smb + CO_KH + (wn * 64 + brow + g * 16) * PKb + (f0 / 8 + bcho) * 16;
            LDSM4(kh[0], kh[1], kh[2], kh[3], ad);
            LDSM4(kl[0], kl[1], kl[2], kl[3], ad + (CO_KL - CO_KH));
#pragma unroll
            for (int i = 0; i < 2; ++i)
#pragma unroll
                for (int hf = 0; hf < 2; ++hf) {
                    const int jn = g * 2 + hf;
                    MMA16816(accA[i][jn], qh[i][0], qh[i][1], qh[i][2], qh[i][3],
                             kh[hf * 2], kh[hf * 2 + 1]);
                    MMA16816(accA[i][jn], qh[i][0], qh[i][1], qh[i][2], qh[i][3],
                             kl[hf * 2], kl[hf * 2 + 1]);
                    MMA16816(accA[i][jn], ql[i][0], ql[i][1], ql[i][2], ql[i][3],
                             kh[hf * 2], kh[hf * 2 + 1]);
                }
        }
    }
    __syncthreads();

#pragma unroll
    for (int i = 0; i < 2; ++i) {
        const int tr = wm * 32 + i * 16 + (l >> 2);
#pragma unroll
        for (int jn = 0; jn < 8; ++jn) {
            const int sc = wn * 64 + jn * 8 + (l & 3) * 2;
            float v0 = (sc     <= tr) ? accA[i][jn][0] : 0.f;
            float v1 = (sc + 1 <= tr) ? accA[i][jn][1] : 0.f;
            uint32_t hi, lo;
            split2(v0, v1, hi, lo);
            *(uint32_t*)(sm + CO_KH + tr * PKb + sc * 2) = hi;
            *(uint32_t*)(sm + CO_KL + tr * PKb + sc * 2) = lo;
            const int tr8 = tr + 8;
            v0 = (sc     <= tr8) ? accA[i][jn][2] : 0.f;
            v1 = (sc + 1 <= tr8) ? accA[i][jn][3] : 0.f;
            split2(v0, v1, hi, lo);
            *(uint32_t*)(sm + CO_KH + tr8 * PKb + sc * 2) = hi;
            *(uint32_t*)(sm + CO_KL + tr8 * PKb + sc * 2) = lo;
        }
    }
    __syncthreads();

    if (tid < 128) {
        const int t = tid;
        float den = EPSf;
        const float* zp = (const float*)(sm + CO_Z);
#pragma unroll 8
        for (int f2 = 0; f2 < 64; ++f2) {
            __nv_bfloat162 qh2 = *(__nv_bfloat162*)(sm + CO_QH + t * PKb + f2 * 4);
            __nv_bfloat162 ql2 = *(__nv_bfloat162*)(sm + CO_QL + t * PKb + f2 * 4);
            float2 fh = __bfloat1622float2(qh2), fl = __bfloat1622float2(ql2);
            den += (fh.x + fl.x) * zp[2 * f2] + (fh.y + fl.y) * zp[2 * f2 + 1];
        }
#pragma unroll 8
        for (int s2 = 0; s2 < 64; ++s2) {
            __nv_bfloat162 ah2 = *(__nv_bfloat162*)(sm + CO_KH + t * PKb + s2 * 4);
            __nv_bfloat162 al2 = *(__nv_bfloat162*)(sm + CO_KL + t * PKb + s2 * 4);
            float2 fa = __bfloat1622float2(ah2), fb = __bfloat1622float2(al2);
            den += fa.x + fa.y + fb.x + fb.y;
        }
        ((float*)(sm + CO_D))[t] = 1.f / den;
    }
    __syncthreads();

    const int e0w = wn * 32;
    float accY[2][4][4];
#pragma unroll
    for (int i = 0; i < 2; i++)
#pragma unroll
        for (int jn = 0; jn < 4; jn++)
#pragma unroll
            for (int q = 0; q < 4; q++) accY[i][jn][q] = 0.f;

    for (int s0 = 0; s0 < 128; s0 += 16) {
        uint32_t aah[2][4], aal[2][4], vh[2][4], vl[2][4];
#pragma unroll
        for (int i = 0; i < 2; ++i) {
            uint32_t ad = smb + CO_KH + (arow + i * 16) * PKb + (s0 / 8 + acho) * 16;
            LDSM4(aah[i][0], aah[i][1], aah[i][2], aah[i][3], ad);
            LDSM4(aal[i][0], aal[i][1], aal[i][2], aal[i][3], ad + (CO_KL - CO_KH));
        }
#pragma unroll
        for (int j2 = 0; j2 < 2; ++j2) {
            uint32_t ad = smb + CO_VH + (s0 + sB + r) * PVb + (e0w + j2 * 16 + eB) * 2;
            LDSM4T(vh[j2][0], vh[j2][1], vh[j2][2], vh[j2][3], ad);
            LDSM4T(vl[j2][0], vl[j2][1], vl[j2][2], vl[j2][3], ad + (CO_VL - CO_VH));
        }
#pragma unroll
        for (int i = 0; i < 2; ++i)
#pragma unroll
            for (int jn = 0; jn < 4; ++jn) {
                const int j2 = jn >> 1, o = (jn & 1) * 2;
                MMA16816(accY[i][jn], aah[i][0], aah[i][1], aah[i][2], aah[i][3],
                         vh[j2][o], vh[j2][o + 1]);
                MMA16816(accY[i][jn], aah[i][0], aah[i][1], aah[i][2], aah[i][3],
                         vl[j2][o], vl[j2][o + 1]);
                MMA16816(accY[i][jn], aal[i][0], aal[i][1], aal[i][2], aal[i][3],
                         vh[j2][o], vh[j2][o + 1]);
            }
    }
    for (int f0 = 0; f0 < 128; f0 += 16) {
        uint32_t qh[2][4], ql[2][4], sh[2][4], sl[2][4];
#pragma unroll
        for (int i = 0; i < 2; ++i) {
            uint32_t ad = smb + CO_QH + (arow + i * 16) * PKb + (f0 / 8 + acho) * 16;
            LDSM4(qh[i][0], qh[i][1], qh[i][2], qh[i][3], ad);
            LDSM4(ql[i][0], ql[i][1], ql[i][2], ql[i][3], ad + (CO_QL - CO_QH));
        }
#pragma unroll
        for (int j2 = 0; j2 < 2; ++j2) {
            uint32_t ad = smb + CO_SH + (f0 + sB + r) * PVb + (e0w + j2 * 16 + eB) * 2;
            LDSM4T(sh[j2][0], sh[j2][1], sh[j2][2], sh[j2][3], ad);
            LDSM4T(sl[j2][0], sl[j2][1], sl[j2][2], sl[j2][3], ad + (CO_SL - CO_SH));
        }
#pragma unroll
        for (int i = 0; i < 2; ++i)
#pragma unroll
            for (int jn = 0; jn < 4; ++jn) {
                const int j2 = jn >> 1, o = (jn & 1) * 2;
                MMA16816(accY[i][jn], qh[i][0], qh[i][1], qh[i][2], qh[i][3],
                         sh[j2][o], sh[j2][o + 1]);
                MMA16816(accY[i][jn], qh[i][0], qh[i][1], qh[i][2], qh[i][3],
                         sl[j2][o], sl[j2][o + 1]);
                MMA16816(accY[i][jn], ql[i][0], ql[i][1], ql[i][2], ql[i][3],
                         sh[j2][o], sh[j2][o + 1]);
            }
    }

    const float* dv = (const float*)(sm + CO_D);
#pragma unroll
    for (int i = 0; i < 2; ++i) {
        const int tr = wm * 32 + i * 16 + (l >> 2);
        const float d0 = dv[tr], d1 = dv[tr + 8];
#pragma unroll
        for (int jn = 0; jn < 4; ++jn) {
            const int ec = e0w + jn * 8 + (l & 3) * 2;
            size_t o0 = ((size_t)(b * Tt + c * CHK + tr)) * Dm + h * HDm + ec;
            size_t o1 = ((size_t)(b * Tt + c * CHK + tr + 8)) * Dm + h * HDm + ec;
            uint32_t hi, lo;
            split2h(accY[i][jn][0] * d0, accY[i][jn][1] * d0, hi, lo);
            *(uint32_t*)(g_yh16 + o0) = hi;
            *(uint32_t*)(g_yl16 + o0) = lo;
            split2h(accY[i][jn][2] * d1, accY[i][jn][3] * d1, hi, lo);
            *(uint32_t*)(g_yh16 + o1) = hi;
            *(uint32_t*)(g_yl16 + o1) = lo;
        }
    }
}

// ---------------------------------------------------------------------------
extern "C" void kernel_launch(void* const* d_in, const int* in_sizes, int n_in,
                              void* d_out, int out_size) {
    const float* x  = (const float*)d_in[0];
    const float* Wq = (const float*)d_in[1];
    const float* Wk = (const float*)d_in[2];
    const float* Wv = (const float*)d_in[3];
    const float* Wo = (const float*)d_in[4];
    const float* Wf = (const float*)d_in[5];
    float* out = (float*)d_out;

    cudaFuncSetAttribute(proj_kernel,      cudaFuncAttributeMaxDynamicSharedMemorySize, G2SMEM);
    cudaFuncSetAttribute(out_kernel,       cudaFuncAttributeMaxDynamicSharedMemorySize, G2SMEM);
    cudaFuncSetAttribute(feat_kernel,      cudaFuncAttributeMaxDynamicSharedMemorySize, FSM);
    cudaFuncSetAttribute(chunk_sum_kernel, cudaFuncAttributeMaxDynamicSharedMemorySize, SMEM3);
    cudaFuncSetAttribute(chunk_out_kernel, cudaFuncAttributeMaxDynamicSharedMemorySize, SMEM5);

    split_kernel<<<(MR * Dm / 4) / 256, 256>>>(x);
    wsplit_kernel<<<dim3(32, 32, 4), 256>>>(Wq, Wk, Wv, Wo);
    proj_kernel<<<dim3(8, 64, 3), 256, G2SMEM>>>();             // q, k, v — all fp16 2-pass
    feat_kernel<<<dim3(MR / 128, Hh, 2), 256, FSM>>>(Wf);
    chunk_sum_kernel<<<dim3(NCH, BH), 256, SMEM3>>>();
    prefix_kernel<<<dim3(32, BH), 256>>>();
    chunk_out_kernel<<<dim3(NCH, BH), 256, SMEM5>>>();
    out_kernel<<<dim3(8, 64), 256, G2SMEM>>>(out);
}

// round 14
// speedup vs baseline: 3.8742x; 1.0063x over previous
#include <cuda_runtime.h>
#include <cuda_bf16.h>
#include <cuda_fp16.h>
#include <math.h>
#include <stdint.h>

// ---------------- problem constants ----------------
#define Bb   4
#define Tt   2048
#define Dm   1024
#define Hh   16
#define HDm  64
#define NFm  128
#define CHK  128
#define NCH  16
#define BH   64
#define MR   8192
#define EPSf 1e-6f
#define INV_SQRT_NF 0.08838834764831845f

#define QKV_OFF ((size_t)MR * Dm)

// ---------------- scratch ----------------
__device__ float g_qkv[3 * (size_t)MR * Dm];   // q | k | v
__device__ float g_qp [(size_t)BH * Tt * NFm];
__device__ float g_kp [(size_t)BH * Tt * NFm];
__device__ float g_S  [(size_t)BH * NCH * NFm * HDm];
__device__ float g_z  [(size_t)BH * NCH * NFm];

__device__ __half g_xh16[(size_t)MR * Dm], g_xl16[(size_t)MR * Dm];   // x fp16 split
__device__ __half g_yh16[(size_t)MR * Dm], g_yl16[(size_t)MR * Dm];   // y fp16 split
__device__ __half g_wt16[4 * (size_t)Dm * Dm];                        // Wq,Wk,Wv,Wo ^T fp16

// ---------------- helpers ----------------
__device__ __forceinline__ uint32_t smem_u32(const void* p) {
    uint32_t a;
    asm("{ .reg .u64 t; cvta.to.shared.u64 t, %1; cvt.u32.u64 %0, t; }" : "=r"(a) : "l"(p));
    return a;
}

#define LDSM4(r0, r1, r2, r3, addr)                                          \
    asm volatile("ldmatrix.sync.aligned.m8n8.x4.shared.b16 {%0,%1,%2,%3}, [%4];" \
                 : "=r"(r0), "=r"(r1), "=r"(r2), "=r"(r3) : "r"(addr))

#define LDSM4T(r0, r1, r2, r3, addr)                                         \
    asm volatile("ldmatrix.sync.aligned.m8n8.x4.trans.shared.b16 {%0,%1,%2,%3}, [%4];" \
                 : "=r"(r0), "=r"(r1), "=r"(r2), "=r"(r3) : "r"(addr))

#define MMA16816(d, a0, a1, a2, a3, b0, b1)                                  \
    asm volatile("mma.sync.aligned.m16n8k16.row.col.f32.bf16.bf16.f32 "      \
                 "{%0,%1,%2,%3}, {%4,%5,%6,%7}, {%8,%9}, {%0,%1,%2,%3};"     \
                 : "+f"((d)[0]), "+f"((d)[1]), "+f"((d)[2]), "+f"((d)[3])    \
                 : "r"(a0), "r"(a1), "r"(a2), "r"(a3), "r"(b0), "r"(b1))

#define MMA16816H(d, a0, a1, a2, a3, b0, b1)                                 \
    asm volatile("mma.sync.aligned.m16n8k16.row.col.f32.f16.f16.f32 "        \
                 "{%0,%1,%2,%3}, {%4,%5,%6,%7}, {%8,%9}, {%0,%1,%2,%3};"     \
                 : "+f"((d)[0]), "+f"((d)[1]), "+f"((d)[2]), "+f"((d)[3])    \
                 : "r"(a0), "r"(a1), "r"(a2), "r"(a3), "r"(b0), "r"(b1))

#define CP_ASYNC16(sa, g) \
    asm volatile("cp.async.cg.shared.global [%0], [%1], 16;" :: "r"(sa), "l"(g))

__device__ __forceinline__ void split2(float a, float b, uint32_t& hi, uint32_t& lo) {
    __nv_bfloat16 ha = __float2bfloat16(a), hb = __float2bfloat16(b);
    __nv_bfloat16 la = __float2bfloat16(a - __bfloat162float(ha));
    __nv_bfloat16 lb = __float2bfloat16(b - __bfloat162float(hb));
    hi = ((uint32_t)__bfloat16_as_ushort(hb) << 16) | __bfloat16_as_ushort(ha);
    lo = ((uint32_t)__bfloat16_as_ushort(lb) << 16) | __bfloat16_as_ushort(la);
}

__device__ __forceinline__ void split2h(float a, float b, uint32_t& hi, uint32_t& lo) {
    __half ha = __float2half_rn(a), hb = __float2half_rn(b);
    __half la = __float2half_rn(a - __half2float(ha));
    __half lb = __float2half_rn(b - __half2float(hb));
    hi = ((uint32_t)__half_as_ushort(hb) << 16) | __half_as_ushort(ha);
    lo = ((uint32_t)__half_as_ushort(lb) << 16) | __half_as_ushort(la);
}

// ---------------- K0: fp32 x -> fp16 hi/lo ----------------
__global__ void __launch_bounds__(256) split_kernel(const float* __restrict__ xsrc) {
    const size_t i = (size_t)blockIdx.x * 256 + threadIdx.x;   // float4 index
    const float4 v = ((const float4*)xsrc)[i];
    uint32_t h01, l01, h23, l23;
    split2h(v.x, v.y, h01, l01);
    split2h(v.z, v.w, h23, l23);
    *(uint2*)(g_xh16 + 4 * i) = make_uint2(h01, h23);
    *(uint2*)(g_xl16 + 4 * i) = make_uint2(l01, l23);
}

// ---------------- K0b: W transpose -> fp16, all four ----------------
__global__ void __launch_bounds__(256) wsplit_kernel(const float* __restrict__ Wq,
                                                     const float* __restrict__ Wk,
                                                     const float* __restrict__ Wv,
                                                     const float* __restrict__ Wo) {
    __shared__ float t[32][33];
    const int z = blockIdx.z;
    const float* W = (z == 0) ? Wq : (z == 1) ? Wk : (z == 2) ? Wv : Wo;
    const int tx = threadIdx.x & 31, ty = threadIdx.x >> 5;   // 32 x 8
    const int bx = blockIdx.x, by = blockIdx.y;
#pragma unroll
    for (int j = 0; j < 4; j++) {
        int k = by * 32 + ty + j * 8;
        int n = bx * 32 + tx;
        t[ty + j * 8][tx] = W[(size_t)k * Dm + n];
    }
    __syncthreads();
#pragma unroll
    for (int j = 0; j < 4; j++) {
        int n = bx * 32 + ty + j * 8;
        int k = by * 32 + tx;
        g_wt16[(size_t)z * Dm * Dm + (size_t)n * Dm + k] = __float2half_rn(t[tx][ty + j * 8]);
    }
}

// ---------------- K1: 2-pass fp16 GEMM (q/k/v projections AND output) ----------
// 2 stages x 30KB = 60KB smem, 2 CTAs/SM, single sync per k-iter.
// MMA issue order: per B-group, all 4 hi-pass MMAs then all 4 lo-pass
// (same-accumulator distance 4 instead of 1 — breaks HMMA RAW chains).
#define TROW   80
#define TILE_B (128 * TROW)
#define STG2_B (3 * TILE_B)          // 30720
#define G2SMEM (2 * STG2_B)          // 61440

__device__ __forceinline__ void gemm2p_body(const __half* __restrict__ Ahi,
                                            const __half* __restrict__ Alo,
                                            const __half* __restrict__ B,
                                            float* __restrict__ C,
                                            char* sm, int m0, int n0) {
    const uint32_t smb = smem_u32(sm);
    const int tid = threadIdx.x;

#define LOAD_G(buf, k0)                                                       \
    do {                                                                      \
        uint32_t sb_ = smb + (buf) * STG2_B;                                  \
        _Pragma("unroll")                                                     \
        for (int j_ = 0; j_ < 6; ++j_) {                                      \
            int lin_ = tid + 256 * j_;                                        \
            int tile_ = lin_ >> 9;                                            \
            int idx_ = lin_ & 511;                                            \
            int r_ = idx_ >> 2, c_ = idx_ & 3;                                \
            const __half* gp_ = (tile_ == 0) ? Ahi : (tile_ == 1) ? Alo : B;  \
            int gr_ = (tile_ < 2) ? (m0 + r_) : (n0 + r_);                    \
            CP_ASYNC16(sb_ + tile_ * TILE_B + r_ * TROW + c_ * 16,            \
                       gp_ + (size_t)gr_ * Dm + (k0) + c_ * 8);               \
        }                                                                     \
    } while (0)

    const int lane = tid & 31, w = tid >> 5;
    const int wm = w & 3, wn = w >> 2;
    const int lj = lane >> 3, lm = lane & 7;
    const int arow = wm * 32 + (lj & 1) * 8 + lm;
    const int acho = lj >> 1;
    const int brow = wn * 64 + ((lj & 2) ? 8 : 0) + lm;
    const int bcho = lj & 1;

    float acc[2][8][4];
#pragma unroll
    for (int i = 0; i < 2; i++)
#pragma unroll
        for (int jn = 0; jn < 8; jn++)
#pragma unroll
            for (int r = 0; r < 4; r++) acc[i][jn][r] = 0.f;

    LOAD_G(0, 0);
    asm volatile("cp.async.commit_group;" ::: "memory");

    for (int it = 0; it < 32; ++it) {
        asm volatile("cp.async.wait_group 0;" ::: "memory");
        __syncthreads();
        const int nxt = it + 1;
        if (nxt < 32) LOAD_G(nxt & 1, nxt * 32);
        asm volatile("cp.async.commit_group;" ::: "memory");

        const uint32_t buf = smb + (it & 1) * STG2_B;
#pragma unroll
        for (int ks = 0; ks < 2; ++ks) {
            uint32_t ah[2][4], al[2][4];
#pragma unroll
            for (int i = 0; i < 2; ++i) {
                uint32_t ra = buf + (arow + i * 16) * TROW + (ks * 2 + acho) * 16;
                LDSM4(ah[i][0], ah[i][1], ah[i][2], ah[i][3], ra);
                LDSM4(al[i][0], al[i][1], al[i][2], al[i][3], ra + TILE_B);
            }
#pragma unroll
            for (int g = 0; g < 4; ++g) {
                uint32_t bfr[4];
                uint32_t rb = buf + 2 * TILE_B + (brow + g * 16) * TROW + (ks * 2 + bcho) * 16;
                LDSM4(bfr[0], bfr[1], bfr[2], bfr[3], rb);
                // hi pass: 4 MMAs, all distinct accumulators
#pragma unroll
                for (int i = 0; i < 2; ++i)
#pragma unroll
                    for (int hf = 0; hf < 2; ++hf)
                        MMA16816H(acc[i][g * 2 + hf], ah[i][0], ah[i][1], ah[i][2], ah[i][3],
                                  bfr[hf * 2], bfr[hf * 2 + 1]);
                // lo pass
#pragma unroll
                for (int i = 0; i < 2; ++i)
#pragma unroll
                    for (int hf = 0; hf < 2; ++hf)
                        MMA16816H(acc[i][g * 2 + hf], al[i][0], al[i][1], al[i][2], al[i][3],
                                  bfr[hf * 2], bfr[hf * 2 + 1]);
            }
        }
    }

#pragma unroll
    for (int i = 0; i < 2; ++i) {
        const int r0 = m0 + wm * 32 + i * 16 + (lane >> 2);
#pragma unroll
        for (int jn = 0; jn < 8; ++jn) {
            const int cc = n0 + wn * 64 + jn * 8 + 2 * (lane & 3);
            *(float2*)&C[(size_t)r0 * Dm + cc]       = make_float2(acc[i][jn][0], acc[i][jn][1]);
            *(float2*)&C[(size_t)(r0 + 8) * Dm + cc] = make_float2(acc[i][jn][2], acc[i][jn][3]);
        }
    }
#undef LOAD_G
}

__global__ void __launch_bounds__(256, 2) proj_kernel() {
    extern __shared__ char sm[];
    const int z = blockIdx.z;   // 0=q, 1=k, 2=v
    gemm2p_body(g_xh16, g_xl16, g_wt16 + (size_t)z * Dm * Dm,
                g_qkv + (size_t)z * QKV_OFF, sm,
                blockIdx.y * 128, blockIdx.x * 128);
}

__global__ void __launch_bounds__(256, 2) out_kernel(float* __restrict__ Cout) {
    extern __shared__ char sm[];
    gemm2p_body(g_yh16, g_yl16, g_wt16 + (size_t)3 * Dm * Dm,
                Cout, sm, blockIdx.y * 128, blockIdx.x * 128);
}

// ---------------- K2: FAVOR+ features via HMMA + exp epilogue ----------------
// fg processed in pairs; pass-outer MMA order (same-acc distance 4).
#define FA_P 144
#define FW_P 272
#define FA_H 0
#define FA_L (FA_H + 128 * FA_P)
#define FW_H (FA_L + 128 * FA_P)
#define FW_L (FW_H + 64 * FW_P)
#define FSQ  (FW_L + 64 * FW_P)
#define FSM  (FSQ + 512)

__global__ void __launch_bounds__(256) feat_kernel(const float* __restrict__ Wf) {
    extern __shared__ char sm[];
    const uint32_t smb = smem_u32(sm);
    const int tid = threadIdx.x;
    const int bt0 = blockIdx.x * 128, h = blockIdx.y, sel = blockIdx.z;
    const float* src = g_qkv + (size_t)sel * QKV_OFF;

#pragma unroll
    for (int j = 0; j < 8; ++j) {
        int lin = tid + 256 * j;
        int rr = lin >> 4, cc = lin & 15;
        float4 v = *(const float4*)(src + (size_t)(bt0 + rr) * Dm + h * HDm + cc * 4);
        uint32_t h01, l01, h23, l23;
        split2(v.x, v.y, h01, l01);
        split2(v.z, v.w, h23, l23);
        *(uint2*)(sm + FA_H + rr * FA_P + cc * 8) = make_uint2(h01, h23);
        *(uint2*)(sm + FA_L + rr * FA_P + cc * 8) = make_uint2(l01, l23);
    }
#pragma unroll
    for (int j = 0; j < 8; ++j) {
        int lin = tid + 256 * j;
        int rr = lin >> 5, cc = lin & 31;
        float4 v = *(const float4*)(Wf + (size_t)rr * NFm + cc * 4);
        uint32_t h01, l01, h23, l23;
        split2(v.x, v.y, h01, l01);
        split2(v.z, v.w, h23, l23);
        *(uint2*)(sm + FW_H + rr * FW_P + cc * 8) = make_uint2(h01, h23);
        *(uint2*)(sm + FW_L + rr * FW_P + cc * 8) = make_uint2(l01, l23);
    }
    __syncthreads();

    if (tid < 128) {
        float s = 0.f;
#pragma unroll
        for (int d2 = 0; d2 < 32; ++d2) {
            __nv_bfloat162 vh = *(__nv_bfloat162*)(sm + FA_H + tid * FA_P + d2 * 4);
            __nv_bfloat162 vl = *(__nv_bfloat162*)(sm + FA_L + tid * FA_P + d2 * 4);
            float2 fh = __bfloat1622float2(vh), fl = __bfloat1622float2(vl);
            float a = fh.x + fl.x, b = fh.y + fl.y;
            s = fmaf(a, a, fmaf(b, b, s));
        }
        ((float*)(sm + FSQ))[tid] = 0.5f * s;
    }
    __syncthreads();

    const int l = tid & 31, w = tid >> 5;
    const int lj = l >> 3, lm = l & 7;
    const int arow = w * 16 + (lj & 1) * 8 + lm;
    const int acho = lj >> 1;
    const int m = l >> 3, r = l & 7;
    const int sB = (m & 1) ? 8 : 0, eB = (m & 2) ? 8 : 0;

    float acc[16][4];
#pragma unroll
    for (int nb = 0; nb < 16; ++nb)
#pragma unroll
        for (int q = 0; q < 4; ++q) acc[nb][q] = 0.f;

#pragma unroll
    for (int ks = 0; ks < 4; ++ks) {
        uint32_t ah[4], al[4];
        uint32_t ad = smb + FA_H + arow * FA_P + (ks * 2 + acho) * 16;
        LDSM4(ah[0], ah[1], ah[2], ah[3], ad);
        LDSM4(al[0], al[1], al[2], al[3], ad + (FA_L - FA_H));
#pragma unroll
        for (int fp = 0; fp < 4; ++fp) {       // fg pairs
            uint32_t bhf[2][4], blf[2][4];
#pragma unroll
            for (int u = 0; u < 2; ++u) {
                const int fg = fp * 2 + u;
                uint32_t bd = smb + FW_H + (ks * 16 + sB + r) * FW_P + (fg * 16 + eB) * 2;
                LDSM4T(bhf[u][0], bhf[u][1], bhf[u][2], bhf[u][3], bd);
                LDSM4T(blf[u][0], blf[u][1], blf[u][2], blf[u][3], bd + (FW_L - FW_H));
            }
            // pass 1: ah x Bhi (4 distinct accs)
#pragma unroll
            for (int u = 0; u < 2; ++u)
#pragma unroll
                for (int hf = 0; hf < 2; ++hf)
                    MMA16816(acc[(fp * 2 + u) * 2 + hf], ah[0], ah[1], ah[2], ah[3],
                             bhf[u][hf * 2], bhf[u][hf * 2 + 1]);
            // pass 2: ah x Blo
#pragma unroll
            for (int u = 0; u < 2; ++u)
#pragma unroll
                for (int hf = 0; hf < 2; ++hf)
                    MMA16816(acc[(fp * 2 + u) * 2 + hf], ah[0], ah[1], ah[2], ah[3],
                             blf[u][hf * 2], blf[u][hf * 2 + 1]);
            // pass 3: al x Bhi
#pragma unroll
            for (int u = 0; u < 2; ++u)
#pragma unroll
                for (int hf = 0; hf < 2; ++hf)
                    MMA16816(acc[(fp * 2 + u) * 2 + hf], al[0], al[1], al[2], al[3],
                             bhf[u][hf * 2], bhf[u][hf * 2 + 1]);
        }
    }

    float* dst = sel ? g_kp : g_qp;
    const int b = bt0 >> 11;
    const int bh = b * Hh + h;
    const int trow0 = w * 16 + (l >> 2);
    const float* sqp = (const float*)(sm + FSQ);
    const float sq0 = sqp[trow0], sq1 = sqp[trow0 + 8];
    const int t0 = (bt0 & 2047) + trow0;
    float* d0 = dst + ((size_t)bh * Tt + t0) * NFm;
    float* d1 = dst + ((size_t)bh * Tt + t0 + 8) * NFm;
#pragma unroll
    for (int nb = 0; nb < 16; ++nb) {
        const int f = nb * 8 + (l & 3) * 2;
        *(float2*)(d0 + f) = make_float2(expf(acc[nb][0] - sq0) * INV_SQRT_NF,
                                         expf(acc[nb][1] - sq0) * INV_SQRT_NF);
        *(float2*)(d1 + f) = make_float2(expf(acc[nb][2] - sq1) * INV_SQRT_NF,
                                         expf(acc[nb][3] - sq1) * INV_SQRT_NF);
    }
}

// ---------------- K3: chunk_sum via HMMA (pass-outer MMA order) ----------------
#define PKb 272
#define PVb 144
#define CS_KH 0
#define CS_KL (CS_KH + 128 * PKb)
#define CS_VH (CS_KL + 128 * PKb)
#define CS_VL (CS_VH + 128 * PVb)
#define SMEM3 (CS_VL + 128 * PVb)

__global__ void __launch_bounds__(256, 1) chunk_sum_kernel() {
    extern __shared__ char sm[];
    const uint32_t smb = smem_u32(sm);
    const int c = blockIdx.x, bh = blockIdx.y;
    const int b = bh >> 4, h = bh & 15;
    const int tid = threadIdx.x;
    const float* GV = g_qkv + 2 * QKV_OFF;
    const size_t kbase = ((size_t)bh * Tt + c * CHK) * NFm;
    const size_t vbase = ((size_t)(b * Tt + c * CHK)) * Dm + h * HDm;

#pragma unroll
    for (int j = 0; j < 16; ++j) {
        int lin = tid + 256 * j;
        int rr = lin >> 5, cc = lin & 31;
        float4 v = *(const float4*)(g_kp + kbase + (size_t)rr * NFm + cc * 4);
        uint32_t h01, l01, h23, l23;
        split2(v.x, v.y, h01, l01);
        split2(v.z, v.w, h23, l23);
        *(uint2*)(sm + CS_KH + rr * PKb + cc * 8) = make_uint2(h01, h23);
        *(uint2*)(sm + CS_KL + rr * PKb + cc * 8) = make_uint2(l01, l23);
    }
#pragma unroll
    for (int j = 0; j < 8; ++j) {
        int lin = tid + 256 * j;
        int rr = lin >> 4, cc = lin & 15;
        float4 v = *(const float4*)(GV + vbase + (size_t)rr * Dm + cc * 4);
        uint32_t h01, l01, h23, l23;
        split2(v.x, v.y, h01, l01);
        split2(v.z, v.w, h23, l23);
        *(uint2*)(sm + CS_VH + rr * PVb + cc * 8) = make_uint2(h01, h23);
        *(uint2*)(sm + CS_VL + rr * PVb + cc * 8) = make_uint2(l01, l23);
    }
    __syncthreads();

    const int l = tid & 31, w = tid >> 5;
    const int m = l >> 3, r = l & 7;
    const int f0w = (w & 3) * 32, e0w = (w >> 2) * 32;
    const int sA = (m & 2) ? 8 : 0, fA = (m & 1) ? 8 : 0;
    const int sB = (m & 1) ? 8 : 0, eB = (m & 2) ? 8 : 0;

    float acc[2][4][4];
#pragma unroll
    for (int i = 0; i < 2; i++)
#pragma unroll
        for (int jn = 0; jn < 4; jn++)
#pragma unroll
            for (int q = 0; q < 4; q++) acc[i][jn][q] = 0.f;

    for (int s0 = 0; s0 < 128; s0 += 16) {
        uint32_t ah[2][4], al[2][4], bhf[2][4], blf[2][4];
#pragma unroll
        for (int i = 0; i < 2; ++i) {
            uint32_t ad = smb + CS_KH + (s0 + sA + r) * PKb + (f0w + i * 16 + fA) * 2;
            LDSM4T(ah[i][0], ah[i][1], ah[i][2], ah[i][3], ad);
            LDSM4T(al[i][0], al[i][1], al[i][2], al[i][3], ad + (CS_KL - CS_KH));
        }
#pragma unroll
        for (int j2 = 0; j2 < 2; ++j2) {
            uint32_t ad = smb + CS_VH + (s0 + sB + r) * PVb + (e0w + j2 * 16 + eB) * 2;
            LDSM4T(bhf[j2][0], bhf[j2][1], bhf[j2][2], bhf[j2][3], ad);
            LDSM4T(blf[j2][0], blf[j2][1], blf[j2][2], blf[j2][3], ad + (CS_VL - CS_VH));
        }
        // pass 1: Khi x Vhi  (8 distinct accs)
#pragma unroll
        for (int i = 0; i < 2; ++i)
#pragma unroll
            for (int jn = 0; jn < 4; ++jn) {
                const int j2 = jn >> 1, o = (jn & 1) * 2;
                MMA16816(acc[i][jn], ah[i][0], ah[i][1], ah[i][2], ah[i][3],
                         bhf[j2][o], bhf[j2][o + 1]);
            }
        // pass 2: Khi x Vlo
#pragma unroll
        for (int i = 0; i < 2; ++i)
#pragma unroll
            for (int jn = 0; jn < 4; ++jn) {
                const int j2 = jn >> 1, o = (jn & 1) * 2;
                MMA16816(acc[i][jn], ah[i][0], ah[i][1], ah[i][2], ah[i][3],
                         blf[j2][o], blf[j2][o + 1]);
            }
        // pass 3: Klo x Vhi
#pragma unroll
        for (int i = 0; i < 2; ++i)
#pragma unroll
            for (int jn = 0; jn < 4; ++jn) {
                const int j2 = jn >> 1, o = (jn & 1) * 2;
                MMA16816(acc[i][jn], al[i][0], al[i][1], al[i][2], al[i][3],
                         bhf[j2][o], bhf[j2][o + 1]);
            }
    }

    const size_t Sbase = ((size_t)bh * NCH + c) * (NFm * HDm);
#pragma unroll
    for (int i = 0; i < 2; ++i) {
        const int fr = f0w + i * 16 + (l >> 2);
#pragma unroll
        for (int jn = 0; jn < 4; ++jn) {
            const int ec = e0w + jn * 8 + (l & 3) * 2;
            *(float2*)(g_S + Sbase + (size_t)fr * HDm + ec) =
                make_float2(acc[i][jn][0], acc[i][jn][1]);
            *(float2*)(g_S + Sbase + (size_t)(fr + 8) * HDm + ec) =
                make_float2(acc[i][jn][2], acc[i][jn][3]);
        }
    }
    if (tid < 128) {
        float zz = 0.f;
        for (int s = 0; s < 128; ++s) zz += g_kp[kbase + (size_t)s * NFm + tid];
        g_z[((size_t)bh * NCH + c) * NFm + tid] = zz;
    }
}

// ---------------- K4: exclusive prefix over chunks ----------------
__global__ void __launch_bounds__(256) prefix_kernel() {   // grid (32, BH)
    const int bh = blockIdx.y, seg = blockIdx.x;
    const int idx = seg * 256 + threadIdx.x;
    float v[NCH];
    const size_t base = (size_t)bh * NCH * NFm * HDm + idx;
#pragma unroll
    for (int c = 0; c < NCH; ++c) v[c] = g_S[base + (size_t)c * NFm * HDm];
    float acc = 0.f;
#pragma unroll
    for (int c = 0; c < NCH; ++c) { float cur = v[c]; v[c] = acc; acc += cur; }
#pragma unroll
    for (int c = 0; c < NCH; ++c) g_S[base + (size_t)c * NFm * HDm] = v[c];
    if (seg == 0 && threadIdx.x < NFm) {
        float zv[NCH];
        const size_t zb = (size_t)bh * NCH * NFm + threadIdx.x;
#pragma unroll
        for (int c = 0; c < NCH; ++c) zv[c] = g_z[zb + c * NFm];
        float az = 0.f;
#pragma unroll
        for (int c = 0; c < NCH; ++c) { float cur = zv[c]; zv[c] = az; az += cur; }
#pragma unroll
        for (int c = 0; c < NCH; ++c) g_z[zb + c * NFm] = zv[c];
    }
}

// ---------------- K5: chunk_out via HMMA (pass-outer MMA order) ----------------
#define CO_QH 0
#define CO_QL (CO_QH + 128 * PKb)
#define CO_KH (CO_QL + 128 * PKb)
#define CO_KL (CO_KH + 128 * PKb)
#define CO_VH (CO_KL + 128 * PKb)
#define CO_VL (CO_VH + 128 * PVb)
#define CO_SH (CO_VL + 128 * PVb)
#define CO_SL (CO_SH + 128 * PVb)
#define CO_Z  (CO_SL + 128 * PVb)
#define CO_D  (CO_Z + 512)
#define SMEM5 (CO_D + 512)

__global__ void __launch_bounds__(256, 1) chunk_out_kernel() {
    extern __shared__ char sm[];
    const uint32_t smb = smem_u32(sm);
    const int c = blockIdx.x, bh = blockIdx.y;
    const int b = bh >> 4, h = bh & 15;
    const int tid = threadIdx.x;
    const float* GV = g_qkv + 2 * QKV_OFF;
    const size_t qbase = ((size_t)bh * Tt + c * CHK) * NFm;
    const size_t vbase = ((size_t)(b * Tt + c * CHK)) * Dm + h * HDm;
    const size_t Sbase = ((size_t)bh * NCH + c) * (NFm * HDm);

#pragma unroll
    for (int j = 0; j < 16; ++j) {
        int lin = tid + 256 * j;
        int rr = lin >> 5, cc = lin & 31;
        float4 q4 = *(const float4*)(g_qp + qbase + (size_t)rr * NFm + cc * 4);
        float4 k4 = *(const float4*)(g_kp + qbase + (size_t)rr * NFm + cc * 4);
        uint32_t h01, l01, h23, l23;
        split2(q4.x, q4.y, h01, l01);
        split2(q4.z, q4.w, h23, l23);
        *(uint2*)(sm + CO_QH + rr * PKb + cc * 8) = make_uint2(h01, h23);
        *(uint2*)(sm + CO_QL + rr * PKb + cc * 8) = make_uint2(l01, l23);
        split2(k4.x, k4.y, h01, l01);
        split2(k4.z, k4.w, h23, l23);
        *(uint2*)(sm + CO_KH + rr * PKb + cc * 8) = make_uint2(h01, h23);
        *(uint2*)(sm + CO_KL + rr * PKb + cc * 8) = make_uint2(l01, l23);
    }
#pragma unroll
    for (int j = 0; j < 8; ++j) {
        int lin = tid + 256 * j;
        int rr = lin >> 4, cc = lin & 15;
        float4 v4 = *(const float4*)(GV + vbase + (size_t)rr * Dm + cc * 4);
        uint32_t h01, l01, h23, l23;
        split2(v4.x, v4.y, h01, l01);
        split2(v4.z, v4.w, h23, l23);
        *(uint2*)(sm + CO_VH + rr * PVb + cc * 8) = make_uint2(h01, h23);
        *(uint2*)(sm + CO_VL + rr * PVb + cc * 8) = make_uint2(l01, l23);
        float4 s4 = *(const float4*)(g_S + Sbase + (size_t)rr * HDm + cc * 4);
        split2(s4.x, s4.y, h01, l01);
        split2(s4.z, s4.w, h23, l23);
        *(uint2*)(sm + CO_SH + rr * PVb + cc * 8) = make_uint2(h01, h23);
        *(uint2*)(sm + CO_SL + rr * PVb + cc * 8) = make_uint2(l01, l23);
    }
    if (tid < 128)
        ((float*)(sm + CO_Z))[tid] = g_z[((size_t)bh * NCH + c) * NFm + tid];
    __syncthreads();

    const int l = tid & 31, w = tid >> 5;
    const int wm = w & 3, wn = w >> 2;
    const int lj = l >> 3, lm = l & 7;
    const int m = l >> 3, r = l & 7;
    const int arow = wm * 32 + (lj & 1) * 8 + lm;
    const int acho = lj >> 1;
    const int brow = ((lj & 2) ? 8 : 0) + lm;
    const int bcho = lj & 1;
    const int sB = (m & 1) ? 8 : 0, eB = (m & 2) ? 8 : 0;

    float accA[2][8][4];
#pragma unroll
    for (int i = 0; i < 2; i++)
#pragma unroll
        for (int jn = 0; jn < 8; jn++)
#pragma unroll
            for (int q = 0; q < 4; q++) accA[i][jn][q] = 0.f;

    for (int f0 = 0; f0 < 128; f0 += 16) {
        uint32_t qh[2][4], ql[2][4];
#pragma unroll
        for (int i = 0; i < 2; ++i) {
            uint32_t ad = smb + CO_QH + (arow + i * 16) * PKb + (f0 / 8 + acho) * 16;
            LDSM4(qh[i][0], qh[i][1], qh[i][2], qh[i][3], ad);
            LDSM4(ql[i][0], ql[i][1], ql[i][2], ql[i][3], ad + (CO_QL - CO_QH));
        }
#pragma unroll
        for (int g = 0; g < 4; ++g) {
            uint32_t kh[4], kl[4];
            uint32_t ad = smb + CO_KH + (wn * 64 + brow + g * 16) * PKb + (f0 / 8 + bcho) * 16;
            LDSM4(kh[0], kh[1], kh[2], kh[3], ad);
            LDSM4(kl[0], kl[1], kl[2], kl[3], ad + (CO_KL - CO_KH));
            // pass 1: Qhi x Khi (4 distinct accs)
#pragma unroll
            for (int i = 0; i < 2; ++i)
#pragma unroll
                for (int hf = 0; hf < 2; ++hf)
                    MMA16816(accA[i][g * 2 + hf], qh[i][0], qh[i][1], qh[i][2], qh[i][3],
                             kh[hf * 2], kh[hf * 2 + 1]);
            // pass 2: Qhi x Klo
#pragma unroll
            for (int i = 0; i < 2; ++i)
#pragma unroll
                for (int hf = 0; hf < 2; ++hf)
                    MMA16816(accA[i][g * 2 + hf], qh[i][0], qh[i][1], qh[i][2], qh[i][3],
                             kl[hf * 2], kl[hf * 2 + 1]);
            // pass 3: Qlo x Khi
#pragma unroll
            for (int i = 0; i < 2; ++i)
#pragma unroll
                for (int hf = 0; hf < 2; ++hf)
                    MMA16816(accA[i][g * 2 + hf], ql[i][0], ql[i][1], ql[i][2], ql[i][3],
                             kh[hf * 2], kh[hf * 2 + 1]);
        }
    }
    __syncthreads();

#pragma unroll
    for (int i = 0; i < 2; ++i) {
        const int tr = wm * 32 + i * 16 + (l >> 2);
#pragma unroll
        for (int jn = 0; jn < 8; ++jn) {
            const int sc = wn * 64 + jn * 8 + (l & 3) * 2;
            float v0 = (sc     <= tr) ? accA[i][jn][0] : 0.f;
            float v1 = (sc + 1 <= tr) ? accA[i][jn][1] : 0.f;
            uint32_t hi, lo;
            split2(v0, v1, hi, lo);
            *(uint32_t*)(sm + CO_KH + tr * PKb + sc * 2) = hi;
            *(uint32_t*)(sm + CO_KL + tr * PKb + sc * 2) = lo;
            const int tr8 = tr + 8;
            v0 = (sc     <= tr8) ? accA[i][jn][2] : 0.f;
            v1 = (sc + 1 <= tr8) ? accA[i][jn][3] : 0.f;
            split2(v0, v1, hi, lo);
            *(uint32_t*)(sm + CO_KH + tr8 * PKb + sc * 2) = hi;
            *(uint32_t*)(sm + CO_KL + tr8 * PKb + sc * 2) = lo;
        }
    }
    __syncthreads();

    if (tid < 128) {
        const int t = tid;
        float den = EPSf;
        const float* zp = (const float*)(sm + CO_Z);
#pragma unroll 8
        for (int f2 = 0; f2 < 64; ++f2) {
            __nv_bfloat162 qh2 = *(__nv_bfloat162*)(sm + CO_QH + t * PKb + f2 * 4);
            __nv_bfloat162 ql2 = *(__nv_bfloat162*)(sm + CO_QL + t * PKb + f2 * 4);
            float2 fh = __bfloat1622float2(qh2), fl = __bfloat1622float2(ql2);
            den += (fh.x + fl.x) * zp[2 * f2] + (fh.y + fl.y) * zp[2 * f2 + 1];
        }
#pragma unroll 8
        for (int s2 = 0; s2 < 64; ++s2) {
            __nv_bfloat162 ah2 = *(__nv_bfloat162*)(sm + CO_KH + t * PKb + s2 * 4);
            __nv_bfloat162 al2 = *(__nv_bfloat162*)(sm + CO_KL + t * PKb + s2 * 4);
            float2 fa = __bfloat1622float2(ah2), fb = __bfloat1622float2(al2);
            den += fa.x + fa.y + fb.x + fb.y;
        }
        ((float*)(sm + CO_D))[t] = 1.f / den;
    }
    __syncthreads();

    const int e0w = wn * 32;
    float accY[2][4][4];
#pragma unroll
    for (int i = 0; i < 2; i++)
#pragma unroll
        for (int jn = 0; jn < 4; jn++)
#pragma unroll
            for (int q = 0; q < 4; q++) accY[i][jn][q] = 0.f;

    // part 1: A(masked) @ V — pass-outer
    for (int s0 = 0; s0 < 128; s0 += 16) {
        uint32_t aah[2][4], aal[2][4], vh[2][4], vl[2][4];
#pragma unroll
        for (int i = 0; i < 2; ++i) {
            uint32_t ad = smb + CO_KH + (arow + i * 16) * PKb + (s0 / 8 + acho) * 16;
            LDSM4(aah[i][0], aah[i][1], aah[i][2], aah[i][3], ad);
            LDSM4(aal[i][0], aal[i][1], aal[i][2], aal[i][3], ad + (CO_KL - CO_KH));
        }
#pragma unroll
        for (int j2 = 0; j2 < 2; ++j2) {
            uint32_t ad = smb + CO_VH + (s0 + sB + r) * PVb + (e0w + j2 * 16 + eB) * 2;
            LDSM4T(vh[j2][0], vh[j2][1], vh[j2][2], vh[j2][3], ad);
            LDSM4T(vl[j2][0], vl[j2][1], vl[j2][2], vl[j2][3], ad + (CO_VL - CO_VH));
        }
#pragma unroll
        for (int i = 0; i < 2; ++i)
#pragma unroll
            for (int jn = 0; jn < 4; ++jn) {
                const int j2 = jn >> 1, o = (jn & 1) * 2;
                MMA16816(accY[i][jn], aah[i][0], aah[i][1], aah[i][2], aah[i][3],
                         vh[j2][o], vh[j2][o + 1]);
            }
#pragma unroll
        for (int i = 0; i < 2; ++i)
#pragma unroll
            for (int jn = 0; jn < 4; ++jn) {
                const int j2 = jn >> 1, o = (jn & 1) * 2;
                MMA16816(accY[i][jn], aah[i][0], aah[i][1], aah[i][2], aah[i][3],
                         vl[j2][o], vl[j2][o + 1]);
            }
#pragma unroll
        for (int i = 0; i < 2; ++i)
#pragma unroll
            for (int jn = 0; jn < 4; ++jn) {
                const int j2 = jn >> 1, o = (jn & 1) * 2;
                MMA16816(accY[i][jn], aal[i][0], aal[i][1], aal[i][2], aal[i][3],
                         vh[j2][o], vh[j2][o + 1]);
            }
    }
    // part 2: Q @ S_prev — pass-outer
    for (int f0 = 0; f0 < 128; f0 += 16) {
        uint32_t qh[2][4], ql[2][4], sh[2][4], sl[2][4];
#pragma unroll
        for (int i = 0; i < 2; ++i) {
            uint32_t ad = smb + CO_QH + (arow + i * 16) * PKb + (f0 / 8 + acho) * 16;
            LDSM4(qh[i][0], qh[i][1], qh[i][2], qh[i][3], ad);
            LDSM4(ql[i][0], ql[i][1], ql[i][2], ql[i][3], ad + (CO_QL - CO_QH));
        }
#pragma unroll
        for (int j2 = 0; j2 < 2; ++j2) {
            uint32_t ad = smb + CO_SH + (f0 + sB + r) * PVb + (e0w + j2 * 16 + eB) * 2;
            LDSM4T(sh[j2][0], sh[j2][1], sh[j2][2], sh[j2][3], ad);
            LDSM4T(sl[j2][0], sl[j2][1], sl[j2][2], sl[j2][3], ad + (CO_SL - CO_SH));
        }
#pragma unroll
        for (int i = 0; i < 2; ++i)
#pragma unroll
            for (int jn = 0; jn < 4; ++jn) {
                const int j2 = jn >> 1, o = (jn & 1) * 2;
                MMA16816(accY[i][jn], qh[i][0], qh[i][1], qh[i][2], qh[i][3],
                         sh[j2][o], sh[j2][o + 1]);
            }
#pragma unroll
        for (int i = 0; i < 2; ++i)
#pragma unroll
            for (int jn = 0; jn < 4; ++jn) {
                const int j2 = jn >> 1, o = (jn & 1) * 2;
                MMA16816(accY[i][jn], qh[i][0], qh[i][1], qh[i][2], qh[i][3],
                         sl[j2][o], sl[j2][o + 1]);
            }
#pragma unroll
        for (int i = 0; i < 2; ++i)
#pragma unroll
            for (int jn = 0; jn < 4; ++jn) {
                const int j2 = jn >> 1, o = (jn & 1) * 2;
                MMA16816(accY[i][jn], ql[i][0], ql[i][1], ql[i][2], ql[i][3],
                         sh[j2][o], sh[j2][o + 1]);
            }
    }

    const float* dv = (const float*)(sm + CO_D);
#pragma unroll
    for (int i = 0; i < 2; ++i) {
        const int tr = wm * 32 + i * 16 + (l >> 2);
        const float d0 = dv[tr], d1 = dv[tr + 8];
#pragma unroll
        for (int jn = 0; jn < 4; ++jn) {
            const int ec = e0w + jn * 8 + (l & 3) * 2;
            size_t o0 = ((size_t)(b * Tt + c * CHK + tr)) * Dm + h * HDm + ec;
            size_t o1 = ((size_t)(b * Tt + c * CHK + tr + 8)) * Dm + h * HDm + ec;
            uint32_t hi, lo;
            split2h(accY[i][jn][0] * d0, accY[i][jn][1] * d0, hi, lo);
            *(uint32_t*)(g_yh16 + o0) = hi;
            *(uint32_t*)(g_yl16 + o0) = lo;
            split2h(accY[i][jn][2] * d1, accY[i][jn][3] * d1, hi, lo);
            *(uint32_t*)(g_yh16 + o1) = hi;
            *(uint32_t*)(g_yl16 + o1) = lo;
        }
    }
}

// ---------------------------------------------------------------------------
extern "C" void kernel_launch(void* const* d_in, const int* in_sizes, int n_in,
                              void* d_out, int out_size) {
    const float* x  = (const float*)d_in[0];
    const float* Wq = (const float*)d_in[1];
    const float* Wk = (const float*)d_in[2];
    const float* Wv = (const float*)d_in[3];
    const float* Wo = (const float*)d_in[4];
    const float* Wf = (const float*)d_in[5];
    float* out = (float*)d_out;

    cudaFuncSetAttribute(proj_kernel,      cudaFuncAttributeMaxDynamicSharedMemorySize, G2SMEM);
    cudaFuncSetAttribute(out_kernel,       cudaFuncAttributeMaxDynamicSharedMemorySize, G2SMEM);
    cudaFuncSetAttribute(feat_kernel,      cudaFuncAttributeMaxDynamicSharedMemorySize, FSM);
    cudaFuncSetAttribute(chunk_sum_kernel, cudaFuncAttributeMaxDynamicSharedMemorySize, SMEM3);
    cudaFuncSetAttribute(chunk_out_kernel, cudaFuncAttributeMaxDynamicSharedMemorySize, SMEM5);

    split_kernel<<<(MR * Dm / 4) / 256, 256>>>(x);
    wsplit_kernel<<<dim3(32, 32, 4), 256>>>(Wq, Wk, Wv, Wo);
    proj_kernel<<<dim3(8, 64, 3), 256, G2SMEM>>>();             // q, k, v — fp16 2-pass
    feat_kernel<<<dim3(MR / 128, Hh, 2), 256, FSM>>>(Wf);
    chunk_sum_kernel<<<dim3(NCH, BH), 256, SMEM3>>>();
    prefix_kernel<<<dim3(32, BH), 256>>>();
    chunk_out_kernel<<<dim3(NCH, BH), 256, SMEM5>>>();
    out_kernel<<<dim3(8, 64), 256, G2SMEM>>>(out);
}

// round 15
// speedup vs baseline: 3.8895x; 1.0039x over previous
#include <cuda_runtime.h>
#include <cuda_bf16.h>
#include <cuda_fp16.h>
#include <math.h>
#include <stdint.h>

// ---------------- problem constants ----------------
#define Bb   4
#define Tt   2048
#define Dm   1024
#define Hh   16
#define HDm  64
#define NFm  128
#define CHK  128
#define NCH  16
#define BH   64
#define MR   8192
#define EPSf 1e-6f
#define INV_SQRT_NF 0.08838834764831845f

#define QKV_OFF ((size_t)MR * Dm)

// ---------------- scratch ----------------
__device__ float g_qkv[3 * (size_t)MR * Dm];   // q | k | v
__device__ float g_qp [(size_t)BH * Tt * NFm];
__device__ float g_kp [(size_t)BH * Tt * NFm];
__device__ float g_S  [(size_t)BH * NCH * NFm * HDm];
__device__ float g_z  [(size_t)BH * NCH * NFm];

__device__ __half g_xh16[(size_t)MR * Dm], g_xl16[(size_t)MR * Dm];   // x fp16 split
__device__ __half g_yh16[(size_t)MR * Dm], g_yl16[(size_t)MR * Dm];   // y fp16 split
__device__ __half g_wt16[4 * (size_t)Dm * Dm];                        // Wq,Wk,Wv,Wo ^T fp16

// ---------------- helpers ----------------
__device__ __forceinline__ uint32_t smem_u32(const void* p) {
    uint32_t a;
    asm("{ .reg .u64 t; cvta.to.shared.u64 t, %1; cvt.u32.u64 %0, t; }" : "=r"(a) : "l"(p));
    return a;
}

#define LDSM4(r0, r1, r2, r3, addr)                                          \
    asm volatile("ldmatrix.sync.aligned.m8n8.x4.shared.b16 {%0,%1,%2,%3}, [%4];" \
                 : "=r"(r0), "=r"(r1), "=r"(r2), "=r"(r3) : "r"(addr))

#define LDSM4T(r0, r1, r2, r3, addr)                                         \
    asm volatile("ldmatrix.sync.aligned.m8n8.x4.trans.shared.b16 {%0,%1,%2,%3}, [%4];" \
                 : "=r"(r0), "=r"(r1), "=r"(r2), "=r"(r3) : "r"(addr))

#define MMA16816(d, a0, a1, a2, a3, b0, b1)                                  \
    asm volatile("mma.sync.aligned.m16n8k16.row.col.f32.bf16.bf16.f32 "      \
                 "{%0,%1,%2,%3}, {%4,%5,%6,%7}, {%8,%9}, {%0,%1,%2,%3};"     \
                 : "+f"((d)[0]), "+f"((d)[1]), "+f"((d)[2]), "+f"((d)[3])    \
                 : "r"(a0), "r"(a1), "r"(a2), "r"(a3), "r"(b0), "r"(b1))

#define MMA16816H(d, a0, a1, a2, a3, b0, b1)                                 \
    asm volatile("mma.sync.aligned.m16n8k16.row.col.f32.f16.f16.f32 "        \
                 "{%0,%1,%2,%3}, {%4,%5,%6,%7}, {%8,%9}, {%0,%1,%2,%3};"     \
                 : "+f"((d)[0]), "+f"((d)[1]), "+f"((d)[2]), "+f"((d)[3])    \
                 : "r"(a0), "r"(a1), "r"(a2), "r"(a3), "r"(b0), "r"(b1))

#define CP_ASYNC16(sa, g) \
    asm volatile("cp.async.cg.shared.global [%0], [%1], 16;" :: "r"(sa), "l"(g))

__device__ __forceinline__ void split2(float a, float b, uint32_t& hi, uint32_t& lo) {
    __nv_bfloat16 ha = __float2bfloat16(a), hb = __float2bfloat16(b);
    __nv_bfloat16 la = __float2bfloat16(a - __bfloat162float(ha));
    __nv_bfloat16 lb = __float2bfloat16(b - __bfloat162float(hb));
    hi = ((uint32_t)__bfloat16_as_ushort(hb) << 16) | __bfloat16_as_ushort(ha);
    lo = ((uint32_t)__bfloat16_as_ushort(lb) << 16) | __bfloat16_as_ushort(la);
}

__device__ __forceinline__ void split2h(float a, float b, uint32_t& hi, uint32_t& lo) {
    __half ha = __float2half_rn(a), hb = __float2half_rn(b);
    __half la = __float2half_rn(a - __half2float(ha));
    __half lb = __float2half_rn(b - __half2float(hb));
    hi = ((uint32_t)__half_as_ushort(hb) << 16) | __half_as_ushort(ha);
    lo = ((uint32_t)__half_as_ushort(lb) << 16) | __half_as_ushort(la);
}

// ---------------- K0: fp32 x -> fp16 hi/lo ----------------
__global__ void __launch_bounds__(256) split_kernel(const float* __restrict__ xsrc) {
    const size_t i = (size_t)blockIdx.x * 256 + threadIdx.x;   // float4 index
    const float4 v = ((const float4*)xsrc)[i];
    uint32_t h01, l01, h23, l23;
    split2h(v.x, v.y, h01, l01);
    split2h(v.z, v.w, h23, l23);
    *(uint2*)(g_xh16 + 4 * i) = make_uint2(h01, h23);
    *(uint2*)(g_xl16 + 4 * i) = make_uint2(l01, l23);
}

// ---------------- K0b: W transpose -> fp16, all four ----------------
__global__ void __launch_bounds__(256) wsplit_kernel(const float* __restrict__ Wq,
                                                     const float* __restrict__ Wk,
                                                     const float* __restrict__ Wv,
                                                     const float* __restrict__ Wo) {
    __shared__ float t[32][33];
    const int z = blockIdx.z;
    const float* W = (z == 0) ? Wq : (z == 1) ? Wk : (z == 2) ? Wv : Wo;
    const int tx = threadIdx.x & 31, ty = threadIdx.x >> 5;   // 32 x 8
    const int bx = blockIdx.x, by = blockIdx.y;
#pragma unroll
    for (int j = 0; j < 4; j++) {
        int k = by * 32 + ty + j * 8;
        int n = bx * 32 + tx;
        t[ty + j * 8][tx] = W[(size_t)k * Dm + n];
    }
    __syncthreads();
#pragma unroll
    for (int j = 0; j < 4; j++) {
        int n = bx * 32 + ty + j * 8;
        int k = by * 32 + tx;
        g_wt16[(size_t)z * Dm * Dm + (size_t)n * Dm + k] = __float2half_rn(t[tx][ty + j * 8]);
    }
}

// ---------------- K1: 2-pass fp16 GEMM (q/k/v projections AND output) ----------
// 3 stages x 30KB = 90KB smem, 2 CTAs/SM, single sync per k-iter,
// cp.async wait_group 1 => the awaited load was committed TWO iterations ago
// (depth-2 prefetch covers DRAM latency + bandwidth).
#define TROW   80
#define TILE_B (128 * TROW)
#define STG2_B (3 * TILE_B)          // 30720
#define G2SMEM (3 * STG2_B)          // 92160

__device__ __forceinline__ void gemm2p_body(const __half* __restrict__ Ahi,
                                            const __half* __restrict__ Alo,
                                            const __half* __restrict__ B,
                                            float* __restrict__ C,
                                            char* sm, int m0, int n0) {
    const uint32_t smb = smem_u32(sm);
    const int tid = threadIdx.x;

#define LOAD_G(buf, k0)                                                       \
    do {                                                                      \
        uint32_t sb_ = smb + (buf) * STG2_B;                                  \
        _Pragma("unroll")                                                     \
        for (int j_ = 0; j_ < 6; ++j_) {                                      \
            int lin_ = tid + 256 * j_;                                        \
            int tile_ = lin_ >> 9;                                            \
            int idx_ = lin_ & 511;                                            \
            int r_ = idx_ >> 2, c_ = idx_ & 3;                                \
            const __half* gp_ = (tile_ == 0) ? Ahi : (tile_ == 1) ? Alo : B;  \
            int gr_ = (tile_ < 2) ? (m0 + r_) : (n0 + r_);                    \
            CP_ASYNC16(sb_ + tile_ * TILE_B + r_ * TROW + c_ * 16,            \
                       gp_ + (size_t)gr_ * Dm + (k0) + c_ * 8);               \
        }                                                                     \
    } while (0)

    const int lane = tid & 31, w = tid >> 5;
    const int wm = w & 3, wn = w >> 2;
    const int lj = lane >> 3, lm = lane & 7;
    const int arow = wm * 32 + (lj & 1) * 8 + lm;
    const int acho = lj >> 1;
    const int brow = wn * 64 + ((lj & 2) ? 8 : 0) + lm;
    const int bcho = lj & 1;

    float acc[2][8][4];
#pragma unroll
    for (int i = 0; i < 2; i++)
#pragma unroll
        for (int jn = 0; jn < 8; jn++)
#pragma unroll
            for (int r = 0; r < 4; r++) acc[i][jn][r] = 0.f;

    // prologue: stages 0 and 1 in flight (G0, G1)
    LOAD_G(0, 0);
    asm volatile("cp.async.commit_group;" ::: "memory");
    LOAD_G(1, 32);
    asm volatile("cp.async.commit_group;" ::: "memory");

    for (int it = 0; it < 32; ++it) {
        // committed so far: G0..G(it+1). wait_group 1 => G(it) (= buf it%3) complete.
        asm volatile("cp.async.wait_group 1;" ::: "memory");
        __syncthreads();   // all warps done with buf (it+2)%3 (last read at iter it-1)
        const int nxt = it + 2;
        if (nxt < 32) LOAD_G(nxt % 3, nxt * 32);
        asm volatile("cp.async.commit_group;" ::: "memory");   // G(it+2) (may be empty)

        const uint32_t buf = smb + (it % 3) * STG2_B;
#pragma unroll
        for (int ks = 0; ks < 2; ++ks) {
            uint32_t ah[2][4], al[2][4];
#pragma unroll
            for (int i = 0; i < 2; ++i) {
                uint32_t ra = buf + (arow + i * 16) * TROW + (ks * 2 + acho) * 16;
                LDSM4(ah[i][0], ah[i][1], ah[i][2], ah[i][3], ra);
                LDSM4(al[i][0], al[i][1], al[i][2], al[i][3], ra + TILE_B);
            }
#pragma unroll
            for (int g = 0; g < 4; ++g) {
                uint32_t bfr[4];
                uint32_t rb = buf + 2 * TILE_B + (brow + g * 16) * TROW + (ks * 2 + bcho) * 16;
                LDSM4(bfr[0], bfr[1], bfr[2], bfr[3], rb);
#pragma unroll
                for (int i = 0; i < 2; ++i)
#pragma unroll
                    for (int hf = 0; hf < 2; ++hf)
                        MMA16816H(acc[i][g * 2 + hf], ah[i][0], ah[i][1], ah[i][2], ah[i][3],
                                  bfr[hf * 2], bfr[hf * 2 + 1]);
#pragma unroll
                for (int i = 0; i < 2; ++i)
#pragma unroll
                    for (int hf = 0; hf < 2; ++hf)
                        MMA16816H(acc[i][g * 2 + hf], al[i][0], al[i][1], al[i][2], al[i][3],
                                  bfr[hf * 2], bfr[hf * 2 + 1]);
            }
        }
    }

#pragma unroll
    for (int i = 0; i < 2; ++i) {
        const int r0 = m0 + wm * 32 + i * 16 + (lane >> 2);
#pragma unroll
        for (int jn = 0; jn < 8; ++jn) {
            const int cc = n0 + wn * 64 + jn * 8 + 2 * (lane & 3);
            *(float2*)&C[(size_t)r0 * Dm + cc]       = make_float2(acc[i][jn][0], acc[i][jn][1]);
            *(float2*)&C[(size_t)(r0 + 8) * Dm + cc] = make_float2(acc[i][jn][2], acc[i][jn][3]);
        }
    }
#undef LOAD_G
}

__global__ void __launch_bounds__(256, 2) proj_kernel() {
    extern __shared__ char sm[];
    const int z = blockIdx.z;   // 0=q, 1=k, 2=v
    gemm2p_body(g_xh16, g_xl16, g_wt16 + (size_t)z * Dm * Dm,
                g_qkv + (size_t)z * QKV_OFF, sm,
                blockIdx.y * 128, blockIdx.x * 128);
}

__global__ void __launch_bounds__(256, 2) out_kernel(float* __restrict__ Cout) {
    extern __shared__ char sm[];
    gemm2p_body(g_yh16, g_yl16, g_wt16 + (size_t)3 * Dm * Dm,
                Cout, sm, blockIdx.y * 128, blockIdx.x * 128);
}

// ---------------- K2: FAVOR+ features via HMMA + exp epilogue ----------------
#define FA_P 144
#define FW_P 272
#define FA_H 0
#define FA_L (FA_H + 128 * FA_P)
#define FW_H (FA_L + 128 * FA_P)
#define FW_L (FW_H + 64 * FW_P)
#define FSQ  (FW_L + 64 * FW_P)
#define FSM  (FSQ + 512)

__global__ void __launch_bounds__(256) feat_kernel(const float* __restrict__ Wf) {
    extern __shared__ char sm[];
    const uint32_t smb = smem_u32(sm);
    const int tid = threadIdx.x;
    const int bt0 = blockIdx.x * 128, h = blockIdx.y, sel = blockIdx.z;
    const float* src = g_qkv + (size_t)sel * QKV_OFF;

#pragma unroll
    for (int j = 0; j < 8; ++j) {
        int lin = tid + 256 * j;
        int rr = lin >> 4, cc = lin & 15;
        float4 v = *(const float4*)(src + (size_t)(bt0 + rr) * Dm + h * HDm + cc * 4);
        uint32_t h01, l01, h23, l23;
        split2(v.x, v.y, h01, l01);
        split2(v.z, v.w, h23, l23);
        *(uint2*)(sm + FA_H + rr * FA_P + cc * 8) = make_uint2(h01, h23);
        *(uint2*)(sm + FA_L + rr * FA_P + cc * 8) = make_uint2(l01, l23);
    }
#pragma unroll
    for (int j = 0; j < 8; ++j) {
        int lin = tid + 256 * j;
        int rr = lin >> 5, cc = lin & 31;
        float4 v = *(const float4*)(Wf + (size_t)rr * NFm + cc * 4);
        uint32_t h01, l01, h23, l23;
        split2(v.x, v.y, h01, l01);
        split2(v.z, v.w, h23, l23);
        *(uint2*)(sm + FW_H + rr * FW_P + cc * 8) = make_uint2(h01, h23);
        *(uint2*)(sm + FW_L + rr * FW_P + cc * 8) = make_uint2(l01, l23);
    }
    __syncthreads();

    if (tid < 128) {
        float s = 0.f;
#pragma unroll
        for (int d2 = 0; d2 < 32; ++d2) {
            __nv_bfloat162 vh = *(__nv_bfloat162*)(sm + FA_H + tid * FA_P + d2 * 4);
            __nv_bfloat162 vl = *(__nv_bfloat162*)(sm + FA_L + tid * FA_P + d2 * 4);
            float2 fh = __bfloat1622float2(vh), fl = __bfloat1622float2(vl);
            float a = fh.x + fl.x, b = fh.y + fl.y;
            s = fmaf(a, a, fmaf(b, b, s));
        }
        ((float*)(sm + FSQ))[tid] = 0.5f * s;
    }
    __syncthreads();

    const int l = tid & 31, w = tid >> 5;
    const int lj = l >> 3, lm = l & 7;
    const int arow = w * 16 + (lj & 1) * 8 + lm;
    const int acho = lj >> 1;
    const int m = l >> 3, r = l & 7;
    const int sB = (m & 1) ? 8 : 0, eB = (m & 2) ? 8 : 0;

    float acc[16][4];
#pragma unroll
    for (int nb = 0; nb < 16; ++nb)
#pragma unroll
        for (int q = 0; q < 4; ++q) acc[nb][q] = 0.f;

#pragma unroll
    for (int ks = 0; ks < 4; ++ks) {
        uint32_t ah[4], al[4];
        uint32_t ad = smb + FA_H + arow * FA_P + (ks * 2 + acho) * 16;
        LDSM4(ah[0], ah[1], ah[2], ah[3], ad);
        LDSM4(al[0], al[1], al[2], al[3], ad + (FA_L - FA_H));
#pragma unroll
        for (int fp = 0; fp < 4; ++fp) {
            uint32_t bhf[2][4], blf[2][4];
#pragma unroll
            for (int u = 0; u < 2; ++u) {
                const int fg = fp * 2 + u;
                uint32_t bd = smb + FW_H + (ks * 16 + sB + r) * FW_P + (fg * 16 + eB) * 2;
                LDSM4T(bhf[u][0], bhf[u][1], bhf[u][2], bhf[u][3], bd);
                LDSM4T(blf[u][0], blf[u][1], blf[u][2], blf[u][3], bd + (FW_L - FW_H));
            }
#pragma unroll
            for (int u = 0; u < 2; ++u)
#pragma unroll
                for (int hf = 0; hf < 2; ++hf)
                    MMA16816(acc[(fp * 2 + u) * 2 + hf], ah[0], ah[1], ah[2], ah[3],
                             bhf[u][hf * 2], bhf[u][hf * 2 + 1]);
#pragma unroll
            for (int u = 0; u < 2; ++u)
#pragma unroll
                for (int hf = 0; hf < 2; ++hf)
                    MMA16816(acc[(fp * 2 + u) * 2 + hf], ah[0], ah[1], ah[2], ah[3],
                             blf[u][hf * 2], blf[u][hf * 2 + 1]);
#pragma unroll
            for (int u = 0; u < 2; ++u)
#pragma unroll
                for (int hf = 0; hf < 2; ++hf)
                    MMA16816(acc[(fp * 2 + u) * 2 + hf], al[0], al[1], al[2], al[3],
                             bhf[u][hf * 2], bhf[u][hf * 2 + 1]);
        }
    }

    float* dst = sel ? g_kp : g_qp;
    const int b = bt0 >> 11;
    const int bh = b * Hh + h;
    const int trow0 = w * 16 + (l >> 2);
    const float* sqp = (const float*)(sm + FSQ);
    const float sq0 = sqp[trow0], sq1 = sqp[trow0 + 8];
    const int t0 = (bt0 & 2047) + trow0;
    float* d0 = dst + ((size_t)bh * Tt + t0) * NFm;
    float* d1 = dst + ((size_t)bh * Tt + t0 + 8) * NFm;
#pragma unroll
    for (int nb = 0; nb < 16; ++nb) {
        const int f = nb * 8 + (l & 3) * 2;
        *(float2*)(d0 + f) = make_float2(expf(acc[nb][0] - sq0) * INV_SQRT_NF,
                                         expf(acc[nb][1] - sq0) * INV_SQRT_NF);
        *(float2*)(d1 + f) = make_float2(expf(acc[nb][2] - sq1) * INV_SQRT_NF,
                                         expf(acc[nb][3] - sq1) * INV_SQRT_NF);
    }
}

// ---------------- K3: chunk_sum via HMMA ----------------
#define PKb 272
#define PVb 144
#define CS_KH 0
#define CS_KL (CS_KH + 128 * PKb)
#define CS_VH (CS_KL + 128 * PKb)
#define CS_VL (CS_VH + 128 * PVb)
#define SMEM3 (CS_VL + 128 * PVb)

__global__ void __launch_bounds__(256, 1) chunk_sum_kernel() {
    extern __shared__ char sm[];
    const uint32_t smb = smem_u32(sm);
    const int c = blockIdx.x, bh = blockIdx.y;
    const int b = bh >> 4, h = bh & 15;
    const int tid = threadIdx.x;
    const float* GV = g_qkv + 2 * QKV_OFF;
    const size_t kbase = ((size_t)bh * Tt + c * CHK) * NFm;
    const size_t vbase = ((size_t)(b * Tt + c * CHK)) * Dm + h * HDm;

#pragma unroll
    for (int j = 0; j < 16; ++j) {
        int lin = tid + 256 * j;
        int rr = lin >> 5, cc = lin & 31;
        float4 v = *(const float4*)(g_kp + kbase + (size_t)rr * NFm + cc * 4);
        uint32_t h01, l01, h23, l23;
        split2(v.x, v.y, h01, l01);
        split2(v.z, v.w, h23, l23);
        *(uint2*)(sm + CS_KH + rr * PKb + cc * 8) = make_uint2(h01, h23);
        *(uint2*)(sm + CS_KL + rr * PKb + cc * 8) = make_uint2(l01, l23);
    }
#pragma unroll
    for (int j = 0; j < 8; ++j) {
        int lin = tid + 256 * j;
        int rr = lin >> 4, cc = lin & 15;
        float4 v = *(const float4*)(GV + vbase + (size_t)rr * Dm + cc * 4);
        uint32_t h01, l01, h23, l23;
        split2(v.x, v.y, h01, l01);
        split2(v.z, v.w, h23, l23);
        *(uint2*)(sm + CS_VH + rr * PVb + cc * 8) = make_uint2(h01, h23);
        *(uint2*)(sm + CS_VL + rr * PVb + cc * 8) = make_uint2(l01, l23);
    }
    __syncthreads();

    const int l = tid & 31, w = tid >> 5;
    const int m = l >> 3, r = l & 7;
    const int f0w = (w & 3) * 32, e0w = (w >> 2) * 32;
    const int sA = (m & 2) ? 8 : 0, fA = (m & 1) ? 8 : 0;
    const int sB = (m & 1) ? 8 : 0, eB = (m & 2) ? 8 : 0;

    float acc[2][4][4];
#pragma unroll
    for (int i = 0; i < 2; i++)
#pragma unroll
        for (int jn = 0; jn < 4; jn++)
#pragma unroll
            for (int q = 0; q < 4; q++) acc[i][jn][q] = 0.f;

    for (int s0 = 0; s0 < 128; s0 += 16) {
        uint32_t ah[2][4], al[2][4], bhf[2][4], blf[2][4];
#pragma unroll
        for (int i = 0; i < 2; ++i) {
            uint32_t ad = smb + CS_KH + (s0 + sA + r) * PKb + (f0w + i * 16 + fA) * 2;
            LDSM4T(ah[i][0], ah[i][1], ah[i][2], ah[i][3], ad);
            LDSM4T(al[i][0], al[i][1], al[i][2], al[i][3], ad + (CS_KL - CS_KH));
        }
#pragma unroll
        for (int j2 = 0; j2 < 2; ++j2) {
            uint32_t ad = smb + CS_VH + (s0 + sB + r) * PVb + (e0w + j2 * 16 + eB) * 2;
            LDSM4T(bhf[j2][0], bhf[j2][1], bhf[j2][2], bhf[j2][3], ad);
            LDSM4T(blf[j2][0], blf[j2][1], blf[j2][2], blf[j2][3], ad + (CS_VL - CS_VH));
        }
#pragma unroll
        for (int i = 0; i < 2; ++i)
#pragma unroll
            for (int jn = 0; jn < 4; ++jn) {
                const int j2 = jn >> 1, o = (jn & 1) * 2;
                MMA16816(acc[i][jn], ah[i][0], ah[i][1], ah[i][2], ah[i][3],
                         bhf[j2][o], bhf[j2][o + 1]);
            }
#pragma unroll
        for (int i = 0; i < 2; ++i)
#pragma unroll
            for (int jn = 0; jn < 4; ++jn) {
                const int j2 = jn >> 1, o = (jn & 1) * 2;
                MMA16816(acc[i][jn], ah[i][0], ah[i][1], ah[i][2], ah[i][3],
                         blf[j2][o], blf[j2][o + 1]);
            }
#pragma unroll
        for (int i = 0; i < 2; ++i)
#pragma unroll
            for (int jn = 0; jn < 4; ++jn) {
                const int j2 = jn >> 1, o = (jn & 1) * 2;
                MMA16816(acc[i][jn], al[i][0], al[i][1], al[i][2], al[i][3],
                         bhf[j2][o], bhf[j2][o + 1]);
            }
    }

    const size_t Sbase = ((size_t)bh * NCH + c) * (NFm * HDm);
#pragma unroll
    for (int i = 0; i < 2; ++i) {
        const int fr = f0w + i * 16 + (l >> 2);
#pragma unroll
        for (int jn = 0; jn < 4; ++jn) {
            const int ec = e0w + jn * 8 + (l & 3) * 2;
            *(float2*)(g_S + Sbase + (size_t)fr * HDm + ec) =
                make_float2(acc[i][jn][0], acc[i][jn][1]);
            *(float2*)(g_S + Sbase + (size_t)(fr + 8) * HDm + ec) =
                make_float2(acc[i][jn][2], acc[i][jn][3]);
        }
    }
    if (tid < 128) {
        float zz = 0.f;
        for (int s = 0; s < 128; ++s) zz += g_kp[kbase + (size_t)s * NFm + tid];
        g_z[((size_t)bh * NCH + c) * NFm + tid] = zz;
    }
}

// ---------------- K4: exclusive prefix over chunks ----------------
__global__ void __launch_bounds__(256) prefix_kernel() {   // grid (32, BH)
    const int bh = blockIdx.y, seg = blockIdx.x;
    const int idx = seg * 256 + threadIdx.x;
    float v[NCH];
    const size_t base = (size_t)bh * NCH * NFm * HDm + idx;
#pragma unroll
    for (int c = 0; c < NCH; ++c) v[c] = g_S[base + (size_t)c * NFm * HDm];
    float acc = 0.f;
#pragma unroll
    for (int c = 0; c < NCH; ++c) { float cur = v[c]; v[c] = acc; acc += cur; }
#pragma unroll
    for (int c = 0; c < NCH; ++c) g_S[base + (size_t)c * NFm * HDm] = v[c];
    if (seg == 0 && threadIdx.x < NFm) {
        float zv[NCH];
        const size_t zb = (size_t)bh * NCH * NFm + threadIdx.x;
#pragma unroll
        for (int c = 0; c < NCH; ++c) zv[c] = g_z[zb + c * NFm];
        float az = 0.f;
#pragma unroll
        for (int c = 0; c < NCH; ++c) { float cur = zv[c]; zv[c] = az; az += cur; }
#pragma unroll
        for (int c = 0; c < NCH; ++c) g_z[zb + c * NFm] = zv[c];
    }
}

// ---------------- K5: chunk_out via HMMA (writes y as fp16 hi/lo) ----------------
#define CO_QH 0
#define CO_QL (CO_QH + 128 * PKb)
#define CO_KH (CO_QL + 128 * PKb)
#define CO_KL (CO_KH + 128 * PKb)
#define CO_VH (CO_KL + 128 * PKb)
#define CO_VL (CO_VH + 128 * PVb)
#define CO_SH (CO_VL + 128 * PVb)
#define CO_SL (CO_SH + 128 * PVb)
#define CO_Z  (CO_SL + 128 * PVb)
#define CO_D  (CO_Z + 512)
#define SMEM5 (CO_D + 512)

__global__ void __launch_bounds__(256, 1) chunk_out_kernel() {
    extern __shared__ char sm[];
    const uint32_t smb = smem_u32(sm);
    const int c = blockIdx.x, bh = blockIdx.y;
    const int b = bh >> 4, h = bh & 15;
    const int tid = threadIdx.x;
    const float* GV = g_qkv + 2 * QKV_OFF;
    const size_t qbase = ((size_t)bh * Tt + c * CHK) * NFm;
    const size_t vbase = ((size_t)(b * Tt + c * CHK)) * Dm + h * HDm;
    const size_t Sbase = ((size_t)bh * NCH + c) * (NFm * HDm);

#pragma unroll
    for (int j = 0; j < 16; ++j) {
        int lin = tid + 256 * j;
        int rr = lin >> 5, cc = lin & 31;
        float4 q4 = *(const float4*)(g_qp + qbase + (size_t)rr * NFm + cc * 4);
        float4 k4 = *(const float4*)(g_kp + qbase + (size_t)rr * NFm + cc * 4);
        uint32_t h01, l01, h23, l23;
        split2(q4.x, q4.y, h01, l01);
        split2(q4.z, q4.w, h23, l23);
        *(uint2*)(sm + CO_QH + rr * PKb + cc * 8) = make_uint2(h01, h23);
        *(uint2*)(sm + CO_QL + rr * PKb + cc * 8) = make_uint2(l01, l23);
        split2(k4.x, k4.y, h01, l01);
        split2(k4.z, k4.w, h23, l23);
        *(uint2*)(sm + CO_KH + rr * PKb + cc * 8) = make_uint2(h01, h23);
        *(uint2*)(sm + CO_KL + rr * PKb + cc * 8) = make_uint2(l01, l23);
    }
#pragma unroll
    for (int j = 0; j < 8; ++j) {
        int lin = tid + 256 * j;
        int rr = lin >> 4, cc = lin & 15;
        float4 v4 = *(const float4*)(GV + vbase + (size_t)rr * Dm + cc * 4);
        uint32_t h01, l01, h23, l23;
        split2(v4.x, v4.y, h01, l01);
        split2(v4.z, v4.w, h23, l23);
        *(uint2*)(sm + CO_VH + rr * PVb + cc * 8) = make_uint2(h01, h23);
        *(uint2*)(sm + CO_VL + rr * PVb + cc * 8) = make_uint2(l01, l23);
        float4 s4 = *(const float4*)(g_S + Sbase + (size_t)rr * HDm + cc * 4);
        split2(s4.x, s4.y, h01, l01);
        split2(s4.z, s4.w, h23, l23);
        *(uint2*)(sm + CO_SH + rr * PVb + cc * 8) = make_uint2(h01, h23);
        *(uint2*)(sm + CO_SL + rr * PVb + cc * 8) = make_uint2(l01, l23);
    }
    if (tid < 128)
        ((float*)(sm + CO_Z))[tid] = g_z[((size_t)bh * NCH + c) * NFm + tid];
    __syncthreads();

    const int l = tid & 31, w = tid >> 5;
    const int wm = w & 3, wn = w >> 2;
    const int lj = l >> 3, lm = l & 7;
    const int m = l >> 3, r = l & 7;
    const int arow = wm * 32 + (lj & 1) * 8 + lm;
    const int acho = lj >> 1;
    const int brow = ((lj & 2) ? 8 : 0) + lm;
    const int bcho = lj & 1;
    const int sB = (m & 1) ? 8 : 0, eB = (m & 2) ? 8 : 0;

    float accA[2][8][4];
#pragma unroll
    for (int i = 0; i < 2; i++)
#pragma unroll
        for (int jn = 0; jn < 8; jn++)
#pragma unroll
            for (int q = 0; q < 4; q++) accA[i][jn][q] = 0.f;

    for (int f0 = 0; f0 < 128; f0 += 16) {
        uint32_t qh[2][4], ql[2][4];
#pragma unroll
        for (int i = 0; i < 2; ++i) {
            uint32_t ad = smb + CO_QH + (arow + i * 16) * PKb + (f0 / 8 + acho) * 16;
            LDSM4(qh[i][0], qh[i][1], qh[i][2], qh[i][3], ad);
            LDSM4(ql[i][0], ql[i][1], ql[i][2], ql[i][3], ad + (CO_QL - CO_QH));
        }
#pragma unroll
        for (int g = 0; g < 4; ++g) {
            uint32_t kh[4], kl[4];
            uint32_t ad = smb + CO_KH + (wn * 64 + brow + g * 16) * PKb + (f0 / 8 + bcho) * 16;
            LDSM4(kh[0], kh[1], kh[2], kh[3], ad);
            LDSM4(kl[0], kl[1], kl[2], kl[3], ad + (CO_KL - CO_KH));
#pragma unroll
            for (int i = 0; i < 2; ++i)
#pragma unroll
                for (int hf = 0; hf < 2; ++hf)
                    MMA16816(accA[i][g * 2 + hf], qh[i][0], qh[i][1], qh[i][2], qh[i][3],
                             kh[hf * 2], kh[hf * 2 + 1]);
#pragma unroll
            for (int i = 0; i < 2; ++i)
#pragma unroll
                for (int hf = 0; hf < 2; ++hf)
                    MMA16816(accA[i][g * 2 + hf], qh[i][0], qh[i][1], qh[i][2], qh[i][3],
                             kl[hf * 2], kl[hf * 2 + 1]);
#pragma unroll
            for (int i = 0; i < 2; ++i)
#pragma unroll
                for (int hf = 0; hf < 2; ++hf)
                    MMA16816(accA[i][g * 2 + hf], ql[i][0], ql[i][1], ql[i][2], ql[i][3],
                             kh[hf * 2], kh[hf * 2 + 1]);
        }
    }
    __syncthreads();

#pragma unroll
    for (int i = 0; i < 2; ++i) {
        const int tr = wm * 32 + i * 16 + (l >> 2);
#pragma unroll
        for (int jn = 0; jn < 8; ++jn) {
            const int sc = wn * 64 + jn * 8 + (l & 3) * 2;
            float v0 = (sc     <= tr) ? accA[i][jn][0] : 0.f;
            float v1 = (sc + 1 <= tr) ? accA[i][jn][1] : 0.f;
            uint32_t hi, lo;
            split2(v0, v1, hi, lo);
            *(uint32_t*)(sm + CO_KH + tr * PKb + sc * 2) = hi;
            *(uint32_t*)(sm + CO_KL + tr * PKb + sc * 2) = lo;
            const int tr8 = tr + 8;
            v0 = (sc     <= tr8) ? accA[i][jn][2] : 0.f;
            v1 = (sc + 1 <= tr8) ? accA[i][jn][3] : 0.f;
            split2(v0, v1, hi, lo);
            *(uint32_t*)(sm + CO_KH + tr8 * PKb + sc * 2) = hi;
            *(uint32_t*)(sm + CO_KL + tr8 * PKb + sc * 2) = lo;
        }
    }
    __syncthreads();

    if (tid < 128) {
        const int t = tid;
        float den = EPSf;
        const float* zp = (const float*)(sm + CO_Z);
#pragma unroll 8
        for (int f2 = 0; f2 < 64; ++f2) {
            __nv_bfloat162 qh2 = *(__nv_bfloat162*)(sm + CO_QH + t * PKb + f2 * 4);
            __nv_bfloat162 ql2 = *(__nv_bfloat162*)(sm + CO_QL + t * PKb + f2 * 4);
            float2 fh = __bfloat1622float2(qh2), fl = __bfloat1622float2(ql2);
            den += (fh.x + fl.x) * zp[2 * f2] + (fh.y + fl.y) * zp[2 * f2 + 1];
        }
#pragma unroll 8
        for (int s2 = 0; s2 < 64; ++s2) {
            __nv_bfloat162 ah2 = *(__nv_bfloat162*)(sm + CO_KH + t * PKb + s2 * 4);
            __nv_bfloat162 al2 = *(__nv_bfloat162*)(sm + CO_KL + t * PKb + s2 * 4);
            float2 fa = __bfloat1622float2(ah2), fb = __bfloat1622float2(al2);
            den += fa.x + fa.y + fb.x + fb.y;
        }
        ((float*)(sm + CO_D))[t] = 1.f / den;
    }
    __syncthreads();

    const int e0w = wn * 32;
    float accY[2][4][4];
#pragma unroll
    for (int i = 0; i < 2; i++)
#pragma unroll
        for (int jn = 0; jn < 4; jn++)
#pragma unroll
            for (int q = 0; q < 4; q++) accY[i][jn][q] = 0.f;

    for (int s0 = 0; s0 < 128; s0 += 16) {
        uint32_t aah[2][4], aal[2][4], vh[2][4], vl[2][4];
#pragma unroll
        for (int i = 0; i < 2; ++i) {
            uint32_t ad = smb + CO_KH + (arow + i * 16) * PKb + (s0 / 8 + acho) * 16;
            LDSM4(aah[i][0], aah[i][1], aah[i][2], aah[i][3], ad);
            LDSM4(aal[i][0], aal[i][1], aal[i][2], aal[i][3], ad + (CO_KL - CO_KH));
        }
#pragma unroll
        for (int j2 = 0; j2 < 2; ++j2) {
            uint32_t ad = smb + CO_VH + (s0 + sB + r) * PVb + (e0w + j2 * 16 + eB) * 2;
            LDSM4T(vh[j2][0], vh[j2][1], vh[j2][2], vh[j2][3], ad);
            LDSM4T(vl[j2][0], vl[j2][1], vl[j2][2], vl[j2][3], ad + (CO_VL - CO_VH));
        }
#pragma unroll
        for (int i = 0; i < 2; ++i)
#pragma unroll
            for (int jn = 0; jn < 4; ++jn) {
                const int j2 = jn >> 1, o = (jn & 1) * 2;
                MMA16816(accY[i][jn], aah[i][0], aah[i][1], aah[i][2], aah[i][3],
                         vh[j2][o], vh[j2][o + 1]);
            }
#pragma unroll
        for (int i = 0; i < 2; ++i)
#pragma unroll
            for (int jn = 0; jn < 4; ++jn) {
                const int j2 = jn >> 1, o = (jn & 1) * 2;
                MMA16816(accY[i][jn], aah[i][0], aah[i][1], aah[i][2], aah[i][3],
                         vl[j2][o], vl[j2][o + 1]);
            }
#pragma unroll
        for (int i = 0; i < 2; ++i)
#pragma unroll
            for (int jn = 0; jn < 4; ++jn) {
                const int j2 = jn >> 1, o = (jn & 1) * 2;
                MMA16816(accY[i][jn], aal[i][0], aal[i][1], aal[i][2], aal[i][3],
                         vh[j2][o], vh[j2][o + 1]);
            }
    }
    for (int f0 = 0; f0 < 128; f0 += 16) {
        uint32_t qh[2][4], ql[2][4], sh[2][4], sl[2][4];
#pragma unroll
        for (int i = 0; i < 2; ++i) {
            uint32_t ad = smb + CO_QH + (arow + i * 16) * PKb + (f0 / 8 + acho) * 16;
            LDSM4(qh[i][0], qh[i][1], qh[i][2], qh[i][3], ad);
            LDSM4(ql[i][0], ql[i][1], ql[i][2], ql[i][3], ad + (CO_QL - CO_QH));
        }
#pragma unroll
        for (int j2 = 0; j2 < 2; ++j2) {
            uint32_t ad = smb + CO_SH + (f0 + sB + r) * PVb + (e0w + j2 * 16 + eB) * 2;
            LDSM4T(sh[j2][0], sh[j2][1], sh[j2][2], sh[j2][3], ad);
            LDSM4T(sl[j2][0], sl[j2][1], sl[j2][2], sl[j2][3], ad + (CO_SL - CO_SH));
        }
#pragma unroll
        for (int i = 0; i < 2; ++i)
#pragma unroll
            for (int jn = 0; jn < 4; ++jn) {
                const int j2 = jn >> 1, o = (jn & 1) * 2;
                MMA16816(accY[i][jn], qh[i][0], qh[i][1], qh[i][2], qh[i][3],
                         sh[j2][o], sh[j2][o + 1]);
            }
#pragma unroll
        for (int i = 0; i < 2; ++i)
#pragma unroll
            for (int jn = 0; jn < 4; ++jn) {
                const int j2 = jn >> 1, o = (jn & 1) * 2;
                MMA16816(accY[i][jn], qh[i][0], qh[i][1], qh[i][2], qh[i][3],
                         sl[j2][o], sl[j2][o + 1]);
            }
#pragma unroll
        for (int i = 0; i < 2; ++i)
#pragma unroll
            for (int jn = 0; jn < 4; ++jn) {
                const int j2 = jn >> 1, o = (jn & 1) * 2;
                MMA16816(accY[i][jn], ql[i][0], ql[i][1], ql[i][2], ql[i][3],
                         sh[j2][o], sh[j2][o + 1]);
            }
    }

    const float* dv = (const float*)(sm + CO_D);
#pragma unroll
    for (int i = 0; i < 2; ++i) {
        const int tr = wm * 32 + i * 16 + (l >> 2);
        const float d0 = dv[tr], d1 = dv[tr + 8];
#pragma unroll
        for (int jn = 0; jn < 4; ++jn) {
            const int ec = e0w + jn * 8 + (l & 3) * 2;
            size_t o0 = ((size_t)(b * Tt + c * CHK + tr)) * Dm + h * HDm + ec;
            size_t o1 = ((size_t)(b * Tt + c * CHK + tr + 8)) * Dm + h * HDm + ec;
            uint32_t hi, lo;
            split2h(accY[i][jn][0] * d0, accY[i][jn][1] * d0, hi, lo);
            *(uint32_t*)(g_yh16 + o0) = hi;
            *(uint32_t*)(g_yl16 + o0) = lo;
            split2h(accY[i][jn][2] * d1, accY[i][jn][3] * d1, hi, lo);
            *(uint32_t*)(g_yh16 + o1) = hi;
            *(uint32_t*)(g_yl16 + o1) = lo;
        }
    }
}

// ---------------------------------------------------------------------------
extern "C" void kernel_launch(void* const* d_in, const int* in_sizes, int n_in,
                              void* d_out, int out_size) {
    const float* x  = (const float*)d_in[0];
    const float* Wq = (const float*)d_in[1];
    const float* Wk = (const float*)d_in[2];
    const float* Wv = (const float*)d_in[3];
    const float* Wo = (const float*)d_in[4];
    const float* Wf = (const float*)d_in[5];
    float* out = (float*)d_out;

    cudaFuncSetAttribute(proj_kernel,      cudaFuncAttributeMaxDynamicSharedMemorySize, G2SMEM);
    cudaFuncSetAttribute(out_kernel,       cudaFuncAttributeMaxDynamicSharedMemorySize, G2SMEM);
    cudaFuncSetAttribute(feat_kernel,      cudaFuncAttributeMaxDynamicSharedMemorySize, FSM);
    cudaFuncSetAttribute(chunk_sum_kernel, cudaFuncAttributeMaxDynamicSharedMemorySize, SMEM3);
    cudaFuncSetAttribute(chunk_out_kernel, cudaFuncAttributeMaxDynamicSharedMemorySize, SMEM5);

    split_kernel<<<(MR * Dm / 4) / 256, 256>>>(x);
    wsplit_kernel<<<dim3(32, 32, 4), 256>>>(Wq, Wk, Wv, Wo);
    proj_kernel<<<dim3(8, 64, 3), 256, G2SMEM>>>();             // q, k, v — fp16 2-pass
    feat_kernel<<<dim3(MR / 128, Hh, 2), 256, FSM>>>(Wf);
    chunk_sum_kernel<<<dim3(NCH, BH), 256, SMEM3>>>();
    prefix_kernel<<<dim3(32, BH), 256>>>();
    chunk_out_kernel<<<dim3(NCH, BH), 256, SMEM5>>>();
    out_kernel<<<dim3(8, 64), 256, G2SMEM>>>(out);
}